// round 2
// baseline (speedup 1.0000x reference)
#include <cuda_runtime.h>
#include <math.h>

#define N_NODES 4096
#define H_DIM   128
#define NEGV    (-1000000000.0f)

// ---------------- device scratch (no allocations allowed) ----------------
__device__ float g_h1[N_NODES * H_DIM];
__device__ float g_s1[N_NODES];
__device__ float g_d1[N_NODES];
__device__ float g_g1[N_NODES * H_DIM];
__device__ float g_h2[N_NODES * H_DIM];
__device__ float g_s2[N_NODES];
__device__ float g_d2[N_NODES];
__device__ float g_hn[N_NODES * H_DIM];
__device__ float g_q [N_NODES * H_DIM];

__device__ __forceinline__ float gelu_exact(float x) {
    // torch nn.GELU default: x * 0.5 * (1 + erf(x/sqrt(2)))
    return 0.5f * x * (1.0f + erff(x * 0.70710678118654752440f));
}

// =========================================================================
// GEMM: out[4096][128] = in[4096][K] @ W[128][K]^T (+bias)
// optionally s_out[i] = h[i]·a_s, d_out[i] = h[i]·a_d   (attention scalars)
// Block: 32 rows x 128 cols, 256 threads, thread = 4 rows x 4 cols.
// dyn smem: in_s[32*K] + Wt[K*128] (W transposed so col-dim is contiguous)
// =========================================================================
__global__ void gemm_attn_kernel(const float* __restrict__ in, int K,
                                 const float* __restrict__ W,
                                 const float* __restrict__ a_s,
                                 const float* __restrict__ a_d,
                                 const float* __restrict__ bias,
                                 float* __restrict__ out,
                                 float* __restrict__ s_out,
                                 float* __restrict__ d_out) {
    extern __shared__ float sm[];
    float* in_s = sm;            // 32*K
    float* Wt   = sm + 32 * K;   // K*128, Wt[k*128+c] = W[c][k]
    const int tid = threadIdx.x;
    const int i0  = blockIdx.x * 32;

    for (int idx = tid; idx < 32 * K; idx += 256)
        in_s[idx] = in[(size_t)(i0 + idx / K) * K + (idx % K)];
    for (int idx = tid; idx < 128 * K; idx += 256) {
        int c = idx / K, k = idx - c * K;
        Wt[k * 128 + c] = W[idx];
    }
    __syncthreads();

    const int rg = tid >> 5;        // warp id: rows rg*4 .. rg*4+3
    const int lane = tid & 31;      // cols lane*4 .. lane*4+3
    float acc[4][4];
#pragma unroll
    for (int r = 0; r < 4; ++r)
#pragma unroll
        for (int c = 0; c < 4; ++c) acc[r][c] = 0.f;

    for (int k = 0; k < K; ++k) {
        float4 b = *reinterpret_cast<const float4*>(&Wt[k * 128 + lane * 4]);
#pragma unroll
        for (int rr = 0; rr < 4; ++rr) {
            float a = in_s[(rg * 4 + rr) * K + k];   // lane-uniform: broadcast
            acc[rr][0] += a * b.x;
            acc[rr][1] += a * b.y;
            acc[rr][2] += a * b.z;
            acc[rr][3] += a * b.w;
        }
    }

    // store h (+bias)
#pragma unroll
    for (int rr = 0; rr < 4; ++rr) {
        int row = i0 + rg * 4 + rr;
        float4 v;
        v.x = acc[rr][0]; v.y = acc[rr][1]; v.z = acc[rr][2]; v.w = acc[rr][3];
        if (bias) {
            v.x += bias[lane * 4 + 0];
            v.y += bias[lane * 4 + 1];
            v.z += bias[lane * 4 + 2];
            v.w += bias[lane * 4 + 3];
        }
        *reinterpret_cast<float4*>(&out[(size_t)row * 128 + lane * 4]) = v;
    }

    // attention scalars s = h·a_s, d = h·a_d (computed from pre-bias h; bias
    // is only used for the q projection, which passes s_out == nullptr)
    if (s_out) {
#pragma unroll
        for (int rr = 0; rr < 4; ++rr) {
            float sp = 0.f, dp = 0.f;
#pragma unroll
            for (int cc = 0; cc < 4; ++cc) {
                int c = lane * 4 + cc;
                sp += acc[rr][cc] * __ldg(&a_s[c]);
                dp += acc[rr][cc] * __ldg(&a_d[c]);
            }
#pragma unroll
            for (int off = 16; off; off >>= 1) {
                sp += __shfl_xor_sync(0xffffffffu, sp, off);
                dp += __shfl_xor_sync(0xffffffffu, dp, off);
            }
            if (lane == 0) {
                s_out[i0 + rg * 4 + rr] = sp;
                d_out[i0 + rg * 4 + rr] = dp;
            }
        }
    }
}

// =========================================================================
// GAT aggregation: out[i][t] = relu( (1/Z_i) * sum_j w_ij * h[j][t] )
//   w_ij = adj[i][j] > 0 ? exp(lrelu(s_i + d_j, 0.2)) : 0,  Z_i = sum_j w_ij
// (no softmax max-subtraction: |s+d| << 1 for this distribution; softmax is
//  shift-invariant so this is exact)
// Layer 2 (do_ln): out = LayerNorm(relu(..) + res)
// Block: 32 rows x 128 cols, 256 threads, thread = 4 rows x 4 cols.
// K-loop over j in tiles of 32, on-the-fly weight tile in smem.
// =========================================================================
__global__ void gat_agg_kernel(const float* __restrict__ h,
                               const float* __restrict__ s,
                               const float* __restrict__ d,
                               const int*   __restrict__ adj,
                               const float* __restrict__ res,
                               const float* __restrict__ lnw,
                               const float* __restrict__ lnb,
                               float* __restrict__ out,
                               int do_ln) {
    __shared__ float h_s[32 * 128];
    __shared__ float w_s[32 * 32];
    __shared__ float s_s[32];
    __shared__ float z_s[32];

    const int tid = threadIdx.x;
    const int i0  = blockIdx.x * 32;
    if (tid < 32) s_s[tid] = s[i0 + tid];

    const int rg   = tid >> 5;       // warp: rows rg*4..rg*4+3
    const int lane = tid & 31;       // cols lane*4..lane*4+3
    const int wi   = tid >> 3;       // w-tile row 0..31
    const int wj   = (tid & 7) * 4;  // w-tile j offset

    float zacc = 0.f;
    float acc[4][4];
#pragma unroll
    for (int r = 0; r < 4; ++r)
#pragma unroll
        for (int c = 0; c < 4; ++c) acc[r][c] = 0.f;

    __syncthreads();

    for (int j0 = 0; j0 < N_NODES; j0 += 32) {
        // --- weight tile 32x32 (coalesced int4 adjacency read) ---
        const int4 av = *reinterpret_cast<const int4*>(
            &adj[(size_t)(i0 + wi) * N_NODES + j0 + wj]);
        const float4 dv = *reinterpret_cast<const float4*>(&d[j0 + wj]);
        const float si = s_s[wi];
        float w0 = 0.f, w1 = 0.f, w2 = 0.f, w3 = 0.f;
        if (av.x > 0) { float e = si + dv.x; e = (e > 0.f) ? e : 0.2f * e; w0 = __expf(e); }
        if (av.y > 0) { float e = si + dv.y; e = (e > 0.f) ? e : 0.2f * e; w1 = __expf(e); }
        if (av.z > 0) { float e = si + dv.z; e = (e > 0.f) ? e : 0.2f * e; w2 = __expf(e); }
        if (av.w > 0) { float e = si + dv.w; e = (e > 0.f) ? e : 0.2f * e; w3 = __expf(e); }
        *reinterpret_cast<float4*>(&w_s[wi * 32 + wj]) = make_float4(w0, w1, w2, w3);
        zacc += (w0 + w1) + (w2 + w3);

        // --- h tile 32x128 (float4, coalesced) ---
#pragma unroll
        for (int t = 0; t < 4; ++t) {
            int idx = tid + t * 256;   // float4 index over 32*32
            reinterpret_cast<float4*>(h_s)[idx] =
                reinterpret_cast<const float4*>(h)[(size_t)(j0 + (idx >> 5)) * 32 + (idx & 31)];
        }
        __syncthreads();

        // --- FMA: thread 4x4 micro-tile ---
#pragma unroll 4
        for (int jj = 0; jj < 32; ++jj) {
            float4 b = *reinterpret_cast<const float4*>(&h_s[jj * 128 + lane * 4]);
#pragma unroll
            for (int rr = 0; rr < 4; ++rr) {
                float a = w_s[(rg * 4 + rr) * 32 + jj];  // lane-uniform broadcast
                acc[rr][0] += a * b.x;
                acc[rr][1] += a * b.y;
                acc[rr][2] += a * b.z;
                acc[rr][3] += a * b.w;
            }
        }
        __syncthreads();
    }

    // Z reduction: 8 lanes per row (aligned groups)
    zacc += __shfl_xor_sync(0xffffffffu, zacc, 4);
    zacc += __shfl_xor_sync(0xffffffffu, zacc, 2);
    zacc += __shfl_xor_sync(0xffffffffu, zacc, 1);
    if ((tid & 7) == 0) z_s[wi] = zacc;
    __syncthreads();

    // epilogue
#pragma unroll
    for (int rr = 0; rr < 4; ++rr) {
        const int row = i0 + rg * 4 + rr;
        const float z = z_s[rg * 4 + rr];
        const float zinv = (z > 0.f) ? (1.0f / z) : 0.f;
        float v[4];
#pragma unroll
        for (int cc = 0; cc < 4; ++cc) {
            float t = fmaxf(acc[rr][cc] * zinv, 0.f);       // relu
            if (res) t += res[(size_t)row * 128 + lane * 4 + cc];
            v[cc] = t;
        }
        if (do_ln) {
            float sum = v[0] + v[1] + v[2] + v[3];
            float sq  = v[0]*v[0] + v[1]*v[1] + v[2]*v[2] + v[3]*v[3];
#pragma unroll
            for (int off = 16; off; off >>= 1) {
                sum += __shfl_xor_sync(0xffffffffu, sum, off);
                sq  += __shfl_xor_sync(0xffffffffu, sq,  off);
            }
            const float mu  = sum * (1.0f / 128.0f);
            const float var = sq  * (1.0f / 128.0f) - mu * mu;
            const float rs  = rsqrtf(var + 1e-5f);
#pragma unroll
            for (int cc = 0; cc < 4; ++cc) {
                int c = lane * 4 + cc;
                v[cc] = (v[cc] - mu) * rs * __ldg(&lnw[c]) + __ldg(&lnb[c]);
            }
        }
        float4 o; o.x = v[0]; o.y = v[1]; o.z = v[2]; o.w = v[3];
        *reinterpret_cast<float4*>(&out[(size_t)row * 128 + lane * 4]) = o;
    }
}

// =========================================================================
// Candidate head, fully fused. Block = 2 nodes (128 (n,c) rows), 256 thr.
// All weights live in smem (transposed: reduction dim = smem row, so the
// inner loop does conflict-free LDS.128 along the k-contiguous dim).
//   stage1: T1 = gelu(cf @ Wc1^T + bc1)          K=10
//   stage2: T2 = gelu(T1 @ Wc2^T + bc2)          K=128
//   stage3: t  = gelu([q*T2, T2] @ Ws1^T + bs1)  K=256 (two 128 passes)
//   logit  = t · Ws2 + bs2 + bias(cf) ; masked by action_mask (+no-valid fix)
// smem phases:  A: Wc1t|Wc2t|T1   B (overwrites A): Ws1t|q_s
// =========================================================================
#define CSM_WC1T   0        // [10][128]     -> 1280
#define CSM_WC2T   1280     // [128][128]    -> 16384
#define CSM_T1     17664    // [128][128]    -> 16384   (phase A end 34048)
#define CSM_WS1T   0        // [256][128]    -> 32768   (phase B)
#define CSM_QS     32768    // [2][128]      -> 256     (phase B end 33024)
#define CSM_T2     34048    // [128][128]    -> 16384
#define CSM_CF     50432    // [128][10]     -> 1280
#define CSM_AM     51712    // [128]
#define CSM_BC1    51840    // [128]
#define CSM_BC2    51968    // [128]
#define CSM_BS1    52096    // [128]
#define CSM_WS2    52224    // [128]
#define CSM_MISC   52352    // [8]
#define CAND_SMEM_FLOATS 52360

__global__ void cand_kernel(const float* __restrict__ cf,   // [4096*64][10]
                            const float* __restrict__ am,   // [4096][64]
                            const float* __restrict__ Wc1, const float* __restrict__ bc1,
                            const float* __restrict__ Wc2, const float* __restrict__ bc2,
                            const float* __restrict__ Ws1, const float* __restrict__ bs1,
                            const float* __restrict__ Ws2, const float* __restrict__ bs2,
                            const float* __restrict__ q,    // [4096][128]
                            float* __restrict__ out) {      // [4096][64]
    extern __shared__ float sm[];
    float* Wc1t = sm + CSM_WC1T;
    float* Wc2t = sm + CSM_WC2T;
    float* T1   = sm + CSM_T1;
    float* Ws1t = sm + CSM_WS1T;
    float* q_s  = sm + CSM_QS;
    float* T2   = sm + CSM_T2;
    float* cf_s = sm + CSM_CF;
    float* am_s = sm + CSM_AM;
    float* bc1s = sm + CSM_BC1;
    float* bc2s = sm + CSM_BC2;
    float* bs1s = sm + CSM_BS1;
    float* Ws2s = sm + CSM_WS2;
    float* misc = sm + CSM_MISC;

    const int tid = threadIdx.x;
    const int n0  = blockIdx.x * 2;
    const int base_row = n0 * 64;

    // ---- phase A loads ----
    for (int idx = tid; idx < 1280; idx += 256) {
        int k = idx / 10, j = idx - k * 10;
        Wc1t[j * 128 + k] = Wc1[idx];
    }
    for (int idx = tid; idx < 16384; idx += 256) {
        int k = idx >> 7, j = idx & 127;
        Wc2t[j * 128 + k] = Wc2[idx];
    }
    for (int idx = tid; idx < 1280; idx += 256)
        cf_s[idx] = cf[(size_t)base_row * 10 + idx];
    if (tid < 128) {
        am_s[tid] = am[base_row + tid];
        bc1s[tid] = bc1[tid];
        bc2s[tid] = bc2[tid];
        bs1s[tid] = bs1[tid];
        Ws2s[tid] = Ws2[tid];
    }
    __syncthreads();

    if (tid < 2) {     // no-valid-action flags for the 2 nodes
        float ssum = 0.f;
        for (int c = 0; c < 64; ++c) ssum += am_s[tid * 64 + c];
        misc[tid] = (ssum <= 0.f) ? 1.f : 0.f;
    }

    const int rg = tid >> 4;     // 0..15 -> rows rg*8 .. rg*8+7
    const int cg = tid & 15;     // cols cg*8 .. cg*8+7
    float acc[8][8];

    // ---- stage 1: cf[10] -> 128 ----
#pragma unroll
    for (int r = 0; r < 8; ++r)
#pragma unroll
        for (int c = 0; c < 8; ++c) acc[r][c] = 0.f;
#pragma unroll
    for (int j = 0; j < 10; ++j) {
        float4 b0 = *reinterpret_cast<const float4*>(&Wc1t[j * 128 + cg * 8]);
        float4 b1 = *reinterpret_cast<const float4*>(&Wc1t[j * 128 + cg * 8 + 4]);
#pragma unroll
        for (int rr = 0; rr < 8; ++rr) {
            float a = cf_s[(rg * 8 + rr) * 10 + j];
            acc[rr][0] += a * b0.x; acc[rr][1] += a * b0.y;
            acc[rr][2] += a * b0.z; acc[rr][3] += a * b0.w;
            acc[rr][4] += a * b1.x; acc[rr][5] += a * b1.y;
            acc[rr][6] += a * b1.z; acc[rr][7] += a * b1.w;
        }
    }
#pragma unroll
    for (int rr = 0; rr < 8; ++rr) {
        int r = rg * 8 + rr;
        float4 o0, o1;
        o0.x = gelu_exact(acc[rr][0] + bc1s[cg * 8 + 0]);
        o0.y = gelu_exact(acc[rr][1] + bc1s[cg * 8 + 1]);
        o0.z = gelu_exact(acc[rr][2] + bc1s[cg * 8 + 2]);
        o0.w = gelu_exact(acc[rr][3] + bc1s[cg * 8 + 3]);
        o1.x = gelu_exact(acc[rr][4] + bc1s[cg * 8 + 4]);
        o1.y = gelu_exact(acc[rr][5] + bc1s[cg * 8 + 5]);
        o1.z = gelu_exact(acc[rr][6] + bc1s[cg * 8 + 6]);
        o1.w = gelu_exact(acc[rr][7] + bc1s[cg * 8 + 7]);
        *reinterpret_cast<float4*>(&T1[r * 128 + cg * 8])     = o0;
        *reinterpret_cast<float4*>(&T1[r * 128 + cg * 8 + 4]) = o1;
    }
    __syncthreads();

    // ---- stage 2: T1[128] -> 128 ----
#pragma unroll
    for (int r = 0; r < 8; ++r)
#pragma unroll
        for (int c = 0; c < 8; ++c) acc[r][c] = 0.f;
#pragma unroll 2
    for (int j = 0; j < 128; ++j) {
        float4 b0 = *reinterpret_cast<const float4*>(&Wc2t[j * 128 + cg * 8]);
        float4 b1 = *reinterpret_cast<const float4*>(&Wc2t[j * 128 + cg * 8 + 4]);
#pragma unroll
        for (int rr = 0; rr < 8; ++rr) {
            float a = T1[(rg * 8 + rr) * 128 + j];
            acc[rr][0] += a * b0.x; acc[rr][1] += a * b0.y;
            acc[rr][2] += a * b0.z; acc[rr][3] += a * b0.w;
            acc[rr][4] += a * b1.x; acc[rr][5] += a * b1.y;
            acc[rr][6] += a * b1.z; acc[rr][7] += a * b1.w;
        }
    }
    __syncthreads();   // all stage-2 reads of T1/Wc2t done; region A now reusable

    // write T2 + phase B loads (disjoint smem regions)
#pragma unroll
    for (int rr = 0; rr < 8; ++rr) {
        int r = rg * 8 + rr;
        float4 o0, o1;
        o0.x = gelu_exact(acc[rr][0] + bc2s[cg * 8 + 0]);
        o0.y = gelu_exact(acc[rr][1] + bc2s[cg * 8 + 1]);
        o0.z = gelu_exact(acc[rr][2] + bc2s[cg * 8 + 2]);
        o0.w = gelu_exact(acc[rr][3] + bc2s[cg * 8 + 3]);
        o1.x = gelu_exact(acc[rr][4] + bc2s[cg * 8 + 4]);
        o1.y = gelu_exact(acc[rr][5] + bc2s[cg * 8 + 5]);
        o1.z = gelu_exact(acc[rr][6] + bc2s[cg * 8 + 6]);
        o1.w = gelu_exact(acc[rr][7] + bc2s[cg * 8 + 7]);
        *reinterpret_cast<float4*>(&T2[r * 128 + cg * 8])     = o0;
        *reinterpret_cast<float4*>(&T2[r * 128 + cg * 8 + 4]) = o1;
    }
    for (int idx = tid; idx < 32768; idx += 256) {
        int k = idx >> 8, j = idx & 255;
        Ws1t[j * 128 + k] = Ws1[idx];
    }
    if (tid < 256) q_s[tid] = q[(size_t)n0 * 128 + tid];
    __syncthreads();

    // ---- stage 3: fused[256] -> 128 (two 128 passes) ----
#pragma unroll
    for (int r = 0; r < 8; ++r)
#pragma unroll
        for (int c = 0; c < 8; ++c) acc[r][c] = 0.f;
#pragma unroll 2
    for (int j = 0; j < 128; ++j) {   // pass 1: q * T2
        float4 b0 = *reinterpret_cast<const float4*>(&Ws1t[j * 128 + cg * 8]);
        float4 b1 = *reinterpret_cast<const float4*>(&Ws1t[j * 128 + cg * 8 + 4]);
#pragma unroll
        for (int rr = 0; rr < 8; ++rr) {
            int r = rg * 8 + rr;
            float a = q_s[(r >> 6) * 128 + j] * T2[r * 128 + j];
            acc[rr][0] += a * b0.x; acc[rr][1] += a * b0.y;
            acc[rr][2] += a * b0.z; acc[rr][3] += a * b0.w;
            acc[rr][4] += a * b1.x; acc[rr][5] += a * b1.y;
            acc[rr][6] += a * b1.z; acc[rr][7] += a * b1.w;
        }
    }
#pragma unroll 2
    for (int j = 0; j < 128; ++j) {   // pass 2: T2
        float4 b0 = *reinterpret_cast<const float4*>(&Ws1t[(128 + j) * 128 + cg * 8]);
        float4 b1 = *reinterpret_cast<const float4*>(&Ws1t[(128 + j) * 128 + cg * 8 + 4]);
#pragma unroll
        for (int rr = 0; rr < 8; ++rr) {
            float a = T2[(rg * 8 + rr) * 128 + j];
            acc[rr][0] += a * b0.x; acc[rr][1] += a * b0.y;
            acc[rr][2] += a * b0.z; acc[rr][3] += a * b0.w;
            acc[rr][4] += a * b1.x; acc[rr][5] += a * b1.y;
            acc[rr][6] += a * b1.z; acc[rr][7] += a * b1.w;
        }
    }

    // ---- epilogue: gelu, dot Ws2, reduce over the 16 col-threads ----
    const float bs2v = __ldg(&bs2[0]);
#pragma unroll
    for (int rr = 0; rr < 8; ++rr) {
        float p = 0.f;
#pragma unroll
        for (int kk = 0; kk < 8; ++kk) {
            int k = cg * 8 + kk;
            p += gelu_exact(acc[rr][kk] + bs1s[k]) * Ws2s[k];
        }
        p += __shfl_xor_sync(0xffffffffu, p, 8);
        p += __shfl_xor_sync(0xffffffffu, p, 4);
        p += __shfl_xor_sync(0xffffffffu, p, 2);
        p += __shfl_xor_sync(0xffffffffu, p, 1);
        if (cg == 0) {
            const int r = rg * 8 + rr;
            const int l = r >> 6, c = r & 63;
            const float* cfr = &cf_s[r * 10];
            float bias = 20.0f * cfr[0] + 4.0f * cfr[4] + 1.5f * cfr[5]
                       + 1.5f * cfr[1] - 1.5f * cfr[2] + 1.2f * cfr[6]
                       + 2.5f * cfr[7] + 1.6f * cfr[8] + 1.2f * cfr[9];
            float logit = p + bs2v + bias;
            float amv = am_s[r];
            bool valid = (amv > 0.f) || (c == 0 && misc[l] > 0.5f);
            out[(size_t)(n0 + l) * 64 + c] = valid ? logit : NEGV;
        }
    }
}

// =========================================================================
extern "C" void kernel_launch(void* const* d_in, const int* in_sizes, int n_in,
                              void* d_out, int out_size) {
    const float* x    = (const float*)d_in[0];
    const float* cf   = (const float*)d_in[1];
    const int*   adj  = (const int*)  d_in[2];
    const float* am   = (const float*)d_in[3];
    const float* W1   = (const float*)d_in[4];
    const float* a1s  = (const float*)d_in[5];
    const float* a1d  = (const float*)d_in[6];
    const float* W2   = (const float*)d_in[7];
    const float* a2s  = (const float*)d_in[8];
    const float* a2d  = (const float*)d_in[9];
    const float* lnw  = (const float*)d_in[10];
    const float* lnb  = (const float*)d_in[11];
    const float* Wc1  = (const float*)d_in[12];
    const float* bc1  = (const float*)d_in[13];
    const float* Wc2  = (const float*)d_in[14];
    const float* bc2  = (const float*)d_in[15];
    const float* Wq   = (const float*)d_in[16];
    const float* bq   = (const float*)d_in[17];
    const float* Ws1  = (const float*)d_in[18];
    const float* bs1  = (const float*)d_in[19];
    const float* Ws2  = (const float*)d_in[20];
    const float* bs2  = (const float*)d_in[21];
    float* out = (float*)d_out;

    float *h1, *s1, *d1, *g1, *h2, *s2, *d2, *hn, *qp;
    cudaGetSymbolAddress((void**)&h1, g_h1);
    cudaGetSymbolAddress((void**)&s1, g_s1);
    cudaGetSymbolAddress((void**)&d1, g_d1);
    cudaGetSymbolAddress((void**)&g1, g_g1);
    cudaGetSymbolAddress((void**)&h2, g_h2);
    cudaGetSymbolAddress((void**)&s2, g_s2);
    cudaGetSymbolAddress((void**)&d2, g_d2);
    cudaGetSymbolAddress((void**)&hn, g_hn);
    cudaGetSymbolAddress((void**)&qp, g_q);

    const int smem_k64  = (32 * 64  + 64  * 128) * 4;   // 40960
    const int smem_k128 = (32 * 128 + 128 * 128) * 4;   // 81920
    const int smem_cand = CAND_SMEM_FLOATS * 4;          // 209440

    cudaFuncSetAttribute(gemm_attn_kernel,
                         cudaFuncAttributeMaxDynamicSharedMemorySize, smem_k128);
    cudaFuncSetAttribute(cand_kernel,
                         cudaFuncAttributeMaxDynamicSharedMemorySize, smem_cand);

    // layer 1
    gemm_attn_kernel<<<128, 256, smem_k64>>>(x, 64, W1, a1s, a1d, nullptr,
                                             h1, s1, d1);
    gat_agg_kernel<<<128, 256>>>(h1, s1, d1, adj, nullptr, nullptr, nullptr,
                                 g1, 0);
    // layer 2 + residual + LN
    gemm_attn_kernel<<<128, 256, smem_k128>>>(g1, 128, W2, a2s, a2d, nullptr,
                                              h2, s2, d2);
    gat_agg_kernel<<<128, 256>>>(h2, s2, d2, adj, g1, lnw, lnb, hn, 1);
    // q projection
    gemm_attn_kernel<<<128, 256, smem_k128>>>(hn, 128, Wq, nullptr, nullptr, bq,
                                              qp, nullptr, nullptr);
    // fused candidate head + bias + mask
    cand_kernel<<<2048, 256, smem_cand>>>(cf, am, Wc1, bc1, Wc2, bc2,
                                          Ws1, bs1, Ws2, bs2, qp, out);
}

// round 3
// speedup vs baseline: 1.0704x; 1.0704x over previous
#include <cuda_runtime.h>
#include <math.h>

#define N_NODES 4096
#define H_DIM   128
#define NEGV    (-1000000000.0f)

// ---------------- device scratch (no allocations allowed) ----------------
__device__ float g_h1[N_NODES * H_DIM];
__device__ float g_s1[N_NODES];
__device__ float g_d1[N_NODES];
__device__ float g_g1[N_NODES * H_DIM];
__device__ float g_h2[N_NODES * H_DIM];
__device__ float g_s2[N_NODES];
__device__ float g_d2[N_NODES];
__device__ float g_hn[N_NODES * H_DIM];
__device__ float g_q [N_NODES * H_DIM];

__device__ __forceinline__ float gelu_exact(float x) {
    return 0.5f * x * (1.0f + erff(x * 0.70710678118654752440f));
}

// ---- packed fp32x2 FMA (Blackwell FFMA2: 2x fp32 FMA throughput, exact) ----
__device__ __forceinline__ unsigned long long ffma2(unsigned long long a,
                                                    unsigned long long b,
                                                    unsigned long long c) {
    unsigned long long d;
    asm("fma.rn.f32x2 %0, %1, %2, %3;" : "=l"(d) : "l"(a), "l"(b), "l"(c));
    return d;
}
__device__ __forceinline__ unsigned long long pack2(float x, float y) {
    unsigned long long d;
    asm("mov.b64 %0, {%1, %2};" : "=l"(d) : "f"(x), "f"(y));
    return d;
}
__device__ __forceinline__ float2 unpack2(unsigned long long v) {
    float2 r;
    asm("mov.b64 {%0, %1}, %2;" : "=f"(r.x), "=f"(r.y) : "l"(v));
    return r;
}

// =========================================================================
// GEMM: out[4096][128] = in[4096][K] @ W[128][K]^T (+bias)
// optionally s_out[i] = h[i]·a_s, d_out[i] = h[i]·a_d   (attention scalars)
// Block: 32 rows x 128 cols, 256 threads, thread = 4 rows x 4 cols (2 f32x2).
// =========================================================================
__global__ void gemm_attn_kernel(const float* __restrict__ in, int K,
                                 const float* __restrict__ W,
                                 const float* __restrict__ a_s,
                                 const float* __restrict__ a_d,
                                 const float* __restrict__ bias,
                                 float* __restrict__ out,
                                 float* __restrict__ s_out,
                                 float* __restrict__ d_out) {
    extern __shared__ float sm[];
    float* in_s = sm;            // 32*K
    float* Wt   = sm + 32 * K;   // K*128, Wt[k*128+c] = W[c][k]
    const int tid = threadIdx.x;
    const int i0  = blockIdx.x * 32;

    for (int idx = tid; idx < 32 * K; idx += 256)
        in_s[idx] = in[(size_t)(i0 + idx / K) * K + (idx % K)];
    for (int idx = tid; idx < 128 * K; idx += 256) {
        int c = idx / K, k = idx - c * K;
        Wt[k * 128 + c] = W[idx];
    }
    __syncthreads();

    const int rg = tid >> 5;        // warp id: rows rg*4 .. rg*4+3
    const int lane = tid & 31;      // cols lane*4 .. lane*4+3
    unsigned long long acc2[4][2];
#pragma unroll
    for (int r = 0; r < 4; ++r) { acc2[r][0] = 0ull; acc2[r][1] = 0ull; }

    for (int k = 0; k < K; ++k) {
        longlong2 B = *reinterpret_cast<const longlong2*>(&Wt[k * 128 + lane * 4]);
#pragma unroll
        for (int rr = 0; rr < 4; ++rr) {
            float a = in_s[(rg * 4 + rr) * K + k];   // warp-uniform rg: broadcast-ish
            unsigned long long aa = pack2(a, a);
            acc2[rr][0] = ffma2(aa, (unsigned long long)B.x, acc2[rr][0]);
            acc2[rr][1] = ffma2(aa, (unsigned long long)B.y, acc2[rr][1]);
        }
    }

    float acc[4][4];
#pragma unroll
    for (int rr = 0; rr < 4; ++rr) {
        float2 p0 = unpack2(acc2[rr][0]);
        float2 p1 = unpack2(acc2[rr][1]);
        acc[rr][0] = p0.x; acc[rr][1] = p0.y; acc[rr][2] = p1.x; acc[rr][3] = p1.y;
    }

    // store h (+bias)
#pragma unroll
    for (int rr = 0; rr < 4; ++rr) {
        int row = i0 + rg * 4 + rr;
        float4 v;
        v.x = acc[rr][0]; v.y = acc[rr][1]; v.z = acc[rr][2]; v.w = acc[rr][3];
        if (bias) {
            v.x += bias[lane * 4 + 0];
            v.y += bias[lane * 4 + 1];
            v.z += bias[lane * 4 + 2];
            v.w += bias[lane * 4 + 3];
        }
        *reinterpret_cast<float4*>(&out[(size_t)row * 128 + lane * 4]) = v;
    }

    // attention scalars s = h·a_s, d = h·a_d (pre-bias h)
    if (s_out) {
#pragma unroll
        for (int rr = 0; rr < 4; ++rr) {
            float sp = 0.f, dp = 0.f;
#pragma unroll
            for (int cc = 0; cc < 4; ++cc) {
                int c = lane * 4 + cc;
                sp += acc[rr][cc] * __ldg(&a_s[c]);
                dp += acc[rr][cc] * __ldg(&a_d[c]);
            }
#pragma unroll
            for (int off = 16; off; off >>= 1) {
                sp += __shfl_xor_sync(0xffffffffu, sp, off);
                dp += __shfl_xor_sync(0xffffffffu, dp, off);
            }
            if (lane == 0) {
                s_out[i0 + rg * 4 + rr] = sp;
                d_out[i0 + rg * 4 + rr] = dp;
            }
        }
    }
}

// =========================================================================
// GAT aggregation, software-pipelined + f32x2.
//   out[i][t] = relu( (1/Z_i) * sum_j w_ij * h[j][t] ), w_ij rank-1 + adj mask
// Layer 2 (do_ln): out = LayerNorm(relu(..) + res)
// Pipeline per 32-j tile: LDG(next)->regs | compute(cur smem) | STS(next) | BAR
// =========================================================================
__global__ void gat_agg_kernel(const float* __restrict__ h,
                               const float* __restrict__ s,
                               const float* __restrict__ d,
                               const int*   __restrict__ adj,
                               const float* __restrict__ res,
                               const float* __restrict__ lnw,
                               const float* __restrict__ lnb,
                               float* __restrict__ out,
                               int do_ln) {
    __shared__ float h_s[2][32 * 128];
    __shared__ float w_s[2][32 * 32];
    __shared__ float z_s[32];

    const int tid = threadIdx.x;
    const int i0  = blockIdx.x * 32;

    const int rg   = tid >> 5;       // warp: rows rg*4..rg*4+3 (warp-uniform)
    const int lane = tid & 31;       // cols lane*4..lane*4+3
    const int wi   = tid >> 3;       // w-tile row 0..31
    const int wj   = (tid & 7) * 4;  // w-tile j offset
    const float si = s[i0 + wi];

    float zacc = 0.f;
    unsigned long long acc2[4][2];
#pragma unroll
    for (int r = 0; r < 4; ++r) { acc2[r][0] = 0ull; acc2[r][1] = 0ull; }

    const float4* hp = reinterpret_cast<const float4*>(h);

    // staging registers
    int4 av; float4 dv; float4 hv0, hv1, hv2, hv3;

#define GAT_LOAD(J0)                                                          \
    do {                                                                      \
        av = *reinterpret_cast<const int4*>(                                  \
            &adj[(size_t)(i0 + wi) * N_NODES + (J0) + wj]);                   \
        dv = *reinterpret_cast<const float4*>(&d[(J0) + wj]);                 \
        hv0 = hp[(size_t)((J0) + rg +  0) * 32 + lane];                       \
        hv1 = hp[(size_t)((J0) + rg +  8) * 32 + lane];                       \
        hv2 = hp[(size_t)((J0) + rg + 16) * 32 + lane];                       \
        hv3 = hp[(size_t)((J0) + rg + 24) * 32 + lane];                       \
    } while (0)

#define GAT_STORE(BUF)                                                        \
    do {                                                                      \
        float w0 = 0.f, w1 = 0.f, w2 = 0.f, w3 = 0.f;                         \
        if (av.x > 0) { float e = si + dv.x; e = (e > 0.f) ? e : 0.2f * e; w0 = __expf(e); } \
        if (av.y > 0) { float e = si + dv.y; e = (e > 0.f) ? e : 0.2f * e; w1 = __expf(e); } \
        if (av.z > 0) { float e = si + dv.z; e = (e > 0.f) ? e : 0.2f * e; w2 = __expf(e); } \
        if (av.w > 0) { float e = si + dv.w; e = (e > 0.f) ? e : 0.2f * e; w3 = __expf(e); } \
        *reinterpret_cast<float4*>(&w_s[BUF][wi * 32 + wj]) =                 \
            make_float4(w0, w1, w2, w3);                                      \
        zacc += (w0 + w1) + (w2 + w3);                                        \
        float4* hb = reinterpret_cast<float4*>(&h_s[BUF][0]);                 \
        hb[(rg +  0) * 32 + lane] = hv0;                                      \
        hb[(rg +  8) * 32 + lane] = hv1;                                      \
        hb[(rg + 16) * 32 + lane] = hv2;                                      \
        hb[(rg + 24) * 32 + lane] = hv3;                                      \
    } while (0)

    // prologue: tile 0
    GAT_LOAD(0);
    GAT_STORE(0);
    __syncthreads();

    int buf = 0;
    for (int t = 0; t < N_NODES / 32; ++t) {
        const int nxt = (t + 1) * 32;
        if (nxt < N_NODES) GAT_LOAD(nxt);

        // compute on current buffer
#pragma unroll 4
        for (int jj = 0; jj < 32; ++jj) {
            longlong2 B = *reinterpret_cast<const longlong2*>(
                &h_s[buf][jj * 128 + lane * 4]);
#pragma unroll
            for (int rr = 0; rr < 4; ++rr) {
                float a = w_s[buf][(rg * 4 + rr) * 32 + jj];  // warp-uniform
                unsigned long long aa = pack2(a, a);
                acc2[rr][0] = ffma2(aa, (unsigned long long)B.x, acc2[rr][0]);
                acc2[rr][1] = ffma2(aa, (unsigned long long)B.y, acc2[rr][1]);
            }
        }

        if (nxt < N_NODES) GAT_STORE(buf ^ 1);
        __syncthreads();
        buf ^= 1;
    }
#undef GAT_LOAD
#undef GAT_STORE

    // Z reduction: 8 lanes per row (aligned groups)
    zacc += __shfl_xor_sync(0xffffffffu, zacc, 4);
    zacc += __shfl_xor_sync(0xffffffffu, zacc, 2);
    zacc += __shfl_xor_sync(0xffffffffu, zacc, 1);
    if ((tid & 7) == 0) z_s[wi] = zacc;
    __syncthreads();

    // epilogue
#pragma unroll
    for (int rr = 0; rr < 4; ++rr) {
        const int row = i0 + rg * 4 + rr;
        const float z = z_s[rg * 4 + rr];
        const float zinv = (z > 0.f) ? (1.0f / z) : 0.f;
        float2 p0 = unpack2(acc2[rr][0]);
        float2 p1 = unpack2(acc2[rr][1]);
        float v[4] = {p0.x, p0.y, p1.x, p1.y};
#pragma unroll
        for (int cc = 0; cc < 4; ++cc) {
            float t = fmaxf(v[cc] * zinv, 0.f);       // relu
            if (res) t += res[(size_t)row * 128 + lane * 4 + cc];
            v[cc] = t;
        }
        if (do_ln) {
            float sum = v[0] + v[1] + v[2] + v[3];
            float sq  = v[0]*v[0] + v[1]*v[1] + v[2]*v[2] + v[3]*v[3];
#pragma unroll
            for (int off = 16; off; off >>= 1) {
                sum += __shfl_xor_sync(0xffffffffu, sum, off);
                sq  += __shfl_xor_sync(0xffffffffu, sq,  off);
            }
            const float mu  = sum * (1.0f / 128.0f);
            const float var = sq  * (1.0f / 128.0f) - mu * mu;
            const float rs  = rsqrtf(var + 1e-5f);
#pragma unroll
            for (int cc = 0; cc < 4; ++cc) {
                int c = lane * 4 + cc;
                v[cc] = (v[cc] - mu) * rs * __ldg(&lnw[c]) + __ldg(&lnb[c]);
            }
        }
        float4 o; o.x = v[0]; o.y = v[1]; o.z = v[2]; o.w = v[3];
        *reinterpret_cast<float4*>(&out[(size_t)row * 128 + lane * 4]) = o;
    }
}

// =========================================================================
// Candidate head, fully fused, f32x2 FMAs. Block = 2 nodes (128 rows), 256 thr.
// =========================================================================
#define CSM_WC1T   0        // [10][128]     -> 1280
#define CSM_WC2T   1280     // [128][128]    -> 16384
#define CSM_T1     17664    // [128][128]    -> 16384   (phase A end 34048)
#define CSM_WS1T   0        // [256][128]    -> 32768   (phase B)
#define CSM_QS     32768    // [2][128]      -> 256     (phase B end 33024)
#define CSM_T2     34048    // [128][128]    -> 16384
#define CSM_CF     50432    // [128][10]     -> 1280
#define CSM_AM     51712    // [128]
#define CSM_BC1    51840    // [128]
#define CSM_BC2    51968    // [128]
#define CSM_BS1    52096    // [128]
#define CSM_WS2    52224    // [128]
#define CSM_MISC   52352    // [8]
#define CAND_SMEM_FLOATS 52360

__global__ void cand_kernel(const float* __restrict__ cf,   // [4096*64][10]
                            const float* __restrict__ am,   // [4096][64]
                            const float* __restrict__ Wc1, const float* __restrict__ bc1,
                            const float* __restrict__ Wc2, const float* __restrict__ bc2,
                            const float* __restrict__ Ws1, const float* __restrict__ bs1,
                            const float* __restrict__ Ws2, const float* __restrict__ bs2,
                            const float* __restrict__ q,    // [4096][128]
                            float* __restrict__ out) {      // [4096][64]
    extern __shared__ float sm[];
    float* Wc1t = sm + CSM_WC1T;
    float* Wc2t = sm + CSM_WC2T;
    float* T1   = sm + CSM_T1;
    float* Ws1t = sm + CSM_WS1T;
    float* q_s  = sm + CSM_QS;
    float* T2   = sm + CSM_T2;
    float* cf_s = sm + CSM_CF;
    float* am_s = sm + CSM_AM;
    float* bc1s = sm + CSM_BC1;
    float* bc2s = sm + CSM_BC2;
    float* bs1s = sm + CSM_BS1;
    float* Ws2s = sm + CSM_WS2;
    float* misc = sm + CSM_MISC;

    const int tid = threadIdx.x;
    const int n0  = blockIdx.x * 2;
    const int base_row = n0 * 64;

    // ---- phase A loads ----
    for (int idx = tid; idx < 1280; idx += 256) {
        int k = idx / 10, j = idx - k * 10;
        Wc1t[j * 128 + k] = Wc1[idx];
    }
    for (int idx = tid; idx < 16384; idx += 256) {
        int k = idx >> 7, j = idx & 127;
        Wc2t[j * 128 + k] = Wc2[idx];
    }
    for (int idx = tid; idx < 1280; idx += 256)
        cf_s[idx] = cf[(size_t)base_row * 10 + idx];
    if (tid < 128) {
        am_s[tid] = am[base_row + tid];
        bc1s[tid] = bc1[tid];
        bc2s[tid] = bc2[tid];
        bs1s[tid] = bs1[tid];
        Ws2s[tid] = Ws2[tid];
    }
    __syncthreads();

    if (tid < 2) {     // no-valid-action flags for the 2 nodes
        float ssum = 0.f;
        for (int c = 0; c < 64; ++c) ssum += am_s[tid * 64 + c];
        misc[tid] = (ssum <= 0.f) ? 1.f : 0.f;
    }

    const int rg = tid >> 4;     // 0..15 -> rows rg*8 .. rg*8+7
    const int cg = tid & 15;     // cols cg*8 .. cg*8+7
    unsigned long long acc2[8][4];

    // ---- stage 1: cf[10] -> 128 ----
#pragma unroll
    for (int r = 0; r < 8; ++r)
#pragma unroll
        for (int c = 0; c < 4; ++c) acc2[r][c] = 0ull;
#pragma unroll
    for (int j = 0; j < 10; ++j) {
        longlong2 B0 = *reinterpret_cast<const longlong2*>(&Wc1t[j * 128 + cg * 8]);
        longlong2 B1 = *reinterpret_cast<const longlong2*>(&Wc1t[j * 128 + cg * 8 + 4]);
#pragma unroll
        for (int rr = 0; rr < 8; ++rr) {
            float a = cf_s[(rg * 8 + rr) * 10 + j];
            unsigned long long aa = pack2(a, a);
            acc2[rr][0] = ffma2(aa, (unsigned long long)B0.x, acc2[rr][0]);
            acc2[rr][1] = ffma2(aa, (unsigned long long)B0.y, acc2[rr][1]);
            acc2[rr][2] = ffma2(aa, (unsigned long long)B1.x, acc2[rr][2]);
            acc2[rr][3] = ffma2(aa, (unsigned long long)B1.y, acc2[rr][3]);
        }
    }
#pragma unroll
    for (int rr = 0; rr < 8; ++rr) {
        int r = rg * 8 + rr;
        float2 p0 = unpack2(acc2[rr][0]);
        float2 p1 = unpack2(acc2[rr][1]);
        float2 p2 = unpack2(acc2[rr][2]);
        float2 p3 = unpack2(acc2[rr][3]);
        float4 o0, o1;
        o0.x = gelu_exact(p0.x + bc1s[cg * 8 + 0]);
        o0.y = gelu_exact(p0.y + bc1s[cg * 8 + 1]);
        o0.z = gelu_exact(p1.x + bc1s[cg * 8 + 2]);
        o0.w = gelu_exact(p1.y + bc1s[cg * 8 + 3]);
        o1.x = gelu_exact(p2.x + bc1s[cg * 8 + 4]);
        o1.y = gelu_exact(p2.y + bc1s[cg * 8 + 5]);
        o1.z = gelu_exact(p3.x + bc1s[cg * 8 + 6]);
        o1.w = gelu_exact(p3.y + bc1s[cg * 8 + 7]);
        *reinterpret_cast<float4*>(&T1[r * 128 + cg * 8])     = o0;
        *reinterpret_cast<float4*>(&T1[r * 128 + cg * 8 + 4]) = o1;
    }
    __syncthreads();

    // ---- stage 2: T1[128] -> 128 ----
#pragma unroll
    for (int r = 0; r < 8; ++r)
#pragma unroll
        for (int c = 0; c < 4; ++c) acc2[r][c] = 0ull;
#pragma unroll 2
    for (int j = 0; j < 128; ++j) {
        longlong2 B0 = *reinterpret_cast<const longlong2*>(&Wc2t[j * 128 + cg * 8]);
        longlong2 B1 = *reinterpret_cast<const longlong2*>(&Wc2t[j * 128 + cg * 8 + 4]);
#pragma unroll
        for (int rr = 0; rr < 8; ++rr) {
            float a = T1[(rg * 8 + rr) * 128 + j];
            unsigned long long aa = pack2(a, a);
            acc2[rr][0] = ffma2(aa, (unsigned long long)B0.x, acc2[rr][0]);
            acc2[rr][1] = ffma2(aa, (unsigned long long)B0.y, acc2[rr][1]);
            acc2[rr][2] = ffma2(aa, (unsigned long long)B1.x, acc2[rr][2]);
            acc2[rr][3] = ffma2(aa, (unsigned long long)B1.y, acc2[rr][3]);
        }
    }
    __syncthreads();   // stage-2 reads of T1/Wc2t done; region A reusable

    // write T2 + phase B loads (disjoint smem regions)
#pragma unroll
    for (int rr = 0; rr < 8; ++rr) {
        int r = rg * 8 + rr;
        float2 p0 = unpack2(acc2[rr][0]);
        float2 p1 = unpack2(acc2[rr][1]);
        float2 p2 = unpack2(acc2[rr][2]);
        float2 p3 = unpack2(acc2[rr][3]);
        float4 o0, o1;
        o0.x = gelu_exact(p0.x + bc2s[cg * 8 + 0]);
        o0.y = gelu_exact(p0.y + bc2s[cg * 8 + 1]);
        o0.z = gelu_exact(p1.x + bc2s[cg * 8 + 2]);
        o0.w = gelu_exact(p1.y + bc2s[cg * 8 + 3]);
        o1.x = gelu_exact(p2.x + bc2s[cg * 8 + 4]);
        o1.y = gelu_exact(p2.y + bc2s[cg * 8 + 5]);
        o1.z = gelu_exact(p3.x + bc2s[cg * 8 + 6]);
        o1.w = gelu_exact(p3.y + bc2s[cg * 8 + 7]);
        *reinterpret_cast<float4*>(&T2[r * 128 + cg * 8])     = o0;
        *reinterpret_cast<float4*>(&T2[r * 128 + cg * 8 + 4]) = o1;
    }
    for (int idx = tid; idx < 32768; idx += 256) {
        int k = idx >> 8, j = idx & 255;
        Ws1t[j * 128 + k] = Ws1[idx];
    }
    q_s[tid] = q[(size_t)n0 * 128 + tid];
    __syncthreads();

    // ---- stage 3: fused[256] -> 128 (two 128 passes) ----
#pragma unroll
    for (int r = 0; r < 8; ++r)
#pragma unroll
        for (int c = 0; c < 4; ++c) acc2[r][c] = 0ull;
    const float* qrow = &q_s[(rg >> 3) * 128];  // node index constant per thread
#pragma unroll 2
    for (int j = 0; j < 128; ++j) {   // pass 1: q * T2
        longlong2 B0 = *reinterpret_cast<const longlong2*>(&Ws1t[j * 128 + cg * 8]);
        longlong2 B1 = *reinterpret_cast<const longlong2*>(&Ws1t[j * 128 + cg * 8 + 4]);
        float qv = qrow[j];
#pragma unroll
        for (int rr = 0; rr < 8; ++rr) {
            float a = qv * T2[(rg * 8 + rr) * 128 + j];
            unsigned long long aa = pack2(a, a);
            acc2[rr][0] = ffma2(aa, (unsigned long long)B0.x, acc2[rr][0]);
            acc2[rr][1] = ffma2(aa, (unsigned long long)B0.y, acc2[rr][1]);
            acc2[rr][2] = ffma2(aa, (unsigned long long)B1.x, acc2[rr][2]);
            acc2[rr][3] = ffma2(aa, (unsigned long long)B1.y, acc2[rr][3]);
        }
    }
#pragma unroll 2
    for (int j = 0; j < 128; ++j) {   // pass 2: T2
        longlong2 B0 = *reinterpret_cast<const longlong2*>(&Ws1t[(128 + j) * 128 + cg * 8]);
        longlong2 B1 = *reinterpret_cast<const longlong2*>(&Ws1t[(128 + j) * 128 + cg * 8 + 4]);
#pragma unroll
        for (int rr = 0; rr < 8; ++rr) {
            float a = T2[(rg * 8 + rr) * 128 + j];
            unsigned long long aa = pack2(a, a);
            acc2[rr][0] = ffma2(aa, (unsigned long long)B0.x, acc2[rr][0]);
            acc2[rr][1] = ffma2(aa, (unsigned long long)B0.y, acc2[rr][1]);
            acc2[rr][2] = ffma2(aa, (unsigned long long)B1.x, acc2[rr][2]);
            acc2[rr][3] = ffma2(aa, (unsigned long long)B1.y, acc2[rr][3]);
        }
    }

    // ---- epilogue: gelu, dot Ws2, reduce over the 16 col-threads ----
    const float bs2v = __ldg(&bs2[0]);
#pragma unroll
    for (int rr = 0; rr < 8; ++rr) {
        float af[8];
        float2 p0 = unpack2(acc2[rr][0]);
        float2 p1 = unpack2(acc2[rr][1]);
        float2 p2 = unpack2(acc2[rr][2]);
        float2 p3 = unpack2(acc2[rr][3]);
        af[0] = p0.x; af[1] = p0.y; af[2] = p1.x; af[3] = p1.y;
        af[4] = p2.x; af[5] = p2.y; af[6] = p3.x; af[7] = p3.y;
        float p = 0.f;
#pragma unroll
        for (int kk = 0; kk < 8; ++kk) {
            int k = cg * 8 + kk;
            p += gelu_exact(af[kk] + bs1s[k]) * Ws2s[k];
        }
        p += __shfl_xor_sync(0xffffffffu, p, 8);
        p += __shfl_xor_sync(0xffffffffu, p, 4);
        p += __shfl_xor_sync(0xffffffffu, p, 2);
        p += __shfl_xor_sync(0xffffffffu, p, 1);
        if (cg == 0) {
            const int r = rg * 8 + rr;
            const int l = r >> 6, c = r & 63;
            const float* cfr = &cf_s[r * 10];
            float bias = 20.0f * cfr[0] + 4.0f * cfr[4] + 1.5f * cfr[5]
                       + 1.5f * cfr[1] - 1.5f * cfr[2] + 1.2f * cfr[6]
                       + 2.5f * cfr[7] + 1.6f * cfr[8] + 1.2f * cfr[9];
            float logit = p + bs2v + bias;
            float amv = am_s[r];
            bool valid = (amv > 0.f) || (c == 0 && misc[l] > 0.5f);
            out[(size_t)(n0 + l) * 64 + c] = valid ? logit : NEGV;
        }
    }
}

// =========================================================================
extern "C" void kernel_launch(void* const* d_in, const int* in_sizes, int n_in,
                              void* d_out, int out_size) {
    const float* x    = (const float*)d_in[0];
    const float* cf   = (const float*)d_in[1];
    const int*   adj  = (const int*)  d_in[2];
    const float* am   = (const float*)d_in[3];
    const float* W1   = (const float*)d_in[4];
    const float* a1s  = (const float*)d_in[5];
    const float* a1d  = (const float*)d_in[6];
    const float* W2   = (const float*)d_in[7];
    const float* a2s  = (const float*)d_in[8];
    const float* a2d  = (const float*)d_in[9];
    const float* lnw  = (const float*)d_in[10];
    const float* lnb  = (const float*)d_in[11];
    const float* Wc1  = (const float*)d_in[12];
    const float* bc1  = (const float*)d_in[13];
    const float* Wc2  = (const float*)d_in[14];
    const float* bc2  = (const float*)d_in[15];
    const float* Wq   = (const float*)d_in[16];
    const float* bq   = (const float*)d_in[17];
    const float* Ws1  = (const float*)d_in[18];
    const float* bs1  = (const float*)d_in[19];
    const float* Ws2  = (const float*)d_in[20];
    const float* bs2  = (const float*)d_in[21];
    float* out = (float*)d_out;

    float *h1, *s1, *d1, *g1, *h2, *s2, *d2, *hn, *qp;
    cudaGetSymbolAddress((void**)&h1, g_h1);
    cudaGetSymbolAddress((void**)&s1, g_s1);
    cudaGetSymbolAddress((void**)&d1, g_d1);
    cudaGetSymbolAddress((void**)&g1, g_g1);
    cudaGetSymbolAddress((void**)&h2, g_h2);
    cudaGetSymbolAddress((void**)&s2, g_s2);
    cudaGetSymbolAddress((void**)&d2, g_d2);
    cudaGetSymbolAddress((void**)&hn, g_hn);
    cudaGetSymbolAddress((void**)&qp, g_q);

    const int smem_k64  = (32 * 64  + 64  * 128) * 4;   // 40960
    const int smem_k128 = (32 * 128 + 128 * 128) * 4;   // 81920
    const int smem_cand = CAND_SMEM_FLOATS * 4;          // 209440

    cudaFuncSetAttribute(gemm_attn_kernel,
                         cudaFuncAttributeMaxDynamicSharedMemorySize, smem_k128);
    cudaFuncSetAttribute(cand_kernel,
                         cudaFuncAttributeMaxDynamicSharedMemorySize, smem_cand);

    // layer 1
    gemm_attn_kernel<<<128, 256, smem_k64>>>(x, 64, W1, a1s, a1d, nullptr,
                                             h1, s1, d1);
    gat_agg_kernel<<<128, 256>>>(h1, s1, d1, adj, nullptr, nullptr, nullptr,
                                 g1, 0);
    // layer 2 + residual + LN
    gemm_attn_kernel<<<128, 256, smem_k128>>>(g1, 128, W2, a2s, a2d, nullptr,
                                              h2, s2, d2);
    gat_agg_kernel<<<128, 256>>>(h2, s2, d2, adj, g1, lnw, lnb, hn, 1);
    // q projection
    gemm_attn_kernel<<<128, 256, smem_k128>>>(hn, 128, Wq, nullptr, nullptr, bq,
                                              qp, nullptr, nullptr);
    // fused candidate head + bias + mask
    cand_kernel<<<2048, 256, smem_cand>>>(cf, am, Wc1, bc1, Wc2, bc2,
                                          Ws1, bs1, Ws2, bs2, qp, out);
}

// round 6
// speedup vs baseline: 2.4824x; 2.3192x over previous
#include <cuda_runtime.h>
#include <cuda_bf16.h>
#include <math.h>

#define N_NODES 4096
#define H_DIM   128
#define NEGV    (-1000000000.0f)

// ---------------- device scratch (no allocations allowed) ----------------
__device__ float g_h1[N_NODES * H_DIM];
__device__ float g_s1[N_NODES];
__device__ float g_d1[N_NODES];
__device__ float g_g1[N_NODES * H_DIM];
__device__ float g_h2[N_NODES * H_DIM];
__device__ float g_s2[N_NODES];
__device__ float g_d2[N_NODES];
__device__ float g_hn[N_NODES * H_DIM];
__device__ float g_q [N_NODES * H_DIM];

__device__ __forceinline__ float gelu_exact(float x) {
    return 0.5f * x * (1.0f + erff(x * 0.70710678118654752440f));
}

// ---- packed fp32x2 FMA ----
__device__ __forceinline__ unsigned long long ffma2(unsigned long long a,
                                                    unsigned long long b,
                                                    unsigned long long c) {
    unsigned long long d;
    asm("fma.rn.f32x2 %0, %1, %2, %3;" : "=l"(d) : "l"(a), "l"(b), "l"(c));
    return d;
}
__device__ __forceinline__ unsigned long long pack2(float x, float y) {
    unsigned long long d;
    asm("mov.b64 %0, {%1, %2};" : "=l"(d) : "f"(x), "f"(y));
    return d;
}
__device__ __forceinline__ float2 unpack2(unsigned long long v) {
    float2 r;
    asm("mov.b64 {%0, %1}, %2;" : "=f"(r.x), "=f"(r.y) : "l"(v));
    return r;
}

// ---- bf16 helpers ----
__device__ __forceinline__ unsigned bf16x2_of(float lo, float hi) {
    unsigned r;   // PTX: first src -> upper half, second -> lower half
    asm("cvt.rn.bf16x2.f32 %0, %1, %2;" : "=r"(r) : "f"(hi), "f"(lo));
    return r;
}
__device__ __forceinline__ unsigned mul_bf16x2(unsigned a, unsigned b) {
    unsigned r;
    asm("mul.bf16x2 %0, %1, %2;" : "=r"(r) : "r"(a), "r"(b));
    return r;
}
// bf16 mma: D(16x8,f32) += A(16x16,bf16 row) * B(16x8,bf16 col)
__device__ __forceinline__ void mma16816(float* c, const unsigned* a,
                                         unsigned b0, unsigned b1) {
    asm("mma.sync.aligned.m16n8k16.row.col.f32.bf16.bf16.f32 "
        "{%0,%1,%2,%3}, {%4,%5,%6,%7}, {%8,%9}, {%0,%1,%2,%3};"
        : "+f"(c[0]), "+f"(c[1]), "+f"(c[2]), "+f"(c[3])
        : "r"(a[0]), "r"(a[1]), "r"(a[2]), "r"(a[3]), "r"(b0), "r"(b1));
}

// =========================================================================
// GEMM: out[4096][128] = in[4096][K] @ W[128][K]^T (+bias)
// =========================================================================
__global__ void gemm_attn_kernel(const float* __restrict__ in, int K,
                                 const float* __restrict__ W,
                                 const float* __restrict__ a_s,
                                 const float* __restrict__ a_d,
                                 const float* __restrict__ bias,
                                 float* __restrict__ out,
                                 float* __restrict__ s_out,
                                 float* __restrict__ d_out) {
    extern __shared__ float sm[];
    float* in_s = sm;            // 32*K
    float* Wt   = sm + 32 * K;   // K*128
    const int tid = threadIdx.x;
    const int i0  = blockIdx.x * 32;

    for (int idx = tid; idx < 32 * K; idx += 256)
        in_s[idx] = in[(size_t)(i0 + idx / K) * K + (idx % K)];
    for (int idx = tid; idx < 128 * K; idx += 256) {
        int c = idx / K, k = idx - c * K;
        Wt[k * 128 + c] = W[idx];
    }
    __syncthreads();

    const int rg = tid >> 5;
    const int lane = tid & 31;
    unsigned long long acc2[4][2];
#pragma unroll
    for (int r = 0; r < 4; ++r) { acc2[r][0] = 0ull; acc2[r][1] = 0ull; }

    for (int k = 0; k < K; ++k) {
        longlong2 B = *reinterpret_cast<const longlong2*>(&Wt[k * 128 + lane * 4]);
#pragma unroll
        for (int rr = 0; rr < 4; ++rr) {
            float a = in_s[(rg * 4 + rr) * K + k];
            unsigned long long aa = pack2(a, a);
            acc2[rr][0] = ffma2(aa, (unsigned long long)B.x, acc2[rr][0]);
            acc2[rr][1] = ffma2(aa, (unsigned long long)B.y, acc2[rr][1]);
        }
    }

    float acc[4][4];
#pragma unroll
    for (int rr = 0; rr < 4; ++rr) {
        float2 p0 = unpack2(acc2[rr][0]);
        float2 p1 = unpack2(acc2[rr][1]);
        acc[rr][0] = p0.x; acc[rr][1] = p0.y; acc[rr][2] = p1.x; acc[rr][3] = p1.y;
    }

#pragma unroll
    for (int rr = 0; rr < 4; ++rr) {
        int row = i0 + rg * 4 + rr;
        float4 v;
        v.x = acc[rr][0]; v.y = acc[rr][1]; v.z = acc[rr][2]; v.w = acc[rr][3];
        if (bias) {
            v.x += bias[lane * 4 + 0];
            v.y += bias[lane * 4 + 1];
            v.z += bias[lane * 4 + 2];
            v.w += bias[lane * 4 + 3];
        }
        *reinterpret_cast<float4*>(&out[(size_t)row * 128 + lane * 4]) = v;
    }

    if (s_out) {
#pragma unroll
        for (int rr = 0; rr < 4; ++rr) {
            float sp = 0.f, dp = 0.f;
#pragma unroll
            for (int cc = 0; cc < 4; ++cc) {
                int c = lane * 4 + cc;
                sp += acc[rr][cc] * __ldg(&a_s[c]);
                dp += acc[rr][cc] * __ldg(&a_d[c]);
            }
#pragma unroll
            for (int off = 16; off; off >>= 1) {
                sp += __shfl_xor_sync(0xffffffffu, sp, off);
                dp += __shfl_xor_sync(0xffffffffu, dp, off);
            }
            if (lane == 0) {
                s_out[i0 + rg * 4 + rr] = sp;
                d_out[i0 + rg * 4 + rr] = dp;
            }
        }
    }
}

// =========================================================================
// GAT aggregation (pipelined f32x2)
// =========================================================================
__global__ void gat_agg_kernel(const float* __restrict__ h,
                               const float* __restrict__ s,
                               const float* __restrict__ d,
                               const int*   __restrict__ adj,
                               const float* __restrict__ res,
                               const float* __restrict__ lnw,
                               const float* __restrict__ lnb,
                               float* __restrict__ out,
                               int do_ln) {
    __shared__ float h_s[2][32 * 128];
    __shared__ float w_s[2][32 * 32];
    __shared__ float z_s[32];

    const int tid = threadIdx.x;
    const int i0  = blockIdx.x * 32;

    const int rg   = tid >> 5;
    const int lane = tid & 31;
    const int wi   = tid >> 3;
    const int wj   = (tid & 7) * 4;
    const float si = s[i0 + wi];

    float zacc = 0.f;
    unsigned long long acc2[4][2];
#pragma unroll
    for (int r = 0; r < 4; ++r) { acc2[r][0] = 0ull; acc2[r][1] = 0ull; }

    const float4* hp = reinterpret_cast<const float4*>(h);
    int4 av; float4 dv; float4 hv0, hv1, hv2, hv3;

#define GAT_LOAD(J0)                                                          \
    do {                                                                      \
        av = *reinterpret_cast<const int4*>(                                  \
            &adj[(size_t)(i0 + wi) * N_NODES + (J0) + wj]);                   \
        dv = *reinterpret_cast<const float4*>(&d[(J0) + wj]);                 \
        hv0 = hp[(size_t)((J0) + rg +  0) * 32 + lane];                       \
        hv1 = hp[(size_t)((J0) + rg +  8) * 32 + lane];                       \
        hv2 = hp[(size_t)((J0) + rg + 16) * 32 + lane];                       \
        hv3 = hp[(size_t)((J0) + rg + 24) * 32 + lane];                       \
    } while (0)

#define GAT_STORE(BUF)                                                        \
    do {                                                                      \
        float w0 = 0.f, w1 = 0.f, w2 = 0.f, w3 = 0.f;                         \
        if (av.x > 0) { float e = si + dv.x; e = (e > 0.f) ? e : 0.2f * e; w0 = __expf(e); } \
        if (av.y > 0) { float e = si + dv.y; e = (e > 0.f) ? e : 0.2f * e; w1 = __expf(e); } \
        if (av.z > 0) { float e = si + dv.z; e = (e > 0.f) ? e : 0.2f * e; w2 = __expf(e); } \
        if (av.w > 0) { float e = si + dv.w; e = (e > 0.f) ? e : 0.2f * e; w3 = __expf(e); } \
        *reinterpret_cast<float4*>(&w_s[BUF][wi * 32 + wj]) =                 \
            make_float4(w0, w1, w2, w3);                                      \
        zacc += (w0 + w1) + (w2 + w3);                                        \
        float4* hb = reinterpret_cast<float4*>(&h_s[BUF][0]);                 \
        hb[(rg +  0) * 32 + lane] = hv0;                                      \
        hb[(rg +  8) * 32 + lane] = hv1;                                      \
        hb[(rg + 16) * 32 + lane] = hv2;                                      \
        hb[(rg + 24) * 32 + lane] = hv3;                                      \
    } while (0)

    GAT_LOAD(0);
    GAT_STORE(0);
    __syncthreads();

    int buf = 0;
    for (int t = 0; t < N_NODES / 32; ++t) {
        const int nxt = (t + 1) * 32;
        if (nxt < N_NODES) GAT_LOAD(nxt);

#pragma unroll 4
        for (int jj = 0; jj < 32; ++jj) {
            longlong2 B = *reinterpret_cast<const longlong2*>(
                &h_s[buf][jj * 128 + lane * 4]);
#pragma unroll
            for (int rr = 0; rr < 4; ++rr) {
                float a = w_s[buf][(rg * 4 + rr) * 32 + jj];
                unsigned long long aa = pack2(a, a);
                acc2[rr][0] = ffma2(aa, (unsigned long long)B.x, acc2[rr][0]);
                acc2[rr][1] = ffma2(aa, (unsigned long long)B.y, acc2[rr][1]);
            }
        }

        if (nxt < N_NODES) GAT_STORE(buf ^ 1);
        __syncthreads();
        buf ^= 1;
    }
#undef GAT_LOAD
#undef GAT_STORE

    zacc += __shfl_xor_sync(0xffffffffu, zacc, 4);
    zacc += __shfl_xor_sync(0xffffffffu, zacc, 2);
    zacc += __shfl_xor_sync(0xffffffffu, zacc, 1);
    if ((tid & 7) == 0) z_s[wi] = zacc;
    __syncthreads();

#pragma unroll
    for (int rr = 0; rr < 4; ++rr) {
        const int row = i0 + rg * 4 + rr;
        const float z = z_s[rg * 4 + rr];
        const float zinv = (z > 0.f) ? (1.0f / z) : 0.f;
        float2 p0 = unpack2(acc2[rr][0]);
        float2 p1 = unpack2(acc2[rr][1]);
        float v[4] = {p0.x, p0.y, p1.x, p1.y};
#pragma unroll
        for (int cc = 0; cc < 4; ++cc) {
            float t = fmaxf(v[cc] * zinv, 0.f);
            if (res) t += res[(size_t)row * 128 + lane * 4 + cc];
            v[cc] = t;
        }
        if (do_ln) {
            float sum = v[0] + v[1] + v[2] + v[3];
            float sq  = v[0]*v[0] + v[1]*v[1] + v[2]*v[2] + v[3]*v[3];
#pragma unroll
            for (int off = 16; off; off >>= 1) {
                sum += __shfl_xor_sync(0xffffffffu, sum, off);
                sq  += __shfl_xor_sync(0xffffffffu, sq,  off);
            }
            const float mu  = sum * (1.0f / 128.0f);
            const float var = sq  * (1.0f / 128.0f) - mu * mu;
            const float rs  = rsqrtf(var + 1e-5f);
#pragma unroll
            for (int cc = 0; cc < 4; ++cc) {
                int c = lane * 4 + cc;
                v[cc] = (v[cc] - mu) * rs * __ldg(&lnw[c]) + __ldg(&lnb[c]);
            }
        }
        float4 o; o.x = v[0]; o.y = v[1]; o.z = v[2]; o.w = v[3];
        *reinterpret_cast<float4*>(&out[(size_t)row * 128 + lane * 4]) = o;
    }
}

// =========================================================================
// Candidate head: bf16 tensor-core MMA (m16n8k16), fully fused.
// Block = 2 nodes (128 rows), 256 threads = 8 warps (4 m-groups x 2 n-groups).
// =========================================================================
#define STR1 136      // padded k-stride (bf16 elems) for 128-wide mats
#define STR3 264      // padded k-stride for Ws1 (256-wide)

#define OB_WC2  0                       // bf16 [128][136] = 34816
#define OB_WS1  34816                   // bf16 [128][264] = 67584
#define OB_T1   102400                  // bf16 [128][136] = 34816
#define OB_T2   137216                  // bf16 [128][136] = 34816
#define OB_WC1T 172032                  // f32  [10][128]  = 5120
#define OB_CF   177152                  // f32  [128][10]  = 5120
#define OB_QB   182272                  // u32  [2][64]    = 512
#define OB_BC1  182784
#define OB_BC2  183296
#define OB_BS1  183808
#define OB_WS2  184320
#define OB_AM   184832
#define OB_PART 185344                  // f32 [128][2] = 1024
#define OB_MISC 186368                  // f32 [8]
#define CAND_SMEM_BYTES 186400

__global__ void __launch_bounds__(256, 1)
cand_kernel(const float* __restrict__ cf,   // [4096*64][10]
            const float* __restrict__ am,   // [4096][64]
            const float* __restrict__ Wc1, const float* __restrict__ bc1,
            const float* __restrict__ Wc2, const float* __restrict__ bc2,
            const float* __restrict__ Ws1, const float* __restrict__ bs1,
            const float* __restrict__ Ws2, const float* __restrict__ bs2,
            const float* __restrict__ q,    // [4096][128]
            float* __restrict__ out) {      // [4096][64]
    extern __shared__ char smc[];
    __nv_bfloat16* Wc2b = (__nv_bfloat16*)(smc + OB_WC2);
    __nv_bfloat16* Ws1b = (__nv_bfloat16*)(smc + OB_WS1);
    __nv_bfloat16* T1b  = (__nv_bfloat16*)(smc + OB_T1);
    __nv_bfloat16* T2b  = (__nv_bfloat16*)(smc + OB_T2);
    float* Wc1t = (float*)(smc + OB_WC1T);
    float* cf_s = (float*)(smc + OB_CF);
    unsigned* qb = (unsigned*)(smc + OB_QB);
    float* bc1s = (float*)(smc + OB_BC1);
    float* bc2s = (float*)(smc + OB_BC2);
    float* bs1s = (float*)(smc + OB_BS1);
    float* Ws2s = (float*)(smc + OB_WS2);
    float* am_s = (float*)(smc + OB_AM);
    float* part = (float*)(smc + OB_PART);
    float* misc = (float*)(smc + OB_MISC);

    const int tid = threadIdx.x;
    const int n0  = blockIdx.x * 2;
    const int base_row = n0 * 64;

    // ---------------- loads ----------------
    for (int i2 = tid; i2 < 8192; i2 += 256) {
        int n = i2 >> 6, kp = i2 & 63;
        float2 v = *reinterpret_cast<const float2*>(&Wc2[n * 128 + 2 * kp]);
        *reinterpret_cast<unsigned*>(&Wc2b[n * STR1 + 2 * kp]) = bf16x2_of(v.x, v.y);
    }
    for (int i2 = tid; i2 < 16384; i2 += 256) {
        int n = i2 >> 7, kp = i2 & 127;
        float2 v = *reinterpret_cast<const float2*>(&Ws1[n * 256 + 2 * kp]);
        *reinterpret_cast<unsigned*>(&Ws1b[n * STR3 + 2 * kp]) = bf16x2_of(v.x, v.y);
    }
    for (int idx = tid; idx < 1280; idx += 256) {
        int c = idx / 10, j = idx - c * 10;
        Wc1t[j * 128 + c] = Wc1[idx];
    }
    for (int idx = tid; idx < 1280; idx += 256)
        cf_s[idx] = cf[(size_t)base_row * 10 + idx];
    if (tid < 128) {
        int node = tid >> 6, kp = tid & 63;
        float2 qq = *reinterpret_cast<const float2*>(&q[(size_t)(n0 + node) * 128 + 2 * kp]);
        qb[tid] = bf16x2_of(qq.x, qq.y);
        am_s[tid] = am[base_row + tid];
        bc1s[tid] = bc1[tid];
        bc2s[tid] = bc2[tid];
        bs1s[tid] = bs1[tid];
        Ws2s[tid] = Ws2[tid];
    }
    __syncthreads();

    if (tid < 2) {
        float ssum = 0.f;
        for (int c = 0; c < 64; ++c) ssum += am_s[tid * 64 + c];
        misc[tid] = (ssum <= 0.f) ? 1.f : 0.f;
    }

    // ---------------- stage 1 (fp32, K=10) -> T1b bf16 ----------------
    {
        const int rg = tid >> 4;
        const int cg = tid & 15;
        unsigned long long a2[8][4];
#pragma unroll
        for (int r = 0; r < 8; ++r)
#pragma unroll
            for (int c = 0; c < 4; ++c) a2[r][c] = 0ull;
#pragma unroll
        for (int j = 0; j < 10; ++j) {
            longlong2 B0 = *reinterpret_cast<const longlong2*>(&Wc1t[j * 128 + cg * 8]);
            longlong2 B1 = *reinterpret_cast<const longlong2*>(&Wc1t[j * 128 + cg * 8 + 4]);
#pragma unroll
            for (int rr = 0; rr < 8; ++rr) {
                float a = cf_s[(rg * 8 + rr) * 10 + j];
                unsigned long long aa = pack2(a, a);
                a2[rr][0] = ffma2(aa, (unsigned long long)B0.x, a2[rr][0]);
                a2[rr][1] = ffma2(aa, (unsigned long long)B0.y, a2[rr][1]);
                a2[rr][2] = ffma2(aa, (unsigned long long)B1.x, a2[rr][2]);
                a2[rr][3] = ffma2(aa, (unsigned long long)B1.y, a2[rr][3]);
            }
        }
#pragma unroll
        for (int rr = 0; rr < 8; ++rr) {
            int r = rg * 8 + rr;
            float2 p0 = unpack2(a2[rr][0]);
            float2 p1 = unpack2(a2[rr][1]);
            float2 p2 = unpack2(a2[rr][2]);
            float2 p3 = unpack2(a2[rr][3]);
            uint4 o;
            o.x = bf16x2_of(gelu_exact(p0.x + bc1s[cg * 8 + 0]),
                            gelu_exact(p0.y + bc1s[cg * 8 + 1]));
            o.y = bf16x2_of(gelu_exact(p1.x + bc1s[cg * 8 + 2]),
                            gelu_exact(p1.y + bc1s[cg * 8 + 3]));
            o.z = bf16x2_of(gelu_exact(p2.x + bc1s[cg * 8 + 4]),
                            gelu_exact(p2.y + bc1s[cg * 8 + 5]));
            o.w = bf16x2_of(gelu_exact(p3.x + bc1s[cg * 8 + 6]),
                            gelu_exact(p3.y + bc1s[cg * 8 + 7]));
            *reinterpret_cast<uint4*>(&T1b[r * STR1 + cg * 8]) = o;
        }
    }
    __syncthreads();

    // ---------------- warp/fragment coords ----------------
    const int w    = tid >> 5;
    const int lane = tid & 31;
    const int fg   = lane >> 2;
    const int ft   = lane & 3;
    const int wm   = w & 3;
    const int wn   = w >> 2;
    const int m0   = wm * 32;
    const int nc0  = wn * 64;
    const int node = wm >> 1;

    float acc[2][8][4];

    // ---------------- stage 2: T2 = gelu(T1 @ Wc2^T + bc2) ----------------
#pragma unroll
    for (int mt = 0; mt < 2; ++mt)
#pragma unroll
        for (int i = 0; i < 8; ++i)
#pragma unroll
            for (int k = 0; k < 4; ++k) acc[mt][i][k] = 0.f;

#pragma unroll
    for (int s = 0; s < 8; ++s) {
        const int k0 = 16 * s;
        unsigned A[2][4];
#pragma unroll
        for (int mt = 0; mt < 2; ++mt) {
            const int rb = (m0 + 16 * mt + fg) * STR1 + k0 + 2 * ft;
            A[mt][0] = *reinterpret_cast<const unsigned*>(&T1b[rb]);
            A[mt][1] = *reinterpret_cast<const unsigned*>(&T1b[rb + 8 * STR1]);
            A[mt][2] = *reinterpret_cast<const unsigned*>(&T1b[rb + 8]);
            A[mt][3] = *reinterpret_cast<const unsigned*>(&T1b[rb + 8 * STR1 + 8]);
        }
#pragma unroll
        for (int i = 0; i < 8; ++i) {
            const int bb = (nc0 + 8 * i + fg) * STR1 + k0 + 2 * ft;
            unsigned B0 = *reinterpret_cast<const unsigned*>(&Wc2b[bb]);
            unsigned B1 = *reinterpret_cast<const unsigned*>(&Wc2b[bb + 8]);
            mma16816(acc[0][i], A[0], B0, B1);
            mma16816(acc[1][i], A[1], B0, B1);
        }
    }

#pragma unroll
    for (int mt = 0; mt < 2; ++mt) {
#pragma unroll
        for (int i = 0; i < 8; ++i) {
            const int c0 = nc0 + 8 * i + 2 * ft;
            const int rlo = m0 + 16 * mt + fg;
            float2 bc = *reinterpret_cast<const float2*>(&bc2s[c0]);
            unsigned lo = bf16x2_of(gelu_exact(acc[mt][i][0] + bc.x),
                                    gelu_exact(acc[mt][i][1] + bc.y));
            unsigned hi = bf16x2_of(gelu_exact(acc[mt][i][2] + bc.x),
                                    gelu_exact(acc[mt][i][3] + bc.y));
            *reinterpret_cast<unsigned*>(&T2b[rlo * STR1 + c0]) = lo;
            *reinterpret_cast<unsigned*>(&T2b[(rlo + 8) * STR1 + c0]) = hi;
        }
    }
    __syncthreads();

    // ---------------- stage 3: [q*T2 | T2] @ Ws1^T ----------------
#pragma unroll
    for (int mt = 0; mt < 2; ++mt)
#pragma unroll
        for (int i = 0; i < 8; ++i)
#pragma unroll
            for (int k = 0; k < 4; ++k) acc[mt][i][k] = 0.f;

#pragma unroll
    for (int p = 0; p < 2; ++p) {
#pragma unroll
        for (int s = 0; s < 8; ++s) {
            const int k0 = 16 * s;
            unsigned A[2][4];
#pragma unroll
            for (int mt = 0; mt < 2; ++mt) {
                const int rb = (m0 + 16 * mt + fg) * STR1 + k0 + 2 * ft;
                A[mt][0] = *reinterpret_cast<const unsigned*>(&T2b[rb]);
                A[mt][1] = *reinterpret_cast<const unsigned*>(&T2b[rb + 8 * STR1]);
                A[mt][2] = *reinterpret_cast<const unsigned*>(&T2b[rb + 8]);
                A[mt][3] = *reinterpret_cast<const unsigned*>(&T2b[rb + 8 * STR1 + 8]);
            }
            if (p == 0) {
                unsigned q0 = qb[node * 64 + 8 * s + ft];
                unsigned q1 = qb[node * 64 + 8 * s + ft + 4];
#pragma unroll
                for (int mt = 0; mt < 2; ++mt) {
                    A[mt][0] = mul_bf16x2(A[mt][0], q0);
                    A[mt][1] = mul_bf16x2(A[mt][1], q0);
                    A[mt][2] = mul_bf16x2(A[mt][2], q1);
                    A[mt][3] = mul_bf16x2(A[mt][3], q1);
                }
            }
#pragma unroll
            for (int i = 0; i < 8; ++i) {
                const int bb = (nc0 + 8 * i + fg) * STR3 + p * 128 + k0 + 2 * ft;
                unsigned B0 = *reinterpret_cast<const unsigned*>(&Ws1b[bb]);
                unsigned B1 = *reinterpret_cast<const unsigned*>(&Ws1b[bb + 8]);
                mma16816(acc[0][i], A[0], B0, B1);
                mma16816(acc[1][i], A[1], B0, B1);
            }
        }
    }

    // ---- epilogue: gelu(+bs1) * Ws2, row-reduce ----
    float rs0[2] = {0.f, 0.f};
    float rs1[2] = {0.f, 0.f};
#pragma unroll
    for (int mt = 0; mt < 2; ++mt) {
#pragma unroll
        for (int i = 0; i < 8; ++i) {
            const int c0 = nc0 + 8 * i + 2 * ft;
            float2 b1 = *reinterpret_cast<const float2*>(&bs1s[c0]);
            float2 w2 = *reinterpret_cast<const float2*>(&Ws2s[c0]);
            rs0[mt] += gelu_exact(acc[mt][i][0] + b1.x) * w2.x
                     + gelu_exact(acc[mt][i][1] + b1.y) * w2.y;
            rs1[mt] += gelu_exact(acc[mt][i][2] + b1.x) * w2.x
                     + gelu_exact(acc[mt][i][3] + b1.y) * w2.y;
        }
    }
#pragma unroll
    for (int off = 1; off <= 2; off <<= 1) {
#pragma unroll
        for (int mt = 0; mt < 2; ++mt) {
            rs0[mt] += __shfl_xor_sync(0xffffffffu, rs0[mt], off);
            rs1[mt] += __shfl_xor_sync(0xffffffffu, rs1[mt], off);
        }
    }
    if (ft == 0) {
#pragma unroll
        for (int mt = 0; mt < 2; ++mt) {
            part[(m0 + 16 * mt + fg) * 2 + wn]     = rs0[mt];
            part[(m0 + 16 * mt + 8 + fg) * 2 + wn] = rs1[mt];
        }
    }
    __syncthreads();

    if (tid < 128) {
        const int r = tid;
        const int l = r >> 6, c = r & 63;
        const float* cfr = &cf_s[r * 10];
        float bias = 20.0f * cfr[0] + 4.0f * cfr[4] + 1.5f * cfr[5]
                   + 1.5f * cfr[1] - 1.5f * cfr[2] + 1.2f * cfr[6]
                   + 2.5f * cfr[7] + 1.6f * cfr[8] + 1.2f * cfr[9];
        float logit = part[2 * r] + part[2 * r + 1] + __ldg(&bs2[0]) + bias;
        float amv = am_s[r];
        bool valid = (amv > 0.f) || (c == 0 && misc[l] > 0.5f);
        out[(size_t)(n0 + l) * 64 + c] = valid ? logit : NEGV;
    }
}

// =========================================================================
extern "C" void kernel_launch(void* const* d_in, const int* in_sizes, int n_in,
                              void* d_out, int out_size) {
    const float* x    = (const float*)d_in[0];
    const float* cf   = (const float*)d_in[1];
    const int*   adj  = (const int*)  d_in[2];
    const float* am   = (const float*)d_in[3];
    const float* W1   = (const float*)d_in[4];
    const float* a1s  = (const float*)d_in[5];
    const float* a1d  = (const float*)d_in[6];
    const float* W2   = (const float*)d_in[7];
    const float* a2s  = (const float*)d_in[8];
    const float* a2d  = (const float*)d_in[9];
    const float* lnw  = (const float*)d_in[10];
    const float* lnb  = (const float*)d_in[11];
    const float* Wc1  = (const float*)d_in[12];
    const float* bc1  = (const float*)d_in[13];
    const float* Wc2  = (const float*)d_in[14];
    const float* bc2  = (const float*)d_in[15];
    const float* Wq   = (const float*)d_in[16];
    const float* bq   = (const float*)d_in[17];
    const float* Ws1  = (const float*)d_in[18];
    const float* bs1  = (const float*)d_in[19];
    const float* Ws2  = (const float*)d_in[20];
    const float* bs2  = (const float*)d_in[21];
    float* out = (float*)d_out;

    float *h1, *s1, *d1, *g1, *h2, *s2, *d2, *hn, *qp;
    cudaGetSymbolAddress((void**)&h1, g_h1);
    cudaGetSymbolAddress((void**)&s1, g_s1);
    cudaGetSymbolAddress((void**)&d1, g_d1);
    cudaGetSymbolAddress((void**)&g1, g_g1);
    cudaGetSymbolAddress((void**)&h2, g_h2);
    cudaGetSymbolAddress((void**)&s2, g_s2);
    cudaGetSymbolAddress((void**)&d2, g_d2);
    cudaGetSymbolAddress((void**)&hn, g_hn);
    cudaGetSymbolAddress((void**)&qp, g_q);

    const int smem_k64  = (32 * 64  + 64  * 128) * 4;
    const int smem_k128 = (32 * 128 + 128 * 128) * 4;

    cudaFuncSetAttribute(gemm_attn_kernel,
                         cudaFuncAttributeMaxDynamicSharedMemorySize, smem_k128);
    cudaFuncSetAttribute(cand_kernel,
                         cudaFuncAttributeMaxDynamicSharedMemorySize, CAND_SMEM_BYTES);

    gemm_attn_kernel<<<128, 256, smem_k64>>>(x, 64, W1, a1s, a1d, nullptr,
                                             h1, s1, d1);
    gat_agg_kernel<<<128, 256>>>(h1, s1, d1, adj, nullptr, nullptr, nullptr,
                                 g1, 0);
    gemm_attn_kernel<<<128, 256, smem_k128>>>(g1, 128, W2, a2s, a2d, nullptr,
                                              h2, s2, d2);
    gat_agg_kernel<<<128, 256>>>(h2, s2, d2, adj, g1, lnw, lnb, hn, 1);
    gemm_attn_kernel<<<128, 256, smem_k128>>>(hn, 128, Wq, nullptr, nullptr, bq,
                                              qp, nullptr, nullptr);
    cand_kernel<<<2048, 256, CAND_SMEM_BYTES>>>(cf, am, Wc1, bc1, Wc2, bc2,
                                                Ws1, bs1, Ws2, bs2, qp, out);
}

// round 7
// speedup vs baseline: 3.1352x; 1.2630x over previous
#include <cuda_runtime.h>
#include <cuda_bf16.h>
#include <math.h>

#define N_NODES 4096
#define H_DIM   128
#define NEGV    (-1000000000.0f)

// ---------------- device scratch (no allocations allowed) ----------------
__device__ float g_h1[N_NODES * H_DIM];
__device__ float g_s1[N_NODES];
__device__ float g_d1[N_NODES];
__device__ float g_g1[N_NODES * H_DIM];
__device__ float g_h2[N_NODES * H_DIM];
__device__ float g_s2[N_NODES];
__device__ float g_d2[N_NODES];
__device__ float g_hn[N_NODES * H_DIM];
__device__ float g_q [N_NODES * H_DIM];
__device__ unsigned g_h1b[N_NODES * H_DIM / 2];   // bf16x2 packed h1
__device__ unsigned g_h2b[N_NODES * H_DIM / 2];   // bf16x2 packed h2

__device__ __forceinline__ float gelu_exact(float x) {
    return 0.5f * x * (1.0f + erff(x * 0.70710678118654752440f));
}

// ---- packed fp32x2 FMA ----
__device__ __forceinline__ unsigned long long ffma2(unsigned long long a,
                                                    unsigned long long b,
                                                    unsigned long long c) {
    unsigned long long d;
    asm("fma.rn.f32x2 %0, %1, %2, %3;" : "=l"(d) : "l"(a), "l"(b), "l"(c));
    return d;
}
__device__ __forceinline__ unsigned long long pack2(float x, float y) {
    unsigned long long d;
    asm("mov.b64 %0, {%1, %2};" : "=l"(d) : "f"(x), "f"(y));
    return d;
}
__device__ __forceinline__ float2 unpack2(unsigned long long v) {
    float2 r;
    asm("mov.b64 {%0, %1}, %2;" : "=f"(r.x), "=f"(r.y) : "l"(v));
    return r;
}

// ---- bf16 helpers ----
__device__ __forceinline__ unsigned bf16x2_of(float lo, float hi) {
    unsigned r;   // first src -> upper half, second -> lower half
    asm("cvt.rn.bf16x2.f32 %0, %1, %2;" : "=r"(r) : "f"(hi), "f"(lo));
    return r;
}
__device__ __forceinline__ unsigned mul_bf16x2(unsigned a, unsigned b) {
    unsigned r;
    asm("mul.bf16x2 %0, %1, %2;" : "=r"(r) : "r"(a), "r"(b));
    return r;
}
__device__ __forceinline__ void mma16816(float* c, const unsigned* a,
                                         unsigned b0, unsigned b1) {
    asm("mma.sync.aligned.m16n8k16.row.col.f32.bf16.bf16.f32 "
        "{%0,%1,%2,%3}, {%4,%5,%6,%7}, {%8,%9}, {%0,%1,%2,%3};"
        : "+f"(c[0]), "+f"(c[1]), "+f"(c[2]), "+f"(c[3])
        : "r"(a[0]), "r"(a[1]), "r"(a[2]), "r"(a[3]), "r"(b0), "r"(b1));
}
__device__ __forceinline__ void ldsm_x4_t(unsigned& r0, unsigned& r1,
                                          unsigned& r2, unsigned& r3,
                                          unsigned addr) {
    asm volatile("ldmatrix.sync.aligned.m8n8.x4.trans.shared.b16 "
                 "{%0,%1,%2,%3}, [%4];"
                 : "=r"(r0), "=r"(r1), "=r"(r2), "=r"(r3) : "r"(addr));
}
__device__ __forceinline__ unsigned smem_u32(const void* p) {
    return (unsigned)__cvta_generic_to_shared(p);
}

// =========================================================================
// GEMM: out[4096][128] = in[4096][K] @ W[128][K]^T (+bias)
// Optionally also emits a packed bf16 copy (out_bf) for the MMA gat kernel.
// =========================================================================
__global__ void gemm_attn_kernel(const float* __restrict__ in, int K,
                                 const float* __restrict__ W,
                                 const float* __restrict__ a_s,
                                 const float* __restrict__ a_d,
                                 const float* __restrict__ bias,
                                 float* __restrict__ out,
                                 unsigned* __restrict__ out_bf,
                                 float* __restrict__ s_out,
                                 float* __restrict__ d_out) {
    extern __shared__ float sm[];
    float* in_s = sm;            // 32*K
    float* Wt   = sm + 32 * K;   // K*128
    const int tid = threadIdx.x;
    const int i0  = blockIdx.x * 32;

    for (int idx = tid; idx < 32 * K; idx += 256)
        in_s[idx] = in[(size_t)(i0 + idx / K) * K + (idx % K)];
    for (int idx = tid; idx < 128 * K; idx += 256) {
        int c = idx / K, k = idx - c * K;
        Wt[k * 128 + c] = W[idx];
    }
    __syncthreads();

    const int rg = tid >> 5;
    const int lane = tid & 31;
    unsigned long long acc2[4][2];
#pragma unroll
    for (int r = 0; r < 4; ++r) { acc2[r][0] = 0ull; acc2[r][1] = 0ull; }

    for (int k = 0; k < K; ++k) {
        longlong2 B = *reinterpret_cast<const longlong2*>(&Wt[k * 128 + lane * 4]);
#pragma unroll
        for (int rr = 0; rr < 4; ++rr) {
            float a = in_s[(rg * 4 + rr) * K + k];
            unsigned long long aa = pack2(a, a);
            acc2[rr][0] = ffma2(aa, (unsigned long long)B.x, acc2[rr][0]);
            acc2[rr][1] = ffma2(aa, (unsigned long long)B.y, acc2[rr][1]);
        }
    }

    float acc[4][4];
#pragma unroll
    for (int rr = 0; rr < 4; ++rr) {
        float2 p0 = unpack2(acc2[rr][0]);
        float2 p1 = unpack2(acc2[rr][1]);
        acc[rr][0] = p0.x; acc[rr][1] = p0.y; acc[rr][2] = p1.x; acc[rr][3] = p1.y;
    }

#pragma unroll
    for (int rr = 0; rr < 4; ++rr) {
        int row = i0 + rg * 4 + rr;
        float4 v;
        v.x = acc[rr][0]; v.y = acc[rr][1]; v.z = acc[rr][2]; v.w = acc[rr][3];
        if (bias) {
            v.x += bias[lane * 4 + 0];
            v.y += bias[lane * 4 + 1];
            v.z += bias[lane * 4 + 2];
            v.w += bias[lane * 4 + 3];
        }
        *reinterpret_cast<float4*>(&out[(size_t)row * 128 + lane * 4]) = v;
        if (out_bf) {   // bias is null whenever out_bf is set -> v == h exactly
            out_bf[(size_t)row * 64 + lane * 2 + 0] = bf16x2_of(v.x, v.y);
            out_bf[(size_t)row * 64 + lane * 2 + 1] = bf16x2_of(v.z, v.w);
        }
    }

    if (s_out) {
#pragma unroll
        for (int rr = 0; rr < 4; ++rr) {
            float sp = 0.f, dp = 0.f;
#pragma unroll
            for (int cc = 0; cc < 4; ++cc) {
                int c = lane * 4 + cc;
                sp += acc[rr][cc] * __ldg(&a_s[c]);
                dp += acc[rr][cc] * __ldg(&a_d[c]);
            }
#pragma unroll
            for (int off = 16; off; off >>= 1) {
                sp += __shfl_xor_sync(0xffffffffu, sp, off);
                dp += __shfl_xor_sync(0xffffffffu, dp, off);
            }
            if (lane == 0) {
                s_out[i0 + rg * 4 + rr] = sp;
                d_out[i0 + rg * 4 + rr] = dp;
            }
        }
    }
}

// =========================================================================
// GAT aggregation via bf16 tensor-core MMA.
//   out[32 x 128] = softmax-weights[32 x 4096] @ h[4096 x 128]
// Weight tile (A) generated per 32-j tile into smem bf16 [32][40].
// h tile (B) staged from packed-bf16 gmem into smem [32][136] (natural
// layout); B fragments via ldmatrix.x4.trans (conflict-free: 272B row
// stride => rows land in disjoint 16B regions mod 128).
// Epilogue: 1/Z, relu, (+res, LayerNorm) in fp32 via smem re-layout.
// =========================================================================
#define GB_H0 0          // h_sb buf0: 32*136 bf16 = 8704 B
#define GB_H1 8704       // h_sb buf1
#define GB_W0 17408      // w_sb buf0: 32*40 bf16 = 2560 B
#define GB_W1 19968      // w_sb buf1
#define GB_TOTAL 22528   // osm (32*132 f32 = 16896 B) aliases offset 0

__global__ void __launch_bounds__(256, 1)
gat_agg_kernel(const unsigned* __restrict__ hb,   // packed bf16 h [4096][64]
               const float* __restrict__ s,
               const float* __restrict__ d,
               const int*   __restrict__ adj,
               const float* __restrict__ res,
               const float* __restrict__ lnw,
               const float* __restrict__ lnb,
               float* __restrict__ out,
               int do_ln) {
    __shared__ __align__(16) char smraw[GB_TOTAL];
    __shared__ float z_s[32];
    __nv_bfloat16* h_sb[2] = { (__nv_bfloat16*)(smraw + GB_H0),
                               (__nv_bfloat16*)(smraw + GB_H1) };
    __nv_bfloat16* w_sb[2] = { (__nv_bfloat16*)(smraw + GB_W0),
                               (__nv_bfloat16*)(smraw + GB_W1) };
    float* osm = (float*)smraw;                 // [32][132] after main loop

    const int tid = threadIdx.x;
    const int i0  = blockIdx.x * 32;

    const int lane = tid & 31;
    const int w    = tid >> 5;
    const int rg   = w;              // h-staging row group
    const int wi   = tid >> 3;       // weight row 0..31
    const int wj   = (tid & 7) * 4;  // weight j offset
    const float si = s[i0 + wi];

    // MMA warp coords: 2 m-groups x 4 n-groups
    const int fg = lane >> 2, ft = lane & 3;
    const int m0 = (w & 1) * 16;
    const int n0 = (w >> 1) * 32;
    // lane-dependent ldmatrix row offset (bf16-elem units), within h tile
    const int lm_ti = lane >> 3, lm_r = lane & 7;
    const int lm_off = ((lm_ti & 1) * 8 + lm_r) * 136 + (lm_ti >> 1) * 8;
    const unsigned hb_u32[2] = { smem_u32(h_sb[0]), smem_u32(h_sb[1]) };
    // A-fragment base (bf16-elem units)
    const int aw = (m0 + fg) * 40 + 2 * ft;

    float zacc = 0.f;
    float acc[4][4];
#pragma unroll
    for (int i = 0; i < 4; ++i)
#pragma unroll
        for (int k = 0; k < 4; ++k) acc[i][k] = 0.f;

    // staging registers
    int4 av; float4 dv; uint2 hv0, hv1, hv2, hv3;

#define GAT_LOAD(J0)                                                          \
    do {                                                                      \
        av = *reinterpret_cast<const int4*>(                                  \
            &adj[(size_t)(i0 + wi) * N_NODES + (J0) + wj]);                   \
        dv = *reinterpret_cast<const float4*>(&d[(J0) + wj]);                 \
        const uint2* h2p = reinterpret_cast<const uint2*>(hb);                \
        hv0 = h2p[(size_t)((J0) + rg +  0) * 32 + lane];                      \
        hv1 = h2p[(size_t)((J0) + rg +  8) * 32 + lane];                      \
        hv2 = h2p[(size_t)((J0) + rg + 16) * 32 + lane];                      \
        hv3 = h2p[(size_t)((J0) + rg + 24) * 32 + lane];                      \
    } while (0)

#define GAT_STORE(BUF)                                                        \
    do {                                                                      \
        float w0 = 0.f, w1 = 0.f, w2 = 0.f, w3 = 0.f;                         \
        if (av.x > 0) { float e = si + dv.x; e = (e > 0.f) ? e : 0.2f * e; w0 = __expf(e); } \
        if (av.y > 0) { float e = si + dv.y; e = (e > 0.f) ? e : 0.2f * e; w1 = __expf(e); } \
        if (av.z > 0) { float e = si + dv.z; e = (e > 0.f) ? e : 0.2f * e; w2 = __expf(e); } \
        if (av.w > 0) { float e = si + dv.w; e = (e > 0.f) ? e : 0.2f * e; w3 = __expf(e); } \
        zacc += (w0 + w1) + (w2 + w3);                                        \
        uint2 wp; wp.x = bf16x2_of(w0, w1); wp.y = bf16x2_of(w2, w3);         \
        *reinterpret_cast<uint2*>(&w_sb[BUF][wi * 40 + wj]) = wp;             \
        uint2* hbuf = reinterpret_cast<uint2*>(h_sb[BUF]);                    \
        /* h_sb[j][4*lane..+3]: byte addr j*272 + lane*8 (uint2) */           \
        *reinterpret_cast<uint2*>(&h_sb[BUF][(rg +  0) * 136 + lane * 4]) = hv0; \
        *reinterpret_cast<uint2*>(&h_sb[BUF][(rg +  8) * 136 + lane * 4]) = hv1; \
        *reinterpret_cast<uint2*>(&h_sb[BUF][(rg + 16) * 136 + lane * 4]) = hv2; \
        *reinterpret_cast<uint2*>(&h_sb[BUF][(rg + 24) * 136 + lane * 4]) = hv3; \
        (void)hbuf;                                                           \
    } while (0)

    GAT_LOAD(0);
    GAT_STORE(0);
    __syncthreads();

    int buf = 0;
    for (int t = 0; t < N_NODES / 32; ++t) {
        const int nxt = (t + 1) * 32;
        if (nxt < N_NODES) GAT_LOAD(nxt);

        // ---- MMA on current buffer: 2 k-steps of 16 ----
        const __nv_bfloat16* wb = w_sb[buf];
        const unsigned hbase = hb_u32[buf] + lm_off * 2;
#pragma unroll
        for (int sstep = 0; sstep < 2; ++sstep) {
            const int k0 = 16 * sstep;
            unsigned A[4];
            A[0] = *reinterpret_cast<const unsigned*>(&wb[aw + k0]);
            A[1] = *reinterpret_cast<const unsigned*>(&wb[aw + 320 + k0]);
            A[2] = *reinterpret_cast<const unsigned*>(&wb[aw + k0 + 8]);
            A[3] = *reinterpret_cast<const unsigned*>(&wb[aw + 320 + k0 + 8]);
#pragma unroll
            for (int p = 0; p < 2; ++p) {
                unsigned r0, r1, r2, r3;
                ldsm_x4_t(r0, r1, r2, r3,
                          hbase + (k0 * 136 + n0 + 16 * p) * 2);
                mma16816(acc[2 * p + 0], A, r0, r1);
                mma16816(acc[2 * p + 1], A, r2, r3);
            }
        }

        if (nxt < N_NODES) GAT_STORE(buf ^ 1);
        __syncthreads();
        buf ^= 1;
    }
#undef GAT_LOAD
#undef GAT_STORE

    // Z reduction: 8 lanes per row (aligned groups of 8)
    zacc += __shfl_xor_sync(0xffffffffu, zacc, 4);
    zacc += __shfl_xor_sync(0xffffffffu, zacc, 2);
    zacc += __shfl_xor_sync(0xffffffffu, zacc, 1);
    if ((tid & 7) == 0) z_s[wi] = zacc;

    // write accumulators to osm [32][132] (aliases pipeline buffers; all MMA
    // reads finished at the final loop barrier)
#pragma unroll
    for (int i = 0; i < 4; ++i) {
        const int col = n0 + 8 * i + 2 * ft;
        float2 lo; lo.x = acc[i][0]; lo.y = acc[i][1];
        float2 hi; hi.x = acc[i][2]; hi.y = acc[i][3];
        *reinterpret_cast<float2*>(&osm[(m0 + fg) * 132 + col])     = lo;
        *reinterpret_cast<float2*>(&osm[(m0 + 8 + fg) * 132 + col]) = hi;
    }
    __syncthreads();

    // final epilogue: relu(acc/Z) (+res, LN), fp32
#pragma unroll
    for (int rr = 0; rr < 4; ++rr) {
        const int lrow = rg * 4 + rr;
        const int row  = i0 + lrow;
        const float z = z_s[lrow];
        const float zinv = (z > 0.f) ? (1.0f / z) : 0.f;
        float4 a4 = *reinterpret_cast<const float4*>(&osm[lrow * 132 + lane * 4]);
        float v[4] = {a4.x, a4.y, a4.z, a4.w};
#pragma unroll
        for (int cc = 0; cc < 4; ++cc) {
            float t = fmaxf(v[cc] * zinv, 0.f);
            if (res) t += res[(size_t)row * 128 + lane * 4 + cc];
            v[cc] = t;
        }
        if (do_ln) {
            float sum = v[0] + v[1] + v[2] + v[3];
            float sq  = v[0]*v[0] + v[1]*v[1] + v[2]*v[2] + v[3]*v[3];
#pragma unroll
            for (int off = 16; off; off >>= 1) {
                sum += __shfl_xor_sync(0xffffffffu, sum, off);
                sq  += __shfl_xor_sync(0xffffffffu, sq,  off);
            }
            const float mu  = sum * (1.0f / 128.0f);
            const float var = sq  * (1.0f / 128.0f) - mu * mu;
            const float rs  = rsqrtf(var + 1e-5f);
#pragma unroll
            for (int cc = 0; cc < 4; ++cc) {
                int c = lane * 4 + cc;
                v[cc] = (v[cc] - mu) * rs * __ldg(&lnw[c]) + __ldg(&lnb[c]);
            }
        }
        float4 o; o.x = v[0]; o.y = v[1]; o.z = v[2]; o.w = v[3];
        *reinterpret_cast<float4*>(&out[(size_t)row * 128 + lane * 4]) = o;
    }
}

// =========================================================================
// Candidate head: bf16 tensor-core MMA (m16n8k16), fully fused. (unchanged)
// =========================================================================
#define STR1 136
#define STR3 264

#define OB_WC2  0
#define OB_WS1  34816
#define OB_T1   102400
#define OB_T2   137216
#define OB_WC1T 172032
#define OB_CF   177152
#define OB_QB   182272
#define OB_BC1  182784
#define OB_BC2  183296
#define OB_BS1  183808
#define OB_WS2  184320
#define OB_AM   184832
#define OB_PART 185344
#define OB_MISC 186368
#define CAND_SMEM_BYTES 186400

__global__ void __launch_bounds__(256, 1)
cand_kernel(const float* __restrict__ cf,
            const float* __restrict__ am,
            const float* __restrict__ Wc1, const float* __restrict__ bc1,
            const float* __restrict__ Wc2, const float* __restrict__ bc2,
            const float* __restrict__ Ws1, const float* __restrict__ bs1,
            const float* __restrict__ Ws2, const float* __restrict__ bs2,
            const float* __restrict__ q,
            float* __restrict__ out) {
    extern __shared__ char smc[];
    __nv_bfloat16* Wc2b = (__nv_bfloat16*)(smc + OB_WC2);
    __nv_bfloat16* Ws1b = (__nv_bfloat16*)(smc + OB_WS1);
    __nv_bfloat16* T1b  = (__nv_bfloat16*)(smc + OB_T1);
    __nv_bfloat16* T2b  = (__nv_bfloat16*)(smc + OB_T2);
    float* Wc1t = (float*)(smc + OB_WC1T);
    float* cf_s = (float*)(smc + OB_CF);
    unsigned* qb = (unsigned*)(smc + OB_QB);
    float* bc1s = (float*)(smc + OB_BC1);
    float* bc2s = (float*)(smc + OB_BC2);
    float* bs1s = (float*)(smc + OB_BS1);
    float* Ws2s = (float*)(smc + OB_WS2);
    float* am_s = (float*)(smc + OB_AM);
    float* part = (float*)(smc + OB_PART);
    float* misc = (float*)(smc + OB_MISC);

    const int tid = threadIdx.x;
    const int n0  = blockIdx.x * 2;
    const int base_row = n0 * 64;

    for (int i2 = tid; i2 < 8192; i2 += 256) {
        int n = i2 >> 6, kp = i2 & 63;
        float2 v = *reinterpret_cast<const float2*>(&Wc2[n * 128 + 2 * kp]);
        *reinterpret_cast<unsigned*>(&Wc2b[n * STR1 + 2 * kp]) = bf16x2_of(v.x, v.y);
    }
    for (int i2 = tid; i2 < 16384; i2 += 256) {
        int n = i2 >> 7, kp = i2 & 127;
        float2 v = *reinterpret_cast<const float2*>(&Ws1[n * 256 + 2 * kp]);
        *reinterpret_cast<unsigned*>(&Ws1b[n * STR3 + 2 * kp]) = bf16x2_of(v.x, v.y);
    }
    for (int idx = tid; idx < 1280; idx += 256) {
        int c = idx / 10, j = idx - c * 10;
        Wc1t[j * 128 + c] = Wc1[idx];
    }
    for (int idx = tid; idx < 1280; idx += 256)
        cf_s[idx] = cf[(size_t)base_row * 10 + idx];
    if (tid < 128) {
        int node = tid >> 6, kp = tid & 63;
        float2 qq = *reinterpret_cast<const float2*>(&q[(size_t)(n0 + node) * 128 + 2 * kp]);
        qb[tid] = bf16x2_of(qq.x, qq.y);
        am_s[tid] = am[base_row + tid];
        bc1s[tid] = bc1[tid];
        bc2s[tid] = bc2[tid];
        bs1s[tid] = bs1[tid];
        Ws2s[tid] = Ws2[tid];
    }
    __syncthreads();

    if (tid < 2) {
        float ssum = 0.f;
        for (int c = 0; c < 64; ++c) ssum += am_s[tid * 64 + c];
        misc[tid] = (ssum <= 0.f) ? 1.f : 0.f;
    }

    // ---- stage 1 (fp32, K=10) -> T1b bf16 ----
    {
        const int rg = tid >> 4;
        const int cg = tid & 15;
        unsigned long long a2[8][4];
#pragma unroll
        for (int r = 0; r < 8; ++r)
#pragma unroll
            for (int c = 0; c < 4; ++c) a2[r][c] = 0ull;
#pragma unroll
        for (int j = 0; j < 10; ++j) {
            longlong2 B0 = *reinterpret_cast<const longlong2*>(&Wc1t[j * 128 + cg * 8]);
            longlong2 B1 = *reinterpret_cast<const longlong2*>(&Wc1t[j * 128 + cg * 8 + 4]);
#pragma unroll
            for (int rr = 0; rr < 8; ++rr) {
                float a = cf_s[(rg * 8 + rr) * 10 + j];
                unsigned long long aa = pack2(a, a);
                a2[rr][0] = ffma2(aa, (unsigned long long)B0.x, a2[rr][0]);
                a2[rr][1] = ffma2(aa, (unsigned long long)B0.y, a2[rr][1]);
                a2[rr][2] = ffma2(aa, (unsigned long long)B1.x, a2[rr][2]);
                a2[rr][3] = ffma2(aa, (unsigned long long)B1.y, a2[rr][3]);
            }
        }
#pragma unroll
        for (int rr = 0; rr < 8; ++rr) {
            int r = rg * 8 + rr;
            float2 p0 = unpack2(a2[rr][0]);
            float2 p1 = unpack2(a2[rr][1]);
            float2 p2 = unpack2(a2[rr][2]);
            float2 p3 = unpack2(a2[rr][3]);
            uint4 o;
            o.x = bf16x2_of(gelu_exact(p0.x + bc1s[cg * 8 + 0]),
                            gelu_exact(p0.y + bc1s[cg * 8 + 1]));
            o.y = bf16x2_of(gelu_exact(p1.x + bc1s[cg * 8 + 2]),
                            gelu_exact(p1.y + bc1s[cg * 8 + 3]));
            o.z = bf16x2_of(gelu_exact(p2.x + bc1s[cg * 8 + 4]),
                            gelu_exact(p2.y + bc1s[cg * 8 + 5]));
            o.w = bf16x2_of(gelu_exact(p3.x + bc1s[cg * 8 + 6]),
                            gelu_exact(p3.y + bc1s[cg * 8 + 7]));
            *reinterpret_cast<uint4*>(&T1b[r * STR1 + cg * 8]) = o;
        }
    }
    __syncthreads();

    const int w    = tid >> 5;
    const int lane = tid & 31;
    const int fg   = lane >> 2;
    const int ft   = lane & 3;
    const int wm   = w & 3;
    const int wn   = w >> 2;
    const int m0   = wm * 32;
    const int nc0  = wn * 64;
    const int node = wm >> 1;

    float acc[2][8][4];

#pragma unroll
    for (int mt = 0; mt < 2; ++mt)
#pragma unroll
        for (int i = 0; i < 8; ++i)
#pragma unroll
            for (int k = 0; k < 4; ++k) acc[mt][i][k] = 0.f;

#pragma unroll
    for (int s = 0; s < 8; ++s) {
        const int k0 = 16 * s;
        unsigned A[2][4];
#pragma unroll
        for (int mt = 0; mt < 2; ++mt) {
            const int rb = (m0 + 16 * mt + fg) * STR1 + k0 + 2 * ft;
            A[mt][0] = *reinterpret_cast<const unsigned*>(&T1b[rb]);
            A[mt][1] = *reinterpret_cast<const unsigned*>(&T1b[rb + 8 * STR1]);
            A[mt][2] = *reinterpret_cast<const unsigned*>(&T1b[rb + 8]);
            A[mt][3] = *reinterpret_cast<const unsigned*>(&T1b[rb + 8 * STR1 + 8]);
        }
#pragma unroll
        for (int i = 0; i < 8; ++i) {
            const int bb = (nc0 + 8 * i + fg) * STR1 + k0 + 2 * ft;
            unsigned B0 = *reinterpret_cast<const unsigned*>(&Wc2b[bb]);
            unsigned B1 = *reinterpret_cast<const unsigned*>(&Wc2b[bb + 8]);
            mma16816(acc[0][i], A[0], B0, B1);
            mma16816(acc[1][i], A[1], B0, B1);
        }
    }

#pragma unroll
    for (int mt = 0; mt < 2; ++mt) {
#pragma unroll
        for (int i = 0; i < 8; ++i) {
            const int c0 = nc0 + 8 * i + 2 * ft;
            const int rlo = m0 + 16 * mt + fg;
            float2 bc = *reinterpret_cast<const float2*>(&bc2s[c0]);
            unsigned lo = bf16x2_of(gelu_exact(acc[mt][i][0] + bc.x),
                                    gelu_exact(acc[mt][i][1] + bc.y));
            unsigned hi = bf16x2_of(gelu_exact(acc[mt][i][2] + bc.x),
                                    gelu_exact(acc[mt][i][3] + bc.y));
            *reinterpret_cast<unsigned*>(&T2b[rlo * STR1 + c0]) = lo;
            *reinterpret_cast<unsigned*>(&T2b[(rlo + 8) * STR1 + c0]) = hi;
        }
    }
    __syncthreads();

#pragma unroll
    for (int mt = 0; mt < 2; ++mt)
#pragma unroll
        for (int i = 0; i < 8; ++i)
#pragma unroll
            for (int k = 0; k < 4; ++k) acc[mt][i][k] = 0.f;

#pragma unroll
    for (int p = 0; p < 2; ++p) {
#pragma unroll
        for (int s = 0; s < 8; ++s) {
            const int k0 = 16 * s;
            unsigned A[2][4];
#pragma unroll
            for (int mt = 0; mt < 2; ++mt) {
                const int rb = (m0 + 16 * mt + fg) * STR1 + k0 + 2 * ft;
                A[mt][0] = *reinterpret_cast<const unsigned*>(&T2b[rb]);
                A[mt][1] = *reinterpret_cast<const unsigned*>(&T2b[rb + 8 * STR1]);
                A[mt][2] = *reinterpret_cast<const unsigned*>(&T2b[rb + 8]);
                A[mt][3] = *reinterpret_cast<const unsigned*>(&T2b[rb + 8 * STR1 + 8]);
            }
            if (p == 0) {
                unsigned q0 = qb[node * 64 + 8 * s + ft];
                unsigned q1 = qb[node * 64 + 8 * s + ft + 4];
#pragma unroll
                for (int mt = 0; mt < 2; ++mt) {
                    A[mt][0] = mul_bf16x2(A[mt][0], q0);
                    A[mt][1] = mul_bf16x2(A[mt][1], q0);
                    A[mt][2] = mul_bf16x2(A[mt][2], q1);
                    A[mt][3] = mul_bf16x2(A[mt][3], q1);
                }
            }
#pragma unroll
            for (int i = 0; i < 8; ++i) {
                const int bb = (nc0 + 8 * i + fg) * STR3 + p * 128 + k0 + 2 * ft;
                unsigned B0 = *reinterpret_cast<const unsigned*>(&Ws1b[bb]);
                unsigned B1 = *reinterpret_cast<const unsigned*>(&Ws1b[bb + 8]);
                mma16816(acc[0][i], A[0], B0, B1);
                mma16816(acc[1][i], A[1], B0, B1);
            }
        }
    }

    float rs0[2] = {0.f, 0.f};
    float rs1[2] = {0.f, 0.f};
#pragma unroll
    for (int mt = 0; mt < 2; ++mt) {
#pragma unroll
        for (int i = 0; i < 8; ++i) {
            const int c0 = nc0 + 8 * i + 2 * ft;
            float2 b1 = *reinterpret_cast<const float2*>(&bs1s[c0]);
            float2 w2 = *reinterpret_cast<const float2*>(&Ws2s[c0]);
            rs0[mt] += gelu_exact(acc[mt][i][0] + b1.x) * w2.x
                     + gelu_exact(acc[mt][i][1] + b1.y) * w2.y;
            rs1[mt] += gelu_exact(acc[mt][i][2] + b1.x) * w2.x
                     + gelu_exact(acc[mt][i][3] + b1.y) * w2.y;
        }
    }
#pragma unroll
    for (int off = 1; off <= 2; off <<= 1) {
#pragma unroll
        for (int mt = 0; mt < 2; ++mt) {
            rs0[mt] += __shfl_xor_sync(0xffffffffu, rs0[mt], off);
            rs1[mt] += __shfl_xor_sync(0xffffffffu, rs1[mt], off);
        }
    }
    if (ft == 0) {
#pragma unroll
        for (int mt = 0; mt < 2; ++mt) {
            part[(m0 + 16 * mt + fg) * 2 + wn]     = rs0[mt];
            part[(m0 + 16 * mt + 8 + fg) * 2 + wn] = rs1[mt];
        }
    }
    __syncthreads();

    if (tid < 128) {
        const int r = tid;
        const int l = r >> 6, c = r & 63;
        const float* cfr = &cf_s[r * 10];
        float bias = 20.0f * cfr[0] + 4.0f * cfr[4] + 1.5f * cfr[5]
                   + 1.5f * cfr[1] - 1.5f * cfr[2] + 1.2f * cfr[6]
                   + 2.5f * cfr[7] + 1.6f * cfr[8] + 1.2f * cfr[9];
        float logit = part[2 * r] + part[2 * r + 1] + __ldg(&bs2[0]) + bias;
        float amv = am_s[r];
        bool valid = (amv > 0.f) || (c == 0 && misc[l] > 0.5f);
        out[(size_t)(n0 + l) * 64 + c] = valid ? logit : NEGV;
    }
}

// =========================================================================
extern "C" void kernel_launch(void* const* d_in, const int* in_sizes, int n_in,
                              void* d_out, int out_size) {
    const float* x    = (const float*)d_in[0];
    const float* cf   = (const float*)d_in[1];
    const int*   adj  = (const int*)  d_in[2];
    const float* am   = (const float*)d_in[3];
    const float* W1   = (const float*)d_in[4];
    const float* a1s  = (const float*)d_in[5];
    const float* a1d  = (const float*)d_in[6];
    const float* W2   = (const float*)d_in[7];
    const float* a2s  = (const float*)d_in[8];
    const float* a2d  = (const float*)d_in[9];
    const float* lnw  = (const float*)d_in[10];
    const float* lnb  = (const float*)d_in[11];
    const float* Wc1  = (const float*)d_in[12];
    const float* bc1  = (const float*)d_in[13];
    const float* Wc2  = (const float*)d_in[14];
    const float* bc2  = (const float*)d_in[15];
    const float* Wq   = (const float*)d_in[16];
    const float* bq   = (const float*)d_in[17];
    const float* Ws1  = (const float*)d_in[18];
    const float* bs1  = (const float*)d_in[19];
    const float* Ws2  = (const float*)d_in[20];
    const float* bs2  = (const float*)d_in[21];
    float* out = (float*)d_out;

    float *h1, *s1, *d1, *g1, *h2, *s2, *d2, *hn, *qp;
    unsigned *h1b, *h2b;
    cudaGetSymbolAddress((void**)&h1, g_h1);
    cudaGetSymbolAddress((void**)&s1, g_s1);
    cudaGetSymbolAddress((void**)&d1, g_d1);
    cudaGetSymbolAddress((void**)&g1, g_g1);
    cudaGetSymbolAddress((void**)&h2, g_h2);
    cudaGetSymbolAddress((void**)&s2, g_s2);
    cudaGetSymbolAddress((void**)&d2, g_d2);
    cudaGetSymbolAddress((void**)&hn, g_hn);
    cudaGetSymbolAddress((void**)&qp, g_q);
    cudaGetSymbolAddress((void**)&h1b, g_h1b);
    cudaGetSymbolAddress((void**)&h2b, g_h2b);

    const int smem_k64  = (32 * 64  + 64  * 128) * 4;
    const int smem_k128 = (32 * 128 + 128 * 128) * 4;

    cudaFuncSetAttribute(gemm_attn_kernel,
                         cudaFuncAttributeMaxDynamicSharedMemorySize, smem_k128);
    cudaFuncSetAttribute(cand_kernel,
                         cudaFuncAttributeMaxDynamicSharedMemorySize, CAND_SMEM_BYTES);

    // layer 1
    gemm_attn_kernel<<<128, 256, smem_k64>>>(x, 64, W1, a1s, a1d, nullptr,
                                             h1, h1b, s1, d1);
    gat_agg_kernel<<<128, 256>>>(h1b, s1, d1, adj, nullptr, nullptr, nullptr,
                                 g1, 0);
    // layer 2 + residual + LN
    gemm_attn_kernel<<<128, 256, smem_k128>>>(g1, 128, W2, a2s, a2d, nullptr,
                                              h2, h2b, s2, d2);
    gat_agg_kernel<<<128, 256>>>(h2b, s2, d2, adj, g1, lnw, lnb, hn, 1);
    // q projection
    gemm_attn_kernel<<<128, 256, smem_k128>>>(hn, 128, Wq, nullptr, nullptr, bq,
                                              qp, nullptr, nullptr, nullptr);
    // fused candidate head
    cand_kernel<<<2048, 256, CAND_SMEM_BYTES>>>(cf, am, Wc1, bc1, Wc2, bc2,
                                                Ws1, bs1, Ws2, bs2, qp, out);
}

// round 8
// speedup vs baseline: 3.2966x; 1.0515x over previous
#include <cuda_runtime.h>
#include <cuda_bf16.h>
#include <math.h>

#define N_NODES 4096
#define H_DIM   128
#define NEGV    (-1000000000.0f)
#define GAT_SPLITS 8
#define J_PER_SPLIT (N_NODES / GAT_SPLITS)   // 512 -> 16 tiles of 32

// ---------------- device scratch (no allocations allowed) ----------------
__device__ float g_h1[N_NODES * H_DIM];
__device__ float g_s1[N_NODES];
__device__ float g_d1[N_NODES];
__device__ float g_g1[N_NODES * H_DIM];
__device__ float g_h2[N_NODES * H_DIM];
__device__ float g_s2[N_NODES];
__device__ float g_d2[N_NODES];
__device__ float g_hn[N_NODES * H_DIM];
__device__ float g_q [N_NODES * H_DIM];
__device__ unsigned g_h1b[N_NODES * H_DIM / 2];   // bf16x2 packed h1
__device__ unsigned g_h2b[N_NODES * H_DIM / 2];   // bf16x2 packed h2
__device__ float g_part[GAT_SPLITS * N_NODES * H_DIM];  // split-K partials (16MB)
__device__ float g_zp [GAT_SPLITS * N_NODES];           // split-K partial Z

__device__ __forceinline__ float gelu_exact(float x) {
    return 0.5f * x * (1.0f + erff(x * 0.70710678118654752440f));
}

// ---- packed fp32x2 FMA ----
__device__ __forceinline__ unsigned long long ffma2(unsigned long long a,
                                                    unsigned long long b,
                                                    unsigned long long c) {
    unsigned long long d;
    asm("fma.rn.f32x2 %0, %1, %2, %3;" : "=l"(d) : "l"(a), "l"(b), "l"(c));
    return d;
}
__device__ __forceinline__ unsigned long long pack2(float x, float y) {
    unsigned long long d;
    asm("mov.b64 %0, {%1, %2};" : "=l"(d) : "f"(x), "f"(y));
    return d;
}
__device__ __forceinline__ float2 unpack2(unsigned long long v) {
    float2 r;
    asm("mov.b64 {%0, %1}, %2;" : "=f"(r.x), "=f"(r.y) : "l"(v));
    return r;
}

// ---- bf16 helpers ----
__device__ __forceinline__ unsigned bf16x2_of(float lo, float hi) {
    unsigned r;
    asm("cvt.rn.bf16x2.f32 %0, %1, %2;" : "=r"(r) : "f"(hi), "f"(lo));
    return r;
}
__device__ __forceinline__ unsigned mul_bf16x2(unsigned a, unsigned b) {
    unsigned r;
    asm("mul.bf16x2 %0, %1, %2;" : "=r"(r) : "r"(a), "r"(b));
    return r;
}
__device__ __forceinline__ void mma16816(float* c, const unsigned* a,
                                         unsigned b0, unsigned b1) {
    asm("mma.sync.aligned.m16n8k16.row.col.f32.bf16.bf16.f32 "
        "{%0,%1,%2,%3}, {%4,%5,%6,%7}, {%8,%9}, {%0,%1,%2,%3};"
        : "+f"(c[0]), "+f"(c[1]), "+f"(c[2]), "+f"(c[3])
        : "r"(a[0]), "r"(a[1]), "r"(a[2]), "r"(a[3]), "r"(b0), "r"(b1));
}
__device__ __forceinline__ void ldsm_x4_t(unsigned& r0, unsigned& r1,
                                          unsigned& r2, unsigned& r3,
                                          unsigned addr) {
    asm volatile("ldmatrix.sync.aligned.m8n8.x4.trans.shared.b16 "
                 "{%0,%1,%2,%3}, [%4];"
                 : "=r"(r0), "=r"(r1), "=r"(r2), "=r"(r3) : "r"(addr));
}
__device__ __forceinline__ unsigned smem_u32(const void* p) {
    return (unsigned)__cvta_generic_to_shared(p);
}

// =========================================================================
// GEMM: out[4096][128] = in[4096][K] @ W[128][K]^T (+bias) (+bf16 copy)
// =========================================================================
__global__ void gemm_attn_kernel(const float* __restrict__ in, int K,
                                 const float* __restrict__ W,
                                 const float* __restrict__ a_s,
                                 const float* __restrict__ a_d,
                                 const float* __restrict__ bias,
                                 float* __restrict__ out,
                                 unsigned* __restrict__ out_bf,
                                 float* __restrict__ s_out,
                                 float* __restrict__ d_out) {
    extern __shared__ float sm[];
    float* in_s = sm;            // 32*K
    float* Wt   = sm + 32 * K;   // K*128
    const int tid = threadIdx.x;
    const int i0  = blockIdx.x * 32;

    for (int idx = tid; idx < 32 * K; idx += 256)
        in_s[idx] = in[(size_t)(i0 + idx / K) * K + (idx % K)];
    for (int idx = tid; idx < 128 * K; idx += 256) {
        int c = idx / K, k = idx - c * K;
        Wt[k * 128 + c] = W[idx];
    }
    __syncthreads();

    const int rg = tid >> 5;
    const int lane = tid & 31;
    unsigned long long acc2[4][2];
#pragma unroll
    for (int r = 0; r < 4; ++r) { acc2[r][0] = 0ull; acc2[r][1] = 0ull; }

    for (int k = 0; k < K; ++k) {
        longlong2 B = *reinterpret_cast<const longlong2*>(&Wt[k * 128 + lane * 4]);
#pragma unroll
        for (int rr = 0; rr < 4; ++rr) {
            float a = in_s[(rg * 4 + rr) * K + k];
            unsigned long long aa = pack2(a, a);
            acc2[rr][0] = ffma2(aa, (unsigned long long)B.x, acc2[rr][0]);
            acc2[rr][1] = ffma2(aa, (unsigned long long)B.y, acc2[rr][1]);
        }
    }

    float acc[4][4];
#pragma unroll
    for (int rr = 0; rr < 4; ++rr) {
        float2 p0 = unpack2(acc2[rr][0]);
        float2 p1 = unpack2(acc2[rr][1]);
        acc[rr][0] = p0.x; acc[rr][1] = p0.y; acc[rr][2] = p1.x; acc[rr][3] = p1.y;
    }

#pragma unroll
    for (int rr = 0; rr < 4; ++rr) {
        int row = i0 + rg * 4 + rr;
        float4 v;
        v.x = acc[rr][0]; v.y = acc[rr][1]; v.z = acc[rr][2]; v.w = acc[rr][3];
        if (bias) {
            v.x += bias[lane * 4 + 0];
            v.y += bias[lane * 4 + 1];
            v.z += bias[lane * 4 + 2];
            v.w += bias[lane * 4 + 3];
        }
        *reinterpret_cast<float4*>(&out[(size_t)row * 128 + lane * 4]) = v;
        if (out_bf) {
            out_bf[(size_t)row * 64 + lane * 2 + 0] = bf16x2_of(v.x, v.y);
            out_bf[(size_t)row * 64 + lane * 2 + 1] = bf16x2_of(v.z, v.w);
        }
    }

    if (s_out) {
#pragma unroll
        for (int rr = 0; rr < 4; ++rr) {
            float sp = 0.f, dp = 0.f;
#pragma unroll
            for (int cc = 0; cc < 4; ++cc) {
                int c = lane * 4 + cc;
                sp += acc[rr][cc] * __ldg(&a_s[c]);
                dp += acc[rr][cc] * __ldg(&a_d[c]);
            }
#pragma unroll
            for (int off = 16; off; off >>= 1) {
                sp += __shfl_xor_sync(0xffffffffu, sp, off);
                dp += __shfl_xor_sync(0xffffffffu, dp, off);
            }
            if (lane == 0) {
                s_out[i0 + rg * 4 + rr] = sp;
                d_out[i0 + rg * 4 + rr] = dp;
            }
        }
    }
}

// =========================================================================
// GAT split-K partial: block (bx=i-tile, by=split) computes
//   part[split][i0..i0+31][0..127] = sum_{j in split} w_ij * h[j][:]
//   zp[split][i] = sum_{j in split} w_ij
// bf16 MMA mainloop identical to R7, 16 tiles per block.
// =========================================================================
#define GB_H0 0          // h buf0: 32*136 bf16 = 8704 B
#define GB_H1 8704
#define GB_W0 17408      // w buf0: 32*40 bf16 = 2560 B
#define GB_W1 19968
#define GB_TOTAL 22528

__global__ void __launch_bounds__(256, 3)
gat_part_kernel(const unsigned* __restrict__ hb,   // packed bf16 h [4096][64]
                const float* __restrict__ s,
                const float* __restrict__ d,
                const int*   __restrict__ adj,
                float* __restrict__ part,          // [S][4096][128]
                float* __restrict__ zp) {          // [S][4096]
    __shared__ __align__(16) char smraw[GB_TOTAL];
    __nv_bfloat16* h_sb[2] = { (__nv_bfloat16*)(smraw + GB_H0),
                               (__nv_bfloat16*)(smraw + GB_H1) };
    __nv_bfloat16* w_sb[2] = { (__nv_bfloat16*)(smraw + GB_W0),
                               (__nv_bfloat16*)(smraw + GB_W1) };

    const int tid = threadIdx.x;
    const int i0  = blockIdx.x * 32;
    const int sz  = blockIdx.y;
    const int jb  = sz * J_PER_SPLIT;

    const int lane = tid & 31;
    const int w    = tid >> 5;
    const int rg   = w;              // h-staging row group
    const int wi   = tid >> 3;       // weight row 0..31
    const int wj   = (tid & 7) * 4;  // weight j offset
    const float si = s[i0 + wi];

    const int fg = lane >> 2, ft = lane & 3;
    const int m0 = (w & 1) * 16;
    const int n0 = (w >> 1) * 32;
    const int lm_ti = lane >> 3, lm_r = lane & 7;
    const int lm_off = ((lm_ti & 1) * 8 + lm_r) * 136 + (lm_ti >> 1) * 8;
    const unsigned hb_u32[2] = { smem_u32(h_sb[0]), smem_u32(h_sb[1]) };
    const int aw = (m0 + fg) * 40 + 2 * ft;

    float zacc = 0.f;
    float acc[4][4];
#pragma unroll
    for (int i = 0; i < 4; ++i)
#pragma unroll
        for (int k = 0; k < 4; ++k) acc[i][k] = 0.f;

    int4 av; float4 dv; uint2 hv0, hv1, hv2, hv3;

#define GAT_LOAD(J0)                                                          \
    do {                                                                      \
        av = *reinterpret_cast<const int4*>(                                  \
            &adj[(size_t)(i0 + wi) * N_NODES + (J0) + wj]);                   \
        dv = *reinterpret_cast<const float4*>(&d[(J0) + wj]);                 \
        const uint2* h2p = reinterpret_cast<const uint2*>(hb);                \
        hv0 = h2p[(size_t)((J0) + rg +  0) * 32 + lane];                      \
        hv1 = h2p[(size_t)((J0) + rg +  8) * 32 + lane];                      \
        hv2 = h2p[(size_t)((J0) + rg + 16) * 32 + lane];                      \
        hv3 = h2p[(size_t)((J0) + rg + 24) * 32 + lane];                      \
    } while (0)

#define GAT_STORE(BUF)                                                        \
    do {                                                                      \
        float w0 = 0.f, w1 = 0.f, w2 = 0.f, w3 = 0.f;                         \
        if (av.x > 0) { float e = si + dv.x; e = (e > 0.f) ? e : 0.2f * e; w0 = __expf(e); } \
        if (av.y > 0) { float e = si + dv.y; e = (e > 0.f) ? e : 0.2f * e; w1 = __expf(e); } \
        if (av.z > 0) { float e = si + dv.z; e = (e > 0.f) ? e : 0.2f * e; w2 = __expf(e); } \
        if (av.w > 0) { float e = si + dv.w; e = (e > 0.f) ? e : 0.2f * e; w3 = __expf(e); } \
        zacc += (w0 + w1) + (w2 + w3);                                        \
        uint2 wp; wp.x = bf16x2_of(w0, w1); wp.y = bf16x2_of(w2, w3);         \
        *reinterpret_cast<uint2*>(&w_sb[BUF][wi * 40 + wj]) = wp;             \
        *reinterpret_cast<uint2*>(&h_sb[BUF][(rg +  0) * 136 + lane * 4]) = hv0; \
        *reinterpret_cast<uint2*>(&h_sb[BUF][(rg +  8) * 136 + lane * 4]) = hv1; \
        *reinterpret_cast<uint2*>(&h_sb[BUF][(rg + 16) * 136 + lane * 4]) = hv2; \
        *reinterpret_cast<uint2*>(&h_sb[BUF][(rg + 24) * 136 + lane * 4]) = hv3; \
    } while (0)

    GAT_LOAD(jb);
    GAT_STORE(0);
    __syncthreads();

    int buf = 0;
    const int NT = J_PER_SPLIT / 32;    // 16
    for (int t = 0; t < NT; ++t) {
        const int nxt = jb + (t + 1) * 32;
        if (t + 1 < NT) GAT_LOAD(nxt);

        const __nv_bfloat16* wb = w_sb[buf];
        const unsigned hbase = hb_u32[buf] + lm_off * 2;
#pragma unroll
        for (int sstep = 0; sstep < 2; ++sstep) {
            const int k0 = 16 * sstep;
            unsigned A[4];
            A[0] = *reinterpret_cast<const unsigned*>(&wb[aw + k0]);
            A[1] = *reinterpret_cast<const unsigned*>(&wb[aw + 320 + k0]);
            A[2] = *reinterpret_cast<const unsigned*>(&wb[aw + k0 + 8]);
            A[3] = *reinterpret_cast<const unsigned*>(&wb[aw + 320 + k0 + 8]);
#pragma unroll
            for (int p = 0; p < 2; ++p) {
                unsigned r0, r1, r2, r3;
                ldsm_x4_t(r0, r1, r2, r3,
                          hbase + (k0 * 136 + n0 + 16 * p) * 2);
                mma16816(acc[2 * p + 0], A, r0, r1);
                mma16816(acc[2 * p + 1], A, r2, r3);
            }
        }

        if (t + 1 < NT) GAT_STORE(buf ^ 1);
        __syncthreads();
        buf ^= 1;
    }
#undef GAT_LOAD
#undef GAT_STORE

    // partial Z: 8 aligned lanes per row
    zacc += __shfl_xor_sync(0xffffffffu, zacc, 4);
    zacc += __shfl_xor_sync(0xffffffffu, zacc, 2);
    zacc += __shfl_xor_sync(0xffffffffu, zacc, 1);
    if ((tid & 7) == 0) zp[(size_t)sz * N_NODES + i0 + wi] = zacc;

    // partial accumulators straight from fragments
    float* pb = &part[((size_t)sz * N_NODES + i0) * 128];
#pragma unroll
    for (int i = 0; i < 4; ++i) {
        const int col = n0 + 8 * i + 2 * ft;
        float2 lo; lo.x = acc[i][0]; lo.y = acc[i][1];
        float2 hi; hi.x = acc[i][2]; hi.y = acc[i][3];
        *reinterpret_cast<float2*>(&pb[(m0 + fg) * 128 + col])     = lo;
        *reinterpret_cast<float2*>(&pb[(m0 + 8 + fg) * 128 + col]) = hi;
    }
}

// =========================================================================
// GAT reduce: sum 8 partials + Z, then relu(acc/Z) (+res, LayerNorm)
// =========================================================================
__global__ void gat_reduce_kernel(const float* __restrict__ part,
                                  const float* __restrict__ zp,
                                  const float* __restrict__ res,
                                  const float* __restrict__ lnw,
                                  const float* __restrict__ lnb,
                                  float* __restrict__ out,
                                  int do_ln) {
    __shared__ float z_s[32];
    const int tid = threadIdx.x;
    const int i0  = blockIdx.x * 32;
    const int rg  = tid >> 5;
    const int lane = tid & 31;

    if (tid < 32) {
        float z = 0.f;
#pragma unroll
        for (int s = 0; s < GAT_SPLITS; ++s)
            z += zp[(size_t)s * N_NODES + i0 + tid];
        z_s[tid] = z;
    }
    __syncthreads();

#pragma unroll
    for (int rr = 0; rr < 4; ++rr) {
        const int lrow = rg * 4 + rr;
        const int row  = i0 + lrow;
        float4 a = make_float4(0.f, 0.f, 0.f, 0.f);
#pragma unroll
        for (int s = 0; s < GAT_SPLITS; ++s) {
            float4 p = *reinterpret_cast<const float4*>(
                &part[((size_t)s * N_NODES + row) * 128 + lane * 4]);
            a.x += p.x; a.y += p.y; a.z += p.z; a.w += p.w;
        }
        const float z = z_s[lrow];
        const float zinv = (z > 0.f) ? (1.0f / z) : 0.f;
        float v[4] = {a.x, a.y, a.z, a.w};
#pragma unroll
        for (int cc = 0; cc < 4; ++cc) {
            float t = fmaxf(v[cc] * zinv, 0.f);
            if (res) t += res[(size_t)row * 128 + lane * 4 + cc];
            v[cc] = t;
        }
        if (do_ln) {
            float sum = v[0] + v[1] + v[2] + v[3];
            float sq  = v[0]*v[0] + v[1]*v[1] + v[2]*v[2] + v[3]*v[3];
#pragma unroll
            for (int off = 16; off; off >>= 1) {
                sum += __shfl_xor_sync(0xffffffffu, sum, off);
                sq  += __shfl_xor_sync(0xffffffffu, sq,  off);
            }
            const float mu  = sum * (1.0f / 128.0f);
            const float var = sq  * (1.0f / 128.0f) - mu * mu;
            const float rs  = rsqrtf(var + 1e-5f);
#pragma unroll
            for (int cc = 0; cc < 4; ++cc) {
                int c = lane * 4 + cc;
                v[cc] = (v[cc] - mu) * rs * __ldg(&lnw[c]) + __ldg(&lnb[c]);
            }
        }
        float4 o; o.x = v[0]; o.y = v[1]; o.z = v[2]; o.w = v[3];
        *reinterpret_cast<float4*>(&out[(size_t)row * 128 + lane * 4]) = o;
    }
}

// =========================================================================
// Candidate head: bf16 tensor-core MMA (unchanged from R7)
// =========================================================================
#define STR1 136
#define STR3 264

#define OB_WC2  0
#define OB_WS1  34816
#define OB_T1   102400
#define OB_T2   137216
#define OB_WC1T 172032
#define OB_CF   177152
#define OB_QB   182272
#define OB_BC1  182784
#define OB_BC2  183296
#define OB_BS1  183808
#define OB_WS2  184320
#define OB_AM   184832
#define OB_PART 185344
#define OB_MISC 186368
#define CAND_SMEM_BYTES 186400

__global__ void __launch_bounds__(256, 1)
cand_kernel(const float* __restrict__ cf,
            const float* __restrict__ am,
            const float* __restrict__ Wc1, const float* __restrict__ bc1,
            const float* __restrict__ Wc2, const float* __restrict__ bc2,
            const float* __restrict__ Ws1, const float* __restrict__ bs1,
            const float* __restrict__ Ws2, const float* __restrict__ bs2,
            const float* __restrict__ q,
            float* __restrict__ out) {
    extern __shared__ char smc[];
    __nv_bfloat16* Wc2b = (__nv_bfloat16*)(smc + OB_WC2);
    __nv_bfloat16* Ws1b = (__nv_bfloat16*)(smc + OB_WS1);
    __nv_bfloat16* T1b  = (__nv_bfloat16*)(smc + OB_T1);
    __nv_bfloat16* T2b  = (__nv_bfloat16*)(smc + OB_T2);
    float* Wc1t = (float*)(smc + OB_WC1T);
    float* cf_s = (float*)(smc + OB_CF);
    unsigned* qb = (unsigned*)(smc + OB_QB);
    float* bc1s = (float*)(smc + OB_BC1);
    float* bc2s = (float*)(smc + OB_BC2);
    float* bs1s = (float*)(smc + OB_BS1);
    float* Ws2s = (float*)(smc + OB_WS2);
    float* am_s = (float*)(smc + OB_AM);
    float* part = (float*)(smc + OB_PART);
    float* misc = (float*)(smc + OB_MISC);

    const int tid = threadIdx.x;
    const int n0  = blockIdx.x * 2;
    const int base_row = n0 * 64;

    for (int i2 = tid; i2 < 8192; i2 += 256) {
        int n = i2 >> 6, kp = i2 & 63;
        float2 v = *reinterpret_cast<const float2*>(&Wc2[n * 128 + 2 * kp]);
        *reinterpret_cast<unsigned*>(&Wc2b[n * STR1 + 2 * kp]) = bf16x2_of(v.x, v.y);
    }
    for (int i2 = tid; i2 < 16384; i2 += 256) {
        int n = i2 >> 7, kp = i2 & 127;
        float2 v = *reinterpret_cast<const float2*>(&Ws1[n * 256 + 2 * kp]);
        *reinterpret_cast<unsigned*>(&Ws1b[n * STR3 + 2 * kp]) = bf16x2_of(v.x, v.y);
    }
    for (int idx = tid; idx < 1280; idx += 256) {
        int c = idx / 10, j = idx - c * 10;
        Wc1t[j * 128 + c] = Wc1[idx];
    }
    for (int idx = tid; idx < 1280; idx += 256)
        cf_s[idx] = cf[(size_t)base_row * 10 + idx];
    if (tid < 128) {
        int node = tid >> 6, kp = tid & 63;
        float2 qq = *reinterpret_cast<const float2*>(&q[(size_t)(n0 + node) * 128 + 2 * kp]);
        qb[tid] = bf16x2_of(qq.x, qq.y);
        am_s[tid] = am[base_row + tid];
        bc1s[tid] = bc1[tid];
        bc2s[tid] = bc2[tid];
        bs1s[tid] = bs1[tid];
        Ws2s[tid] = Ws2[tid];
    }
    __syncthreads();

    if (tid < 2) {
        float ssum = 0.f;
        for (int c = 0; c < 64; ++c) ssum += am_s[tid * 64 + c];
        misc[tid] = (ssum <= 0.f) ? 1.f : 0.f;
    }

    // ---- stage 1 (fp32, K=10) -> T1b bf16 ----
    {
        const int rg = tid >> 4;
        const int cg = tid & 15;
        unsigned long long a2[8][4];
#pragma unroll
        for (int r = 0; r < 8; ++r)
#pragma unroll
            for (int c = 0; c < 4; ++c) a2[r][c] = 0ull;
#pragma unroll
        for (int j = 0; j < 10; ++j) {
            longlong2 B0 = *reinterpret_cast<const longlong2*>(&Wc1t[j * 128 + cg * 8]);
            longlong2 B1 = *reinterpret_cast<const longlong2*>(&Wc1t[j * 128 + cg * 8 + 4]);
#pragma unroll
            for (int rr = 0; rr < 8; ++rr) {
                float a = cf_s[(rg * 8 + rr) * 10 + j];
                unsigned long long aa = pack2(a, a);
                a2[rr][0] = ffma2(aa, (unsigned long long)B0.x, a2[rr][0]);
                a2[rr][1] = ffma2(aa, (unsigned long long)B0.y, a2[rr][1]);
                a2[rr][2] = ffma2(aa, (unsigned long long)B1.x, a2[rr][2]);
                a2[rr][3] = ffma2(aa, (unsigned long long)B1.y, a2[rr][3]);
            }
        }
#pragma unroll
        for (int rr = 0; rr < 8; ++rr) {
            int r = rg * 8 + rr;
            float2 p0 = unpack2(a2[rr][0]);
            float2 p1 = unpack2(a2[rr][1]);
            float2 p2 = unpack2(a2[rr][2]);
            float2 p3 = unpack2(a2[rr][3]);
            uint4 o;
            o.x = bf16x2_of(gelu_exact(p0.x + bc1s[cg * 8 + 0]),
                            gelu_exact(p0.y + bc1s[cg * 8 + 1]));
            o.y = bf16x2_of(gelu_exact(p1.x + bc1s[cg * 8 + 2]),
                            gelu_exact(p1.y + bc1s[cg * 8 + 3]));
            o.z = bf16x2_of(gelu_exact(p2.x + bc1s[cg * 8 + 4]),
                            gelu_exact(p2.y + bc1s[cg * 8 + 5]));
            o.w = bf16x2_of(gelu_exact(p3.x + bc1s[cg * 8 + 6]),
                            gelu_exact(p3.y + bc1s[cg * 8 + 7]));
            *reinterpret_cast<uint4*>(&T1b[r * STR1 + cg * 8]) = o;
        }
    }
    __syncthreads();

    const int w    = tid >> 5;
    const int lane = tid & 31;
    const int fg   = lane >> 2;
    const int ft   = lane & 3;
    const int wm   = w & 3;
    const int wn   = w >> 2;
    const int m0   = wm * 32;
    const int nc0  = wn * 64;
    const int node = wm >> 1;

    float acc[2][8][4];

#pragma unroll
    for (int mt = 0; mt < 2; ++mt)
#pragma unroll
        for (int i = 0; i < 8; ++i)
#pragma unroll
            for (int k = 0; k < 4; ++k) acc[mt][i][k] = 0.f;

#pragma unroll
    for (int s = 0; s < 8; ++s) {
        const int k0 = 16 * s;
        unsigned A[2][4];
#pragma unroll
        for (int mt = 0; mt < 2; ++mt) {
            const int rb = (m0 + 16 * mt + fg) * STR1 + k0 + 2 * ft;
            A[mt][0] = *reinterpret_cast<const unsigned*>(&T1b[rb]);
            A[mt][1] = *reinterpret_cast<const unsigned*>(&T1b[rb + 8 * STR1]);
            A[mt][2] = *reinterpret_cast<const unsigned*>(&T1b[rb + 8]);
            A[mt][3] = *reinterpret_cast<const unsigned*>(&T1b[rb + 8 * STR1 + 8]);
        }
#pragma unroll
        for (int i = 0; i < 8; ++i) {
            const int bb = (nc0 + 8 * i + fg) * STR1 + k0 + 2 * ft;
            unsigned B0 = *reinterpret_cast<const unsigned*>(&Wc2b[bb]);
            unsigned B1 = *reinterpret_cast<const unsigned*>(&Wc2b[bb + 8]);
            mma16816(acc[0][i], A[0], B0, B1);
            mma16816(acc[1][i], A[1], B0, B1);
        }
    }

#pragma unroll
    for (int mt = 0; mt < 2; ++mt) {
#pragma unroll
        for (int i = 0; i < 8; ++i) {
            const int c0 = nc0 + 8 * i + 2 * ft;
            const int rlo = m0 + 16 * mt + fg;
            float2 bc = *reinterpret_cast<const float2*>(&bc2s[c0]);
            unsigned lo = bf16x2_of(gelu_exact(acc[mt][i][0] + bc.x),
                                    gelu_exact(acc[mt][i][1] + bc.y));
            unsigned hi = bf16x2_of(gelu_exact(acc[mt][i][2] + bc.x),
                                    gelu_exact(acc[mt][i][3] + bc.y));
            *reinterpret_cast<unsigned*>(&T2b[rlo * STR1 + c0]) = lo;
            *reinterpret_cast<unsigned*>(&T2b[(rlo + 8) * STR1 + c0]) = hi;
        }
    }
    __syncthreads();

#pragma unroll
    for (int mt = 0; mt < 2; ++mt)
#pragma unroll
        for (int i = 0; i < 8; ++i)
#pragma unroll
            for (int k = 0; k < 4; ++k) acc[mt][i][k] = 0.f;

#pragma unroll
    for (int p = 0; p < 2; ++p) {
#pragma unroll
        for (int s = 0; s < 8; ++s) {
            const int k0 = 16 * s;
            unsigned A[2][4];
#pragma unroll
            for (int mt = 0; mt < 2; ++mt) {
                const int rb = (m0 + 16 * mt + fg) * STR1 + k0 + 2 * ft;
                A[mt][0] = *reinterpret_cast<const unsigned*>(&T2b[rb]);
                A[mt][1] = *reinterpret_cast<const unsigned*>(&T2b[rb + 8 * STR1]);
                A[mt][2] = *reinterpret_cast<const unsigned*>(&T2b[rb + 8]);
                A[mt][3] = *reinterpret_cast<const unsigned*>(&T2b[rb + 8 * STR1 + 8]);
            }
            if (p == 0) {
                unsigned q0 = qb[node * 64 + 8 * s + ft];
                unsigned q1 = qb[node * 64 + 8 * s + ft + 4];
#pragma unroll
                for (int mt = 0; mt < 2; ++mt) {
                    A[mt][0] = mul_bf16x2(A[mt][0], q0);
                    A[mt][1] = mul_bf16x2(A[mt][1], q0);
                    A[mt][2] = mul_bf16x2(A[mt][2], q1);
                    A[mt][3] = mul_bf16x2(A[mt][3], q1);
                }
            }
#pragma unroll
            for (int i = 0; i < 8; ++i) {
                const int bb = (nc0 + 8 * i + fg) * STR3 + p * 128 + k0 + 2 * ft;
                unsigned B0 = *reinterpret_cast<const unsigned*>(&Ws1b[bb]);
                unsigned B1 = *reinterpret_cast<const unsigned*>(&Ws1b[bb + 8]);
                mma16816(acc[0][i], A[0], B0, B1);
                mma16816(acc[1][i], A[1], B0, B1);
            }
        }
    }

    float rs0[2] = {0.f, 0.f};
    float rs1[2] = {0.f, 0.f};
#pragma unroll
    for (int mt = 0; mt < 2; ++mt) {
#pragma unroll
        for (int i = 0; i < 8; ++i) {
            const int c0 = nc0 + 8 * i + 2 * ft;
            float2 b1 = *reinterpret_cast<const float2*>(&bs1s[c0]);
            float2 w2 = *reinterpret_cast<const float2*>(&Ws2s[c0]);
            rs0[mt] += gelu_exact(acc[mt][i][0] + b1.x) * w2.x
                     + gelu_exact(acc[mt][i][1] + b1.y) * w2.y;
            rs1[mt] += gelu_exact(acc[mt][i][2] + b1.x) * w2.x
                     + gelu_exact(acc[mt][i][3] + b1.y) * w2.y;
        }
    }
#pragma unroll
    for (int off = 1; off <= 2; off <<= 1) {
#pragma unroll
        for (int mt = 0; mt < 2; ++mt) {
            rs0[mt] += __shfl_xor_sync(0xffffffffu, rs0[mt], off);
            rs1[mt] += __shfl_xor_sync(0xffffffffu, rs1[mt], off);
        }
    }
    if (ft == 0) {
#pragma unroll
        for (int mt = 0; mt < 2; ++mt) {
            part[(m0 + 16 * mt + fg) * 2 + wn]     = rs0[mt];
            part[(m0 + 16 * mt + 8 + fg) * 2 + wn] = rs1[mt];
        }
    }
    __syncthreads();

    if (tid < 128) {
        const int r = tid;
        const int l = r >> 6, c = r & 63;
        const float* cfr = &cf_s[r * 10];
        float bias = 20.0f * cfr[0] + 4.0f * cfr[4] + 1.5f * cfr[5]
                   + 1.5f * cfr[1] - 1.5f * cfr[2] + 1.2f * cfr[6]
                   + 2.5f * cfr[7] + 1.6f * cfr[8] + 1.2f * cfr[9];
        float logit = part[2 * r] + part[2 * r + 1] + __ldg(&bs2[0]) + bias;
        float amv = am_s[r];
        bool valid = (amv > 0.f) || (c == 0 && misc[l] > 0.5f);
        out[(size_t)(n0 + l) * 64 + c] = valid ? logit : NEGV;
    }
}

// =========================================================================
extern "C" void kernel_launch(void* const* d_in, const int* in_sizes, int n_in,
                              void* d_out, int out_size) {
    const float* x    = (const float*)d_in[0];
    const float* cf   = (const float*)d_in[1];
    const int*   adj  = (const int*)  d_in[2];
    const float* am   = (const float*)d_in[3];
    const float* W1   = (const float*)d_in[4];
    const float* a1s  = (const float*)d_in[5];
    const float* a1d  = (const float*)d_in[6];
    const float* W2   = (const float*)d_in[7];
    const float* a2s  = (const float*)d_in[8];
    const float* a2d  = (const float*)d_in[9];
    const float* lnw  = (const float*)d_in[10];
    const float* lnb  = (const float*)d_in[11];
    const float* Wc1  = (const float*)d_in[12];
    const float* bc1  = (const float*)d_in[13];
    const float* Wc2  = (const float*)d_in[14];
    const float* bc2  = (const float*)d_in[15];
    const float* Wq   = (const float*)d_in[16];
    const float* bq   = (const float*)d_in[17];
    const float* Ws1  = (const float*)d_in[18];
    const float* bs1  = (const float*)d_in[19];
    const float* Ws2  = (const float*)d_in[20];
    const float* bs2  = (const float*)d_in[21];
    float* out = (float*)d_out;

    float *h1, *s1, *d1, *g1, *h2, *s2, *d2, *hn, *qp, *pt, *zp;
    unsigned *h1b, *h2b;
    cudaGetSymbolAddress((void**)&h1, g_h1);
    cudaGetSymbolAddress((void**)&s1, g_s1);
    cudaGetSymbolAddress((void**)&d1, g_d1);
    cudaGetSymbolAddress((void**)&g1, g_g1);
    cudaGetSymbolAddress((void**)&h2, g_h2);
    cudaGetSymbolAddress((void**)&s2, g_s2);
    cudaGetSymbolAddress((void**)&d2, g_d2);
    cudaGetSymbolAddress((void**)&hn, g_hn);
    cudaGetSymbolAddress((void**)&qp, g_q);
    cudaGetSymbolAddress((void**)&h1b, g_h1b);
    cudaGetSymbolAddress((void**)&h2b, g_h2b);
    cudaGetSymbolAddress((void**)&pt, g_part);
    cudaGetSymbolAddress((void**)&zp, g_zp);

    const int smem_k64  = (32 * 64  + 64  * 128) * 4;
    const int smem_k128 = (32 * 128 + 128 * 128) * 4;

    cudaFuncSetAttribute(gemm_attn_kernel,
                         cudaFuncAttributeMaxDynamicSharedMemorySize, smem_k128);
    cudaFuncSetAttribute(cand_kernel,
                         cudaFuncAttributeMaxDynamicSharedMemorySize, CAND_SMEM_BYTES);

    dim3 gat_grid(128, GAT_SPLITS);

    // layer 1
    gemm_attn_kernel<<<128, 256, smem_k64>>>(x, 64, W1, a1s, a1d, nullptr,
                                             h1, h1b, s1, d1);
    gat_part_kernel<<<gat_grid, 256>>>(h1b, s1, d1, adj, pt, zp);
    gat_reduce_kernel<<<128, 256>>>(pt, zp, nullptr, nullptr, nullptr, g1, 0);
    // layer 2 + residual + LN
    gemm_attn_kernel<<<128, 256, smem_k128>>>(g1, 128, W2, a2s, a2d, nullptr,
                                              h2, h2b, s2, d2);
    gat_part_kernel<<<gat_grid, 256>>>(h2b, s2, d2, adj, pt, zp);
    gat_reduce_kernel<<<128, 256>>>(pt, zp, g1, lnw, lnb, hn, 1);
    // q projection
    gemm_attn_kernel<<<128, 256, smem_k128>>>(hn, 128, Wq, nullptr, nullptr, bq,
                                              qp, nullptr, nullptr, nullptr);
    // fused candidate head
    cand_kernel<<<2048, 256, CAND_SMEM_BYTES>>>(cf, am, Wc1, bc1, Wc2, bc2,
                                                Ws1, bs1, Ws2, bs2, qp, out);
}

// round 9
// speedup vs baseline: 4.2010x; 1.2743x over previous
#include <cuda_runtime.h>
#include <cuda_bf16.h>
#include <math.h>

#define N_NODES 4096
#define H_DIM   128
#define NEGV    (-1000000000.0f)
#define GAT_SPLITS 16
#define J_PER_SPLIT (N_NODES / GAT_SPLITS)   // 256 -> 8 tiles of 32
#define WT_STR 132                           // padded fp32 col-stride (4-way max)

// ---------------- device scratch (no allocations allowed) ----------------
__device__ float g_h1[N_NODES * H_DIM];
__device__ float g_s1[N_NODES];
__device__ float g_d1[N_NODES];
__device__ float g_g1[N_NODES * H_DIM];
__device__ float g_h2[N_NODES * H_DIM];
__device__ float g_s2[N_NODES];
__device__ float g_d2[N_NODES];
__device__ float g_hn[N_NODES * H_DIM];
__device__ float g_q [N_NODES * H_DIM];
__device__ unsigned g_h1b[N_NODES * H_DIM / 2];
__device__ unsigned g_h2b[N_NODES * H_DIM / 2];
__device__ float g_part[GAT_SPLITS * N_NODES * H_DIM];  // split-K partials
__device__ float g_zp [GAT_SPLITS * N_NODES];

__device__ __forceinline__ float gelu_exact(float x) {
    return 0.5f * x * (1.0f + erff(x * 0.70710678118654752440f));
}

// ---- packed fp32x2 FMA ----
__device__ __forceinline__ unsigned long long ffma2(unsigned long long a,
                                                    unsigned long long b,
                                                    unsigned long long c) {
    unsigned long long d;
    asm("fma.rn.f32x2 %0, %1, %2, %3;" : "=l"(d) : "l"(a), "l"(b), "l"(c));
    return d;
}
__device__ __forceinline__ unsigned long long pack2(float x, float y) {
    unsigned long long d;
    asm("mov.b64 %0, {%1, %2};" : "=l"(d) : "f"(x), "f"(y));
    return d;
}
__device__ __forceinline__ float2 unpack2(unsigned long long v) {
    float2 r;
    asm("mov.b64 {%0, %1}, %2;" : "=f"(r.x), "=f"(r.y) : "l"(v));
    return r;
}

// ---- bf16 helpers ----
__device__ __forceinline__ unsigned bf16x2_of(float lo, float hi) {
    unsigned r;
    asm("cvt.rn.bf16x2.f32 %0, %1, %2;" : "=r"(r) : "f"(hi), "f"(lo));
    return r;
}
__device__ __forceinline__ unsigned mul_bf16x2(unsigned a, unsigned b) {
    unsigned r;
    asm("mul.bf16x2 %0, %1, %2;" : "=r"(r) : "r"(a), "r"(b));
    return r;
}
__device__ __forceinline__ void mma16816(float* c, const unsigned* a,
                                         unsigned b0, unsigned b1) {
    asm("mma.sync.aligned.m16n8k16.row.col.f32.bf16.bf16.f32 "
        "{%0,%1,%2,%3}, {%4,%5,%6,%7}, {%8,%9}, {%0,%1,%2,%3};"
        : "+f"(c[0]), "+f"(c[1]), "+f"(c[2]), "+f"(c[3])
        : "r"(a[0]), "r"(a[1]), "r"(a[2]), "r"(a[3]), "r"(b0), "r"(b1));
}
__device__ __forceinline__ void ldsm_x4_t(unsigned& r0, unsigned& r1,
                                          unsigned& r2, unsigned& r3,
                                          unsigned addr) {
    asm volatile("ldmatrix.sync.aligned.m8n8.x4.trans.shared.b16 "
                 "{%0,%1,%2,%3}, [%4];"
                 : "=r"(r0), "=r"(r1), "=r"(r2), "=r"(r3) : "r"(addr));
}
__device__ __forceinline__ unsigned smem_u32(const void* p) {
    return (unsigned)__cvta_generic_to_shared(p);
}

// =========================================================================
// GEMM: out[4096][128] = in[4096][K] @ W[128][K]^T (+bias) (+bf16 copy)
// Wt stored with padded stride WT_STR=132: STS conflicts 32-way -> 4-way,
// compute-loop float4 reads stay 16B aligned (528B row stride).
// =========================================================================
__global__ void gemm_attn_kernel(const float* __restrict__ in, int K,
                                 const float* __restrict__ W,
                                 const float* __restrict__ a_s,
                                 const float* __restrict__ a_d,
                                 const float* __restrict__ bias,
                                 float* __restrict__ out,
                                 unsigned* __restrict__ out_bf,
                                 float* __restrict__ s_out,
                                 float* __restrict__ d_out) {
    extern __shared__ float sm[];
    float* in_s = sm;            // 32*K
    float* Wt   = sm + 32 * K;   // K rows of WT_STR (128 cols used)
    const int tid = threadIdx.x;
    const int i0  = blockIdx.x * 32;

    for (int idx = tid; idx < 32 * K; idx += 256)
        in_s[idx] = in[(size_t)(i0 + idx / K) * K + (idx % K)];
    for (int idx = tid; idx < 128 * K; idx += 256) {
        int c = idx / K, k = idx - c * K;
        Wt[k * WT_STR + c] = W[idx];
    }
    __syncthreads();

    const int rg = tid >> 5;
    const int lane = tid & 31;
    unsigned long long acc2[4][2];
#pragma unroll
    for (int r = 0; r < 4; ++r) { acc2[r][0] = 0ull; acc2[r][1] = 0ull; }

    for (int k = 0; k < K; ++k) {
        longlong2 B = *reinterpret_cast<const longlong2*>(&Wt[k * WT_STR + lane * 4]);
#pragma unroll
        for (int rr = 0; rr < 4; ++rr) {
            float a = in_s[(rg * 4 + rr) * K + k];
            unsigned long long aa = pack2(a, a);
            acc2[rr][0] = ffma2(aa, (unsigned long long)B.x, acc2[rr][0]);
            acc2[rr][1] = ffma2(aa, (unsigned long long)B.y, acc2[rr][1]);
        }
    }

    float acc[4][4];
#pragma unroll
    for (int rr = 0; rr < 4; ++rr) {
        float2 p0 = unpack2(acc2[rr][0]);
        float2 p1 = unpack2(acc2[rr][1]);
        acc[rr][0] = p0.x; acc[rr][1] = p0.y; acc[rr][2] = p1.x; acc[rr][3] = p1.y;
    }

#pragma unroll
    for (int rr = 0; rr < 4; ++rr) {
        int row = i0 + rg * 4 + rr;
        float4 v;
        v.x = acc[rr][0]; v.y = acc[rr][1]; v.z = acc[rr][2]; v.w = acc[rr][3];
        if (bias) {
            v.x += bias[lane * 4 + 0];
            v.y += bias[lane * 4 + 1];
            v.z += bias[lane * 4 + 2];
            v.w += bias[lane * 4 + 3];
        }
        *reinterpret_cast<float4*>(&out[(size_t)row * 128 + lane * 4]) = v;
        if (out_bf) {
            out_bf[(size_t)row * 64 + lane * 2 + 0] = bf16x2_of(v.x, v.y);
            out_bf[(size_t)row * 64 + lane * 2 + 1] = bf16x2_of(v.z, v.w);
        }
    }

    if (s_out) {
#pragma unroll
        for (int rr = 0; rr < 4; ++rr) {
            float sp = 0.f, dp = 0.f;
#pragma unroll
            for (int cc = 0; cc < 4; ++cc) {
                int c = lane * 4 + cc;
                sp += acc[rr][cc] * __ldg(&a_s[c]);
                dp += acc[rr][cc] * __ldg(&a_d[c]);
            }
#pragma unroll
            for (int off = 16; off; off >>= 1) {
                sp += __shfl_xor_sync(0xffffffffu, sp, off);
                dp += __shfl_xor_sync(0xffffffffu, dp, off);
            }
            if (lane == 0) {
                s_out[i0 + rg * 4 + rr] = sp;
                d_out[i0 + rg * 4 + rr] = dp;
            }
        }
    }
}

// =========================================================================
// GAT split-K partial (16 splits of 256 j => 8 tiles per CTA)
// =========================================================================
#define GB_H0 0
#define GB_H1 8704
#define GB_W0 17408
#define GB_W1 19968
#define GB_TOTAL 22528

__global__ void __launch_bounds__(256, 3)
gat_part_kernel(const unsigned* __restrict__ hb,
                const float* __restrict__ s,
                const float* __restrict__ d,
                const int*   __restrict__ adj,
                float* __restrict__ part,          // [S][4096][128]
                float* __restrict__ zp) {          // [S][4096]
    __shared__ __align__(16) char smraw[GB_TOTAL];
    __nv_bfloat16* h_sb[2] = { (__nv_bfloat16*)(smraw + GB_H0),
                               (__nv_bfloat16*)(smraw + GB_H1) };
    __nv_bfloat16* w_sb[2] = { (__nv_bfloat16*)(smraw + GB_W0),
                               (__nv_bfloat16*)(smraw + GB_W1) };

    const int tid = threadIdx.x;
    const int i0  = blockIdx.x * 32;
    const int sz  = blockIdx.y;
    const int jb  = sz * J_PER_SPLIT;

    const int lane = tid & 31;
    const int w    = tid >> 5;
    const int rg   = w;
    const int wi   = tid >> 3;
    const int wj   = (tid & 7) * 4;
    const float si = s[i0 + wi];

    const int fg = lane >> 2, ft = lane & 3;
    const int m0 = (w & 1) * 16;
    const int n0 = (w >> 1) * 32;
    const int lm_ti = lane >> 3, lm_r = lane & 7;
    const int lm_off = ((lm_ti & 1) * 8 + lm_r) * 136 + (lm_ti >> 1) * 8;
    const unsigned hb_u32[2] = { smem_u32(h_sb[0]), smem_u32(h_sb[1]) };
    const int aw = (m0 + fg) * 40 + 2 * ft;

    float zacc = 0.f;
    float acc[4][4];
#pragma unroll
    for (int i = 0; i < 4; ++i)
#pragma unroll
        for (int k = 0; k < 4; ++k) acc[i][k] = 0.f;

    int4 av; float4 dv; uint2 hv0, hv1, hv2, hv3;

#define GAT_LOAD(J0)                                                          \
    do {                                                                      \
        av = *reinterpret_cast<const int4*>(                                  \
            &adj[(size_t)(i0 + wi) * N_NODES + (J0) + wj]);                   \
        dv = *reinterpret_cast<const float4*>(&d[(J0) + wj]);                 \
        const uint2* h2p = reinterpret_cast<const uint2*>(hb);                \
        hv0 = h2p[(size_t)((J0) + rg +  0) * 32 + lane];                      \
        hv1 = h2p[(size_t)((J0) + rg +  8) * 32 + lane];                      \
        hv2 = h2p[(size_t)((J0) + rg + 16) * 32 + lane];                      \
        hv3 = h2p[(size_t)((J0) + rg + 24) * 32 + lane];                      \
    } while (0)

#define GAT_STORE(BUF)                                                        \
    do {                                                                      \
        float w0 = 0.f, w1 = 0.f, w2 = 0.f, w3 = 0.f;                         \
        if (av.x > 0) { float e = si + dv.x; e = (e > 0.f) ? e : 0.2f * e; w0 = __expf(e); } \
        if (av.y > 0) { float e = si + dv.y; e = (e > 0.f) ? e : 0.2f * e; w1 = __expf(e); } \
        if (av.z > 0) { float e = si + dv.z; e = (e > 0.f) ? e : 0.2f * e; w2 = __expf(e); } \
        if (av.w > 0) { float e = si + dv.w; e = (e > 0.f) ? e : 0.2f * e; w3 = __expf(e); } \
        zacc += (w0 + w1) + (w2 + w3);                                        \
        uint2 wp; wp.x = bf16x2_of(w0, w1); wp.y = bf16x2_of(w2, w3);         \
        *reinterpret_cast<uint2*>(&w_sb[BUF][wi * 40 + wj]) = wp;             \
        *reinterpret_cast<uint2*>(&h_sb[BUF][(rg +  0) * 136 + lane * 4]) = hv0; \
        *reinterpret_cast<uint2*>(&h_sb[BUF][(rg +  8) * 136 + lane * 4]) = hv1; \
        *reinterpret_cast<uint2*>(&h_sb[BUF][(rg + 16) * 136 + lane * 4]) = hv2; \
        *reinterpret_cast<uint2*>(&h_sb[BUF][(rg + 24) * 136 + lane * 4]) = hv3; \
    } while (0)

    GAT_LOAD(jb);
    GAT_STORE(0);
    __syncthreads();

    int buf = 0;
    const int NT = J_PER_SPLIT / 32;    // 8
    for (int t = 0; t < NT; ++t) {
        const int nxt = jb + (t + 1) * 32;
        if (t + 1 < NT) GAT_LOAD(nxt);

        const __nv_bfloat16* wb = w_sb[buf];
        const unsigned hbase = hb_u32[buf] + lm_off * 2;
#pragma unroll
        for (int sstep = 0; sstep < 2; ++sstep) {
            const int k0 = 16 * sstep;
            unsigned A[4];
            A[0] = *reinterpret_cast<const unsigned*>(&wb[aw + k0]);
            A[1] = *reinterpret_cast<const unsigned*>(&wb[aw + 320 + k0]);
            A[2] = *reinterpret_cast<const unsigned*>(&wb[aw + k0 + 8]);
            A[3] = *reinterpret_cast<const unsigned*>(&wb[aw + 320 + k0 + 8]);
#pragma unroll
            for (int p = 0; p < 2; ++p) {
                unsigned r0, r1, r2, r3;
                ldsm_x4_t(r0, r1, r2, r3,
                          hbase + (k0 * 136 + n0 + 16 * p) * 2);
                mma16816(acc[2 * p + 0], A, r0, r1);
                mma16816(acc[2 * p + 1], A, r2, r3);
            }
        }

        if (t + 1 < NT) GAT_STORE(buf ^ 1);
        __syncthreads();
        buf ^= 1;
    }
#undef GAT_LOAD
#undef GAT_STORE

    zacc += __shfl_xor_sync(0xffffffffu, zacc, 4);
    zacc += __shfl_xor_sync(0xffffffffu, zacc, 2);
    zacc += __shfl_xor_sync(0xffffffffu, zacc, 1);
    if ((tid & 7) == 0) zp[(size_t)sz * N_NODES + i0 + wi] = zacc;

    float* pb = &part[((size_t)sz * N_NODES + i0) * 128];
#pragma unroll
    for (int i = 0; i < 4; ++i) {
        const int col = n0 + 8 * i + 2 * ft;
        float2 lo; lo.x = acc[i][0]; lo.y = acc[i][1];
        float2 hi; hi.x = acc[i][2]; hi.y = acc[i][3];
        *reinterpret_cast<float2*>(&pb[(m0 + fg) * 128 + col])     = lo;
        *reinterpret_cast<float2*>(&pb[(m0 + 8 + fg) * 128 + col]) = hi;
    }
}

// =========================================================================
// GAT reduce: sum partials + Z, then relu(acc/Z) (+res, LayerNorm)
// =========================================================================
__global__ void gat_reduce_kernel(const float* __restrict__ part,
                                  const float* __restrict__ zp,
                                  const float* __restrict__ res,
                                  const float* __restrict__ lnw,
                                  const float* __restrict__ lnb,
                                  float* __restrict__ out,
                                  int do_ln) {
    __shared__ float z_s[32];
    const int tid = threadIdx.x;
    const int i0  = blockIdx.x * 32;
    const int rg  = tid >> 5;
    const int lane = tid & 31;

    if (tid < 32) {
        float z = 0.f;
#pragma unroll
        for (int s = 0; s < GAT_SPLITS; ++s)
            z += zp[(size_t)s * N_NODES + i0 + tid];
        z_s[tid] = z;
    }
    __syncthreads();

#pragma unroll
    for (int rr = 0; rr < 4; ++rr) {
        const int lrow = rg * 4 + rr;
        const int row  = i0 + lrow;
        float4 a = make_float4(0.f, 0.f, 0.f, 0.f);
#pragma unroll
        for (int s = 0; s < GAT_SPLITS; ++s) {
            float4 p = *reinterpret_cast<const float4*>(
                &part[((size_t)s * N_NODES + row) * 128 + lane * 4]);
            a.x += p.x; a.y += p.y; a.z += p.z; a.w += p.w;
        }
        const float z = z_s[lrow];
        const float zinv = (z > 0.f) ? (1.0f / z) : 0.f;
        float v[4] = {a.x, a.y, a.z, a.w};
#pragma unroll
        for (int cc = 0; cc < 4; ++cc) {
            float t = fmaxf(v[cc] * zinv, 0.f);
            if (res) t += res[(size_t)row * 128 + lane * 4 + cc];
            v[cc] = t;
        }
        if (do_ln) {
            float sum = v[0] + v[1] + v[2] + v[3];
            float sq  = v[0]*v[0] + v[1]*v[1] + v[2]*v[2] + v[3]*v[3];
#pragma unroll
            for (int off = 16; off; off >>= 1) {
                sum += __shfl_xor_sync(0xffffffffu, sum, off);
                sq  += __shfl_xor_sync(0xffffffffu, sq,  off);
            }
            const float mu  = sum * (1.0f / 128.0f);
            const float var = sq  * (1.0f / 128.0f) - mu * mu;
            const float rs  = rsqrtf(var + 1e-5f);
#pragma unroll
            for (int cc = 0; cc < 4; ++cc) {
                int c = lane * 4 + cc;
                v[cc] = (v[cc] - mu) * rs * __ldg(&lnw[c]) + __ldg(&lnb[c]);
            }
        }
        float4 o; o.x = v[0]; o.y = v[1]; o.z = v[2]; o.w = v[3];
        *reinterpret_cast<float4*>(&out[(size_t)row * 128 + lane * 4]) = o;
    }
}

// =========================================================================
// Candidate head: PERSISTENT bf16-MMA kernel. Grid = 148; each block loads
// the weights into smem ONCE, then loops over node-pairs.
// =========================================================================
#define STR1 136
#define STR3 264

#define OB_WC2  0
#define OB_WS1  34816
#define OB_T1   102400
#define OB_T2   137216
#define OB_WC1T 172032
#define OB_CF   177152
#define OB_QB   182272
#define OB_BC1  182784
#define OB_BC2  183296
#define OB_BS1  183808
#define OB_WS2  184320
#define OB_AM   184832
#define OB_PART 185344
#define OB_MISC 186368
#define CAND_SMEM_BYTES 186400
#define N_PAIRS 2048

__global__ void __launch_bounds__(256, 1)
cand_kernel(const float* __restrict__ cf,
            const float* __restrict__ am,
            const float* __restrict__ Wc1, const float* __restrict__ bc1,
            const float* __restrict__ Wc2, const float* __restrict__ bc2,
            const float* __restrict__ Ws1, const float* __restrict__ bs1,
            const float* __restrict__ Ws2, const float* __restrict__ bs2,
            const float* __restrict__ q,
            float* __restrict__ out) {
    extern __shared__ char smc[];
    __nv_bfloat16* Wc2b = (__nv_bfloat16*)(smc + OB_WC2);
    __nv_bfloat16* Ws1b = (__nv_bfloat16*)(smc + OB_WS1);
    __nv_bfloat16* T1b  = (__nv_bfloat16*)(smc + OB_T1);
    __nv_bfloat16* T2b  = (__nv_bfloat16*)(smc + OB_T2);
    float* Wc1t = (float*)(smc + OB_WC1T);
    float* cf_s = (float*)(smc + OB_CF);
    unsigned* qb = (unsigned*)(smc + OB_QB);
    float* bc1s = (float*)(smc + OB_BC1);
    float* bc2s = (float*)(smc + OB_BC2);
    float* bs1s = (float*)(smc + OB_BS1);
    float* Ws2s = (float*)(smc + OB_WS2);
    float* am_s = (float*)(smc + OB_AM);
    float* part = (float*)(smc + OB_PART);
    float* misc = (float*)(smc + OB_MISC);

    const int tid = threadIdx.x;

    // -------- weights: loaded ONCE per block --------
    for (int i2 = tid; i2 < 8192; i2 += 256) {
        int n = i2 >> 6, kp = i2 & 63;
        float2 v = *reinterpret_cast<const float2*>(&Wc2[n * 128 + 2 * kp]);
        *reinterpret_cast<unsigned*>(&Wc2b[n * STR1 + 2 * kp]) = bf16x2_of(v.x, v.y);
    }
    for (int i2 = tid; i2 < 16384; i2 += 256) {
        int n = i2 >> 7, kp = i2 & 127;
        float2 v = *reinterpret_cast<const float2*>(&Ws1[n * 256 + 2 * kp]);
        *reinterpret_cast<unsigned*>(&Ws1b[n * STR3 + 2 * kp]) = bf16x2_of(v.x, v.y);
    }
    for (int idx = tid; idx < 1280; idx += 256) {
        int c = idx / 10, j = idx - c * 10;
        Wc1t[j * 128 + c] = Wc1[idx];
    }
    if (tid < 128) {
        bc1s[tid] = bc1[tid];
        bc2s[tid] = bc2[tid];
        bs1s[tid] = bs1[tid];
        Ws2s[tid] = Ws2[tid];
    }
    const float bs2v = __ldg(&bs2[0]);

    const int w    = tid >> 5;
    const int lane = tid & 31;
    const int fg   = lane >> 2;
    const int ft   = lane & 3;
    const int wm   = w & 3;
    const int wn   = w >> 2;
    const int m0   = wm * 32;
    const int nc0  = wn * 64;
    const int node = wm >> 1;
    const int rg1  = tid >> 4;      // stage-1 mapping
    const int cg1  = tid & 15;

    // -------- persistent loop over node-pairs --------
    for (int pr = blockIdx.x; pr < N_PAIRS; pr += gridDim.x) {
        const int n0  = pr * 2;
        const int base_row = n0 * 64;

        __syncthreads();   // prev iteration's consumers done before overwrite

        for (int idx = tid; idx < 1280; idx += 256)
            cf_s[idx] = cf[(size_t)base_row * 10 + idx];
        if (tid < 128) {
            int nd = tid >> 6, kp = tid & 63;
            float2 qq = *reinterpret_cast<const float2*>(
                &q[(size_t)(n0 + nd) * 128 + 2 * kp]);
            qb[tid] = bf16x2_of(qq.x, qq.y);
            am_s[tid] = am[base_row + tid];
        }
        __syncthreads();

        if (tid < 2) {
            float ssum = 0.f;
            for (int c = 0; c < 64; ++c) ssum += am_s[tid * 64 + c];
            misc[tid] = (ssum <= 0.f) ? 1.f : 0.f;
        }

        // ---- stage 1 (fp32, K=10) -> T1b bf16 ----
        {
            unsigned long long a2[8][4];
#pragma unroll
            for (int r = 0; r < 8; ++r)
#pragma unroll
                for (int c = 0; c < 4; ++c) a2[r][c] = 0ull;
#pragma unroll
            for (int j = 0; j < 10; ++j) {
                longlong2 B0 = *reinterpret_cast<const longlong2*>(&Wc1t[j * 128 + cg1 * 8]);
                longlong2 B1 = *reinterpret_cast<const longlong2*>(&Wc1t[j * 128 + cg1 * 8 + 4]);
#pragma unroll
                for (int rr = 0; rr < 8; ++rr) {
                    float a = cf_s[(rg1 * 8 + rr) * 10 + j];
                    unsigned long long aa = pack2(a, a);
                    a2[rr][0] = ffma2(aa, (unsigned long long)B0.x, a2[rr][0]);
                    a2[rr][1] = ffma2(aa, (unsigned long long)B0.y, a2[rr][1]);
                    a2[rr][2] = ffma2(aa, (unsigned long long)B1.x, a2[rr][2]);
                    a2[rr][3] = ffma2(aa, (unsigned long long)B1.y, a2[rr][3]);
                }
            }
#pragma unroll
            for (int rr = 0; rr < 8; ++rr) {
                int r = rg1 * 8 + rr;
                float2 p0 = unpack2(a2[rr][0]);
                float2 p1 = unpack2(a2[rr][1]);
                float2 p2 = unpack2(a2[rr][2]);
                float2 p3 = unpack2(a2[rr][3]);
                uint4 o;
                o.x = bf16x2_of(gelu_exact(p0.x + bc1s[cg1 * 8 + 0]),
                                gelu_exact(p0.y + bc1s[cg1 * 8 + 1]));
                o.y = bf16x2_of(gelu_exact(p1.x + bc1s[cg1 * 8 + 2]),
                                gelu_exact(p1.y + bc1s[cg1 * 8 + 3]));
                o.z = bf16x2_of(gelu_exact(p2.x + bc1s[cg1 * 8 + 4]),
                                gelu_exact(p2.y + bc1s[cg1 * 8 + 5]));
                o.w = bf16x2_of(gelu_exact(p3.x + bc1s[cg1 * 8 + 6]),
                                gelu_exact(p3.y + bc1s[cg1 * 8 + 7]));
                *reinterpret_cast<uint4*>(&T1b[r * STR1 + cg1 * 8]) = o;
            }
        }
        __syncthreads();

        float acc[2][8][4];

        // ---- stage 2: T2 = gelu(T1 @ Wc2^T + bc2) ----
#pragma unroll
        for (int mt = 0; mt < 2; ++mt)
#pragma unroll
            for (int i = 0; i < 8; ++i)
#pragma unroll
                for (int k = 0; k < 4; ++k) acc[mt][i][k] = 0.f;

#pragma unroll
        for (int s = 0; s < 8; ++s) {
            const int k0 = 16 * s;
            unsigned A[2][4];
#pragma unroll
            for (int mt = 0; mt < 2; ++mt) {
                const int rb = (m0 + 16 * mt + fg) * STR1 + k0 + 2 * ft;
                A[mt][0] = *reinterpret_cast<const unsigned*>(&T1b[rb]);
                A[mt][1] = *reinterpret_cast<const unsigned*>(&T1b[rb + 8 * STR1]);
                A[mt][2] = *reinterpret_cast<const unsigned*>(&T1b[rb + 8]);
                A[mt][3] = *reinterpret_cast<const unsigned*>(&T1b[rb + 8 * STR1 + 8]);
            }
#pragma unroll
            for (int i = 0; i < 8; ++i) {
                const int bb = (nc0 + 8 * i + fg) * STR1 + k0 + 2 * ft;
                unsigned B0 = *reinterpret_cast<const unsigned*>(&Wc2b[bb]);
                unsigned B1 = *reinterpret_cast<const unsigned*>(&Wc2b[bb + 8]);
                mma16816(acc[0][i], A[0], B0, B1);
                mma16816(acc[1][i], A[1], B0, B1);
            }
        }

#pragma unroll
        for (int mt = 0; mt < 2; ++mt) {
#pragma unroll
            for (int i = 0; i < 8; ++i) {
                const int c0 = nc0 + 8 * i + 2 * ft;
                const int rlo = m0 + 16 * mt + fg;
                float2 bc = *reinterpret_cast<const float2*>(&bc2s[c0]);
                unsigned lo = bf16x2_of(gelu_exact(acc[mt][i][0] + bc.x),
                                        gelu_exact(acc[mt][i][1] + bc.y));
                unsigned hi = bf16x2_of(gelu_exact(acc[mt][i][2] + bc.x),
                                        gelu_exact(acc[mt][i][3] + bc.y));
                *reinterpret_cast<unsigned*>(&T2b[rlo * STR1 + c0]) = lo;
                *reinterpret_cast<unsigned*>(&T2b[(rlo + 8) * STR1 + c0]) = hi;
            }
        }
        __syncthreads();

        // ---- stage 3: [q*T2 | T2] @ Ws1^T ----
#pragma unroll
        for (int mt = 0; mt < 2; ++mt)
#pragma unroll
            for (int i = 0; i < 8; ++i)
#pragma unroll
                for (int k = 0; k < 4; ++k) acc[mt][i][k] = 0.f;

#pragma unroll
        for (int p = 0; p < 2; ++p) {
#pragma unroll
            for (int s = 0; s < 8; ++s) {
                const int k0 = 16 * s;
                unsigned A[2][4];
#pragma unroll
                for (int mt = 0; mt < 2; ++mt) {
                    const int rb = (m0 + 16 * mt + fg) * STR1 + k0 + 2 * ft;
                    A[mt][0] = *reinterpret_cast<const unsigned*>(&T2b[rb]);
                    A[mt][1] = *reinterpret_cast<const unsigned*>(&T2b[rb + 8 * STR1]);
                    A[mt][2] = *reinterpret_cast<const unsigned*>(&T2b[rb + 8]);
                    A[mt][3] = *reinterpret_cast<const unsigned*>(&T2b[rb + 8 * STR1 + 8]);
                }
                if (p == 0) {
                    unsigned q0 = qb[node * 64 + 8 * s + ft];
                    unsigned q1 = qb[node * 64 + 8 * s + ft + 4];
#pragma unroll
                    for (int mt = 0; mt < 2; ++mt) {
                        A[mt][0] = mul_bf16x2(A[mt][0], q0);
                        A[mt][1] = mul_bf16x2(A[mt][1], q0);
                        A[mt][2] = mul_bf16x2(A[mt][2], q1);
                        A[mt][3] = mul_bf16x2(A[mt][3], q1);
                    }
                }
#pragma unroll
                for (int i = 0; i < 8; ++i) {
                    const int bb = (nc0 + 8 * i + fg) * STR3 + p * 128 + k0 + 2 * ft;
                    unsigned B0 = *reinterpret_cast<const unsigned*>(&Ws1b[bb]);
                    unsigned B1 = *reinterpret_cast<const unsigned*>(&Ws1b[bb + 8]);
                    mma16816(acc[0][i], A[0], B0, B1);
                    mma16816(acc[1][i], A[1], B0, B1);
                }
            }
        }

        // ---- epilogue ----
        float rs0[2] = {0.f, 0.f};
        float rs1[2] = {0.f, 0.f};
#pragma unroll
        for (int mt = 0; mt < 2; ++mt) {
#pragma unroll
            for (int i = 0; i < 8; ++i) {
                const int c0 = nc0 + 8 * i + 2 * ft;
                float2 b1 = *reinterpret_cast<const float2*>(&bs1s[c0]);
                float2 w2 = *reinterpret_cast<const float2*>(&Ws2s[c0]);
                rs0[mt] += gelu_exact(acc[mt][i][0] + b1.x) * w2.x
                         + gelu_exact(acc[mt][i][1] + b1.y) * w2.y;
                rs1[mt] += gelu_exact(acc[mt][i][2] + b1.x) * w2.x
                         + gelu_exact(acc[mt][i][3] + b1.y) * w2.y;
            }
        }
#pragma unroll
        for (int off = 1; off <= 2; off <<= 1) {
#pragma unroll
            for (int mt = 0; mt < 2; ++mt) {
                rs0[mt] += __shfl_xor_sync(0xffffffffu, rs0[mt], off);
                rs1[mt] += __shfl_xor_sync(0xffffffffu, rs1[mt], off);
            }
        }
        if (ft == 0) {
#pragma unroll
            for (int mt = 0; mt < 2; ++mt) {
                part[(m0 + 16 * mt + fg) * 2 + wn]     = rs0[mt];
                part[(m0 + 16 * mt + 8 + fg) * 2 + wn] = rs1[mt];
            }
        }
        __syncthreads();

        if (tid < 128) {
            const int r = tid;
            const int l = r >> 6, c = r & 63;
            const float* cfr = &cf_s[r * 10];
            float bias = 20.0f * cfr[0] + 4.0f * cfr[4] + 1.5f * cfr[5]
                       + 1.5f * cfr[1] - 1.5f * cfr[2] + 1.2f * cfr[6]
                       + 2.5f * cfr[7] + 1.6f * cfr[8] + 1.2f * cfr[9];
            float logit = part[2 * r] + part[2 * r + 1] + bs2v + bias;
            float amv = am_s[r];
            bool valid = (amv > 0.f) || (c == 0 && misc[l] > 0.5f);
            out[(size_t)(n0 + l) * 64 + c] = valid ? logit : NEGV;
        }
    }
}

// =========================================================================
extern "C" void kernel_launch(void* const* d_in, const int* in_sizes, int n_in,
                              void* d_out, int out_size) {
    const float* x    = (const float*)d_in[0];
    const float* cf   = (const float*)d_in[1];
    const int*   adj  = (const int*)  d_in[2];
    const float* am   = (const float*)d_in[3];
    const float* W1   = (const float*)d_in[4];
    const float* a1s  = (const float*)d_in[5];
    const float* a1d  = (const float*)d_in[6];
    const float* W2   = (const float*)d_in[7];
    const float* a2s  = (const float*)d_in[8];
    const float* a2d  = (const float*)d_in[9];
    const float* lnw  = (const float*)d_in[10];
    const float* lnb  = (const float*)d_in[11];
    const float* Wc1  = (const float*)d_in[12];
    const float* bc1  = (const float*)d_in[13];
    const float* Wc2  = (const float*)d_in[14];
    const float* bc2  = (const float*)d_in[15];
    const float* Wq   = (const float*)d_in[16];
    const float* bq   = (const float*)d_in[17];
    const float* Ws1  = (const float*)d_in[18];
    const float* bs1  = (const float*)d_in[19];
    const float* Ws2  = (const float*)d_in[20];
    const float* bs2  = (const float*)d_in[21];
    float* out = (float*)d_out;

    float *h1, *s1, *d1, *g1, *h2, *s2, *d2, *hn, *qp, *pt, *zp;
    unsigned *h1b, *h2b;
    cudaGetSymbolAddress((void**)&h1, g_h1);
    cudaGetSymbolAddress((void**)&s1, g_s1);
    cudaGetSymbolAddress((void**)&d1, g_d1);
    cudaGetSymbolAddress((void**)&g1, g_g1);
    cudaGetSymbolAddress((void**)&h2, g_h2);
    cudaGetSymbolAddress((void**)&s2, g_s2);
    cudaGetSymbolAddress((void**)&d2, g_d2);
    cudaGetSymbolAddress((void**)&hn, g_hn);
    cudaGetSymbolAddress((void**)&qp, g_q);
    cudaGetSymbolAddress((void**)&h1b, g_h1b);
    cudaGetSymbolAddress((void**)&h2b, g_h2b);
    cudaGetSymbolAddress((void**)&pt, g_part);
    cudaGetSymbolAddress((void**)&zp, g_zp);

    const int smem_k64  = (32 * 64  + WT_STR * 64)  * 4;   // 41984
    const int smem_k128 = (32 * 128 + WT_STR * 128) * 4;   // 83968

    cudaFuncSetAttribute(gemm_attn_kernel,
                         cudaFuncAttributeMaxDynamicSharedMemorySize, smem_k128);
    cudaFuncSetAttribute(cand_kernel,
                         cudaFuncAttributeMaxDynamicSharedMemorySize, CAND_SMEM_BYTES);

    dim3 gat_grid(128, GAT_SPLITS);

    // layer 1
    gemm_attn_kernel<<<128, 256, smem_k64>>>(x, 64, W1, a1s, a1d, nullptr,
                                             h1, h1b, s1, d1);
    gat_part_kernel<<<gat_grid, 256>>>(h1b, s1, d1, adj, pt, zp);
    gat_reduce_kernel<<<128, 256>>>(pt, zp, nullptr, nullptr, nullptr, g1, 0);
    // layer 2 + residual + LN
    gemm_attn_kernel<<<128, 256, smem_k128>>>(g1, 128, W2, a2s, a2d, nullptr,
                                              h2, h2b, s2, d2);
    gat_part_kernel<<<gat_grid, 256>>>(h2b, s2, d2, adj, pt, zp);
    gat_reduce_kernel<<<128, 256>>>(pt, zp, g1, lnw, lnb, hn, 1);
    // q projection
    gemm_attn_kernel<<<128, 256, smem_k128>>>(hn, 128, Wq, nullptr, nullptr, bq,
                                              qp, nullptr, nullptr, nullptr);
    // persistent fused candidate head
    cand_kernel<<<148, 256, CAND_SMEM_BYTES>>>(cf, am, Wc1, bc1, Wc2, bc2,
                                               Ws1, bs1, Ws2, bs2, qp, out);
}

// round 10
// speedup vs baseline: 5.2472x; 1.2490x over previous
#include <cuda_runtime.h>
#include <cuda_bf16.h>
#include <math.h>

#define N_NODES 4096
#define H_DIM   128
#define NEGV    (-1000000000.0f)
#define GAT_SPLITS 16
#define J_PER_SPLIT (N_NODES / GAT_SPLITS)   // 256 -> 8 tiles of 32
#define WT_STR 132

// ---------------- device scratch (no allocations allowed) ----------------
__device__ float g_s1[N_NODES];
__device__ float g_d1[N_NODES];
__device__ float g_g1[N_NODES * H_DIM];
__device__ float g_s2[N_NODES];
__device__ float g_d2[N_NODES];
__device__ float g_hn[N_NODES * H_DIM];
__device__ unsigned g_h1b[N_NODES * H_DIM / 2];   // bf16x2 packed h1
__device__ unsigned g_h2b[N_NODES * H_DIM / 2];   // bf16x2 packed h2
__device__ unsigned g_qb [N_NODES * H_DIM / 2];   // bf16x2 packed q
__device__ float g_part[GAT_SPLITS * N_NODES * H_DIM];
__device__ float g_zp [GAT_SPLITS * N_NODES];

// ---- fast gelu: tanh-approx via MUFU.TANH (sm_75+) ----
__device__ __forceinline__ float tanh_fast(float y) {
    float r;
    asm("tanh.approx.f32 %0, %1;" : "=f"(r) : "f"(y));
    return r;
}
__device__ __forceinline__ float gelu_fast(float x) {
    float x2 = x * x;
    float inner = x * fmaf(0.0356774081f, x2, 0.79788456080f);
    float hx = 0.5f * x;
    return fmaf(hx, tanh_fast(inner), hx);
}

// ---- packed fp32x2 FMA ----
__device__ __forceinline__ unsigned long long ffma2(unsigned long long a,
                                                    unsigned long long b,
                                                    unsigned long long c) {
    unsigned long long d;
    asm("fma.rn.f32x2 %0, %1, %2, %3;" : "=l"(d) : "l"(a), "l"(b), "l"(c));
    return d;
}
__device__ __forceinline__ unsigned long long pack2(float x, float y) {
    unsigned long long d;
    asm("mov.b64 %0, {%1, %2};" : "=l"(d) : "f"(x), "f"(y));
    return d;
}
__device__ __forceinline__ float2 unpack2(unsigned long long v) {
    float2 r;
    asm("mov.b64 {%0, %1}, %2;" : "=f"(r.x), "=f"(r.y) : "l"(v));
    return r;
}

// ---- bf16 helpers ----
__device__ __forceinline__ unsigned bf16x2_of(float lo, float hi) {
    unsigned r;
    asm("cvt.rn.bf16x2.f32 %0, %1, %2;" : "=r"(r) : "f"(hi), "f"(lo));
    return r;
}
__device__ __forceinline__ unsigned mul_bf16x2(unsigned a, unsigned b) {
    unsigned r;
    asm("mul.bf16x2 %0, %1, %2;" : "=r"(r) : "r"(a), "r"(b));
    return r;
}
__device__ __forceinline__ void mma16816(float* c, const unsigned* a,
                                         unsigned b0, unsigned b1) {
    asm("mma.sync.aligned.m16n8k16.row.col.f32.bf16.bf16.f32 "
        "{%0,%1,%2,%3}, {%4,%5,%6,%7}, {%8,%9}, {%0,%1,%2,%3};"
        : "+f"(c[0]), "+f"(c[1]), "+f"(c[2]), "+f"(c[3])
        : "r"(a[0]), "r"(a[1]), "r"(a[2]), "r"(a[3]), "r"(b0), "r"(b1));
}
__device__ __forceinline__ void ldsm_x4_t(unsigned& r0, unsigned& r1,
                                          unsigned& r2, unsigned& r3,
                                          unsigned addr) {
    asm volatile("ldmatrix.sync.aligned.m8n8.x4.trans.shared.b16 "
                 "{%0,%1,%2,%3}, [%4];"
                 : "=r"(r0), "=r"(r1), "=r"(r2), "=r"(r3) : "r"(addr));
}
__device__ __forceinline__ void ldsm_x4(unsigned& r0, unsigned& r1,
                                        unsigned& r2, unsigned& r3,
                                        unsigned addr) {
    asm volatile("ldmatrix.sync.aligned.m8n8.x4.shared.b16 "
                 "{%0,%1,%2,%3}, [%4];"
                 : "=r"(r0), "=r"(r1), "=r"(r2), "=r"(r3) : "r"(addr));
}
__device__ __forceinline__ unsigned smem_u32(const void* p) {
    return (unsigned)__cvta_generic_to_shared(p);
}

// =========================================================================
// GEMM: h = in[4096][K] @ W[128][K]^T (+bias); emits packed bf16 h only
// (fp32 h is dead in this pipeline). Optionally s/d attention scalars.
// =========================================================================
__global__ void gemm_attn_kernel(const float* __restrict__ in, int K,
                                 const float* __restrict__ W,
                                 const float* __restrict__ a_s,
                                 const float* __restrict__ a_d,
                                 const float* __restrict__ bias,
                                 unsigned* __restrict__ out_bf,
                                 float* __restrict__ s_out,
                                 float* __restrict__ d_out) {
    extern __shared__ float sm[];
    float* in_s = sm;            // 32*K
    float* Wt   = sm + 32 * K;   // K rows of WT_STR
    const int tid = threadIdx.x;
    const int i0  = blockIdx.x * 32;

    {   // rows contiguous -> straight float4 copy
        const float4* gin4 = reinterpret_cast<const float4*>(in + (size_t)i0 * K);
        float4* in4 = reinterpret_cast<float4*>(in_s);
        for (int idx = tid; idx < 8 * K; idx += 256) in4[idx] = gin4[idx];
    }
    for (int idx = tid; idx < 128 * K; idx += 256) {
        int c = idx / K, k = idx - c * K;
        Wt[k * WT_STR + c] = W[idx];
    }
    __syncthreads();

    const int rg = tid >> 5;
    const int lane = tid & 31;
    unsigned long long acc2[4][2];
#pragma unroll
    for (int r = 0; r < 4; ++r) { acc2[r][0] = 0ull; acc2[r][1] = 0ull; }

    for (int k = 0; k < K; ++k) {
        longlong2 B = *reinterpret_cast<const longlong2*>(&Wt[k * WT_STR + lane * 4]);
#pragma unroll
        for (int rr = 0; rr < 4; ++rr) {
            float a = in_s[(rg * 4 + rr) * K + k];
            unsigned long long aa = pack2(a, a);
            acc2[rr][0] = ffma2(aa, (unsigned long long)B.x, acc2[rr][0]);
            acc2[rr][1] = ffma2(aa, (unsigned long long)B.y, acc2[rr][1]);
        }
    }

    float acc[4][4];
#pragma unroll
    for (int rr = 0; rr < 4; ++rr) {
        float2 p0 = unpack2(acc2[rr][0]);
        float2 p1 = unpack2(acc2[rr][1]);
        acc[rr][0] = p0.x; acc[rr][1] = p0.y; acc[rr][2] = p1.x; acc[rr][3] = p1.y;
    }

#pragma unroll
    for (int rr = 0; rr < 4; ++rr) {
        int row = i0 + rg * 4 + rr;
        float v0 = acc[rr][0], v1 = acc[rr][1], v2 = acc[rr][2], v3 = acc[rr][3];
        if (bias) {
            v0 += bias[lane * 4 + 0];
            v1 += bias[lane * 4 + 1];
            v2 += bias[lane * 4 + 2];
            v3 += bias[lane * 4 + 3];
        }
        uint2 o;
        o.x = bf16x2_of(v0, v1);
        o.y = bf16x2_of(v2, v3);
        *reinterpret_cast<uint2*>(&out_bf[(size_t)row * 64 + lane * 2]) = o;
    }

    if (s_out) {
#pragma unroll
        for (int rr = 0; rr < 4; ++rr) {
            float sp = 0.f, dp = 0.f;
#pragma unroll
            for (int cc = 0; cc < 4; ++cc) {
                int c = lane * 4 + cc;
                sp += acc[rr][cc] * __ldg(&a_s[c]);
                dp += acc[rr][cc] * __ldg(&a_d[c]);
            }
#pragma unroll
            for (int off = 16; off; off >>= 1) {
                sp += __shfl_xor_sync(0xffffffffu, sp, off);
                dp += __shfl_xor_sync(0xffffffffu, dp, off);
            }
            if (lane == 0) {
                s_out[i0 + rg * 4 + rr] = sp;
                d_out[i0 + rg * 4 + rr] = dp;
            }
        }
    }
}

// =========================================================================
// GAT split-K partial (unchanged from R9)
// =========================================================================
#define GB_H0 0
#define GB_H1 8704
#define GB_W0 17408
#define GB_W1 19968
#define GB_TOTAL 22528

__global__ void __launch_bounds__(256, 3)
gat_part_kernel(const unsigned* __restrict__ hb,
                const float* __restrict__ s,
                const float* __restrict__ d,
                const int*   __restrict__ adj,
                float* __restrict__ part,
                float* __restrict__ zp) {
    __shared__ __align__(16) char smraw[GB_TOTAL];
    __nv_bfloat16* h_sb[2] = { (__nv_bfloat16*)(smraw + GB_H0),
                               (__nv_bfloat16*)(smraw + GB_H1) };
    __nv_bfloat16* w_sb[2] = { (__nv_bfloat16*)(smraw + GB_W0),
                               (__nv_bfloat16*)(smraw + GB_W1) };

    const int tid = threadIdx.x;
    const int i0  = blockIdx.x * 32;
    const int sz  = blockIdx.y;
    const int jb  = sz * J_PER_SPLIT;

    const int lane = tid & 31;
    const int w    = tid >> 5;
    const int rg   = w;
    const int wi   = tid >> 3;
    const int wj   = (tid & 7) * 4;
    const float si = s[i0 + wi];

    const int fg = lane >> 2, ft = lane & 3;
    const int m0 = (w & 1) * 16;
    const int n0 = (w >> 1) * 32;
    const int lm_ti = lane >> 3, lm_r = lane & 7;
    const int lm_off = ((lm_ti & 1) * 8 + lm_r) * 136 + (lm_ti >> 1) * 8;
    const unsigned hb_u32[2] = { smem_u32(h_sb[0]), smem_u32(h_sb[1]) };
    const int aw = (m0 + fg) * 40 + 2 * ft;

    float zacc = 0.f;
    float acc[4][4];
#pragma unroll
    for (int i = 0; i < 4; ++i)
#pragma unroll
        for (int k = 0; k < 4; ++k) acc[i][k] = 0.f;

    int4 av; float4 dv; uint2 hv0, hv1, hv2, hv3;

#define GAT_LOAD(J0)                                                          \
    do {                                                                      \
        av = *reinterpret_cast<const int4*>(                                  \
            &adj[(size_t)(i0 + wi) * N_NODES + (J0) + wj]);                   \
        dv = *reinterpret_cast<const float4*>(&d[(J0) + wj]);                 \
        const uint2* h2p = reinterpret_cast<const uint2*>(hb);                \
        hv0 = h2p[(size_t)((J0) + rg +  0) * 32 + lane];                      \
        hv1 = h2p[(size_t)((J0) + rg +  8) * 32 + lane];                      \
        hv2 = h2p[(size_t)((J0) + rg + 16) * 32 + lane];                      \
        hv3 = h2p[(size_t)((J0) + rg + 24) * 32 + lane];                      \
    } while (0)

#define GAT_STORE(BUF)                                                        \
    do {                                                                      \
        float w0 = 0.f, w1 = 0.f, w2 = 0.f, w3 = 0.f;                         \
        if (av.x > 0) { float e = si + dv.x; e = (e > 0.f) ? e : 0.2f * e; w0 = __expf(e); } \
        if (av.y > 0) { float e = si + dv.y; e = (e > 0.f) ? e : 0.2f * e; w1 = __expf(e); } \
        if (av.z > 0) { float e = si + dv.z; e = (e > 0.f) ? e : 0.2f * e; w2 = __expf(e); } \
        if (av.w > 0) { float e = si + dv.w; e = (e > 0.f) ? e : 0.2f * e; w3 = __expf(e); } \
        zacc += (w0 + w1) + (w2 + w3);                                        \
        uint2 wp; wp.x = bf16x2_of(w0, w1); wp.y = bf16x2_of(w2, w3);         \
        *reinterpret_cast<uint2*>(&w_sb[BUF][wi * 40 + wj]) = wp;             \
        *reinterpret_cast<uint2*>(&h_sb[BUF][(rg +  0) * 136 + lane * 4]) = hv0; \
        *reinterpret_cast<uint2*>(&h_sb[BUF][(rg +  8) * 136 + lane * 4]) = hv1; \
        *reinterpret_cast<uint2*>(&h_sb[BUF][(rg + 16) * 136 + lane * 4]) = hv2; \
        *reinterpret_cast<uint2*>(&h_sb[BUF][(rg + 24) * 136 + lane * 4]) = hv3; \
    } while (0)

    GAT_LOAD(jb);
    GAT_STORE(0);
    __syncthreads();

    int buf = 0;
    const int NT = J_PER_SPLIT / 32;
    for (int t = 0; t < NT; ++t) {
        const int nxt = jb + (t + 1) * 32;
        if (t + 1 < NT) GAT_LOAD(nxt);

        const __nv_bfloat16* wb = w_sb[buf];
        const unsigned hbase = hb_u32[buf] + lm_off * 2;
#pragma unroll
        for (int sstep = 0; sstep < 2; ++sstep) {
            const int k0 = 16 * sstep;
            unsigned A[4];
            A[0] = *reinterpret_cast<const unsigned*>(&wb[aw + k0]);
            A[1] = *reinterpret_cast<const unsigned*>(&wb[aw + 320 + k0]);
            A[2] = *reinterpret_cast<const unsigned*>(&wb[aw + k0 + 8]);
            A[3] = *reinterpret_cast<const unsigned*>(&wb[aw + 320 + k0 + 8]);
#pragma unroll
            for (int p = 0; p < 2; ++p) {
                unsigned r0, r1, r2, r3;
                ldsm_x4_t(r0, r1, r2, r3,
                          hbase + (k0 * 136 + n0 + 16 * p) * 2);
                mma16816(acc[2 * p + 0], A, r0, r1);
                mma16816(acc[2 * p + 1], A, r2, r3);
            }
        }

        if (t + 1 < NT) GAT_STORE(buf ^ 1);
        __syncthreads();
        buf ^= 1;
    }
#undef GAT_LOAD
#undef GAT_STORE

    zacc += __shfl_xor_sync(0xffffffffu, zacc, 4);
    zacc += __shfl_xor_sync(0xffffffffu, zacc, 2);
    zacc += __shfl_xor_sync(0xffffffffu, zacc, 1);
    if ((tid & 7) == 0) zp[(size_t)sz * N_NODES + i0 + wi] = zacc;

    float* pb = &part[((size_t)sz * N_NODES + i0) * 128];
#pragma unroll
    for (int i = 0; i < 4; ++i) {
        const int col = n0 + 8 * i + 2 * ft;
        float2 lo; lo.x = acc[i][0]; lo.y = acc[i][1];
        float2 hi; hi.x = acc[i][2]; hi.y = acc[i][3];
        *reinterpret_cast<float2*>(&pb[(m0 + fg) * 128 + col])     = lo;
        *reinterpret_cast<float2*>(&pb[(m0 + 8 + fg) * 128 + col]) = hi;
    }
}

// =========================================================================
// GAT reduce (unchanged from R9)
// =========================================================================
__global__ void gat_reduce_kernel(const float* __restrict__ part,
                                  const float* __restrict__ zp,
                                  const float* __restrict__ res,
                                  const float* __restrict__ lnw,
                                  const float* __restrict__ lnb,
                                  float* __restrict__ out,
                                  int do_ln) {
    __shared__ float z_s[32];
    const int tid = threadIdx.x;
    const int i0  = blockIdx.x * 32;
    const int rg  = tid >> 5;
    const int lane = tid & 31;

    if (tid < 32) {
        float z = 0.f;
#pragma unroll
        for (int s = 0; s < GAT_SPLITS; ++s)
            z += zp[(size_t)s * N_NODES + i0 + tid];
        z_s[tid] = z;
    }
    __syncthreads();

#pragma unroll
    for (int rr = 0; rr < 4; ++rr) {
        const int lrow = rg * 4 + rr;
        const int row  = i0 + lrow;
        float4 a = make_float4(0.f, 0.f, 0.f, 0.f);
#pragma unroll
        for (int s = 0; s < GAT_SPLITS; ++s) {
            float4 p = *reinterpret_cast<const float4*>(
                &part[((size_t)s * N_NODES + row) * 128 + lane * 4]);
            a.x += p.x; a.y += p.y; a.z += p.z; a.w += p.w;
        }
        const float z = z_s[lrow];
        const float zinv = (z > 0.f) ? (1.0f / z) : 0.f;
        float v[4] = {a.x, a.y, a.z, a.w};
#pragma unroll
        for (int cc = 0; cc < 4; ++cc) {
            float t = fmaxf(v[cc] * zinv, 0.f);
            if (res) t += res[(size_t)row * 128 + lane * 4 + cc];
            v[cc] = t;
        }
        if (do_ln) {
            float sum = v[0] + v[1] + v[2] + v[3];
            float sq  = v[0]*v[0] + v[1]*v[1] + v[2]*v[2] + v[3]*v[3];
#pragma unroll
            for (int off = 16; off; off >>= 1) {
                sum += __shfl_xor_sync(0xffffffffu, sum, off);
                sq  += __shfl_xor_sync(0xffffffffu, sq,  off);
            }
            const float mu  = sum * (1.0f / 128.0f);
            const float var = sq  * (1.0f / 128.0f) - mu * mu;
            const float rs  = rsqrtf(var + 1e-5f);
#pragma unroll
            for (int cc = 0; cc < 4; ++cc) {
                int c = lane * 4 + cc;
                v[cc] = (v[cc] - mu) * rs * __ldg(&lnw[c]) + __ldg(&lnb[c]);
            }
        }
        float4 o; o.x = v[0]; o.y = v[1]; o.z = v[2]; o.w = v[3];
        *reinterpret_cast<float4*>(&out[(size_t)row * 128 + lane * 4]) = o;
    }
}

// =========================================================================
// Candidate head: persistent, bf16 MMA with ldmatrix fragments + fast gelu
// =========================================================================
#define STR1 136
#define STR3 264

#define OB_WC2  0
#define OB_WS1  34816
#define OB_T1   102400
#define OB_T2   137216
#define OB_WC1T 172032
#define OB_CF   177152
#define OB_QB   182272
#define OB_BC1  182784
#define OB_BC2  183296
#define OB_BS1  183808
#define OB_WS2  184320
#define OB_AM   184832
#define OB_PART 185344
#define OB_MISC 186368
#define CAND_SMEM_BYTES 186400
#define N_PAIRS 2048

__global__ void __launch_bounds__(256, 1)
cand_kernel(const float* __restrict__ cf,
            const float* __restrict__ am,
            const float* __restrict__ Wc1, const float* __restrict__ bc1,
            const float* __restrict__ Wc2, const float* __restrict__ bc2,
            const float* __restrict__ Ws1, const float* __restrict__ bs1,
            const float* __restrict__ Ws2, const float* __restrict__ bs2,
            const unsigned* __restrict__ qbg,   // packed bf16 q [4096][64]
            float* __restrict__ out) {
    extern __shared__ char smc[];
    __nv_bfloat16* Wc2b = (__nv_bfloat16*)(smc + OB_WC2);
    __nv_bfloat16* Ws1b = (__nv_bfloat16*)(smc + OB_WS1);
    __nv_bfloat16* T1b  = (__nv_bfloat16*)(smc + OB_T1);
    __nv_bfloat16* T2b  = (__nv_bfloat16*)(smc + OB_T2);
    float* Wc1t = (float*)(smc + OB_WC1T);
    float* cf_s = (float*)(smc + OB_CF);
    unsigned* qb = (unsigned*)(smc + OB_QB);
    float* bc1s = (float*)(smc + OB_BC1);
    float* bc2s = (float*)(smc + OB_BC2);
    float* bs1s = (float*)(smc + OB_BS1);
    float* Ws2s = (float*)(smc + OB_WS2);
    float* am_s = (float*)(smc + OB_AM);
    float* part = (float*)(smc + OB_PART);
    float* misc = (float*)(smc + OB_MISC);

    const int tid = threadIdx.x;

    // -------- weights: loaded ONCE per block --------
    for (int i2 = tid; i2 < 8192; i2 += 256) {
        int n = i2 >> 6, kp = i2 & 63;
        float2 v = *reinterpret_cast<const float2*>(&Wc2[n * 128 + 2 * kp]);
        *reinterpret_cast<unsigned*>(&Wc2b[n * STR1 + 2 * kp]) = bf16x2_of(v.x, v.y);
    }
    for (int i2 = tid; i2 < 16384; i2 += 256) {
        int n = i2 >> 7, kp = i2 & 127;
        float2 v = *reinterpret_cast<const float2*>(&Ws1[n * 256 + 2 * kp]);
        *reinterpret_cast<unsigned*>(&Ws1b[n * STR3 + 2 * kp]) = bf16x2_of(v.x, v.y);
    }
    for (int idx = tid; idx < 1280; idx += 256) {
        int c = idx / 10, j = idx - c * 10;
        Wc1t[j * 128 + c] = Wc1[idx];
    }
    if (tid < 128) {
        bc1s[tid] = bc1[tid];
        bc2s[tid] = bc2[tid];
        bs1s[tid] = bs1[tid];
        Ws2s[tid] = Ws2[tid];
    }
    const float bs2v = __ldg(&bs2[0]);

    const int w    = tid >> 5;
    const int lane = tid & 31;
    const int fg   = lane >> 2;
    const int ft   = lane & 3;
    const int wm   = w & 3;
    const int wn   = w >> 2;
    const int m0   = wm * 32;
    const int nc0  = wn * 64;
    const int node = wm >> 1;
    const int rg1  = tid >> 4;
    const int cg1  = tid & 15;

    // ---- ldmatrix address precomputation (per-lane bases, bytes) ----
    // A fragment rows (16x16 tiles): lane l -> row (l>>3&1)*8 + (l&7), k-half (l>>4)
    const int a_row  = ((lane >> 3) & 1) * 8 + (lane & 7);
    const int a_koff = (lane >> 4) * 8;
    const unsigned t1_u32 = smem_u32(T1b);
    const unsigned t2_u32 = smem_u32(T2b);
    const unsigned a1_base0 = t1_u32 + 2 * ((m0 + a_row) * STR1 + a_koff);
    const unsigned a1_base1 = t1_u32 + 2 * ((m0 + 16 + a_row) * STR1 + a_koff);
    const unsigned a2_base0 = t2_u32 + 2 * ((m0 + a_row) * STR1 + a_koff);
    const unsigned a2_base1 = t2_u32 + 2 * ((m0 + 16 + a_row) * STR1 + a_koff);
    // B fragments: instr ii covers i=2ii,2ii+1; lane l -> matrix m=l>>3:
    //   i_loc = 2ii + (m>>1), k-half = m&1, row = nc0 + 8*i_loc + (l&7)
    const int b_m     = lane >> 3;
    const int b_iloc  = b_m >> 1;          // 0/1 within instr
    const int b_koff  = (b_m & 1) * 8;
    const int b_row   = lane & 7;
    const unsigned wc2_u32 = smem_u32(Wc2b);
    const unsigned ws1_u32 = smem_u32(Ws1b);
    unsigned b2_base[4], b3_base[4];
#pragma unroll
    for (int ii = 0; ii < 4; ++ii) {
        int nrow = nc0 + 8 * (2 * ii + b_iloc) + b_row;
        b2_base[ii] = wc2_u32 + 2 * (nrow * STR1 + b_koff);
        b3_base[ii] = ws1_u32 + 2 * (nrow * STR3 + b_koff);
    }

    // -------- persistent loop over node-pairs --------
    for (int pr = blockIdx.x; pr < N_PAIRS; pr += gridDim.x) {
        const int n0  = pr * 2;
        const int base_row = n0 * 64;

        __syncthreads();

        for (int idx = tid; idx < 1280; idx += 256)
            cf_s[idx] = cf[(size_t)base_row * 10 + idx];
        if (tid < 128) {
            qb[tid] = qbg[(size_t)n0 * 64 + tid];
            am_s[tid] = am[base_row + tid];
        }
        __syncthreads();

        if (tid < 2) {
            float ssum = 0.f;
            for (int c = 0; c < 64; ++c) ssum += am_s[tid * 64 + c];
            misc[tid] = (ssum <= 0.f) ? 1.f : 0.f;
        }

        // ---- stage 1 (fp32, K=10) -> T1b bf16 ----
        {
            unsigned long long a2[8][4];
#pragma unroll
            for (int r = 0; r < 8; ++r)
#pragma unroll
                for (int c = 0; c < 4; ++c) a2[r][c] = 0ull;
#pragma unroll
            for (int j = 0; j < 10; ++j) {
                longlong2 B0 = *reinterpret_cast<const longlong2*>(&Wc1t[j * 128 + cg1 * 8]);
                longlong2 B1 = *reinterpret_cast<const longlong2*>(&Wc1t[j * 128 + cg1 * 8 + 4]);
#pragma unroll
                for (int rr = 0; rr < 8; ++rr) {
                    float a = cf_s[(rg1 * 8 + rr) * 10 + j];
                    unsigned long long aa = pack2(a, a);
                    a2[rr][0] = ffma2(aa, (unsigned long long)B0.x, a2[rr][0]);
                    a2[rr][1] = ffma2(aa, (unsigned long long)B0.y, a2[rr][1]);
                    a2[rr][2] = ffma2(aa, (unsigned long long)B1.x, a2[rr][2]);
                    a2[rr][3] = ffma2(aa, (unsigned long long)B1.y, a2[rr][3]);
                }
            }
#pragma unroll
            for (int rr = 0; rr < 8; ++rr) {
                int r = rg1 * 8 + rr;
                float2 p0 = unpack2(a2[rr][0]);
                float2 p1 = unpack2(a2[rr][1]);
                float2 p2 = unpack2(a2[rr][2]);
                float2 p3 = unpack2(a2[rr][3]);
                uint4 o;
                o.x = bf16x2_of(gelu_fast(p0.x + bc1s[cg1 * 8 + 0]),
                                gelu_fast(p0.y + bc1s[cg1 * 8 + 1]));
                o.y = bf16x2_of(gelu_fast(p1.x + bc1s[cg1 * 8 + 2]),
                                gelu_fast(p1.y + bc1s[cg1 * 8 + 3]));
                o.z = bf16x2_of(gelu_fast(p2.x + bc1s[cg1 * 8 + 4]),
                                gelu_fast(p2.y + bc1s[cg1 * 8 + 5]));
                o.w = bf16x2_of(gelu_fast(p3.x + bc1s[cg1 * 8 + 6]),
                                gelu_fast(p3.y + bc1s[cg1 * 8 + 7]));
                *reinterpret_cast<uint4*>(&T1b[r * STR1 + cg1 * 8]) = o;
            }
        }
        __syncthreads();

        float acc[2][8][4];

        // ---- stage 2: T2 = gelu(T1 @ Wc2^T + bc2) ----
#pragma unroll
        for (int mt = 0; mt < 2; ++mt)
#pragma unroll
            for (int i = 0; i < 8; ++i)
#pragma unroll
                for (int k = 0; k < 4; ++k) acc[mt][i][k] = 0.f;

#pragma unroll
        for (int s = 0; s < 8; ++s) {
            const unsigned kb = 32 * s;   // 16 bf16 = 32 bytes per k-step
            unsigned A[2][4];
            ldsm_x4(A[0][0], A[0][1], A[0][2], A[0][3], a1_base0 + kb);
            ldsm_x4(A[1][0], A[1][1], A[1][2], A[1][3], a1_base1 + kb);
#pragma unroll
            for (int ii = 0; ii < 4; ++ii) {
                unsigned r0, r1, r2, r3;
                ldsm_x4(r0, r1, r2, r3, b2_base[ii] + kb);
                mma16816(acc[0][2 * ii],     A[0], r0, r1);
                mma16816(acc[1][2 * ii],     A[1], r0, r1);
                mma16816(acc[0][2 * ii + 1], A[0], r2, r3);
                mma16816(acc[1][2 * ii + 1], A[1], r2, r3);
            }
        }

#pragma unroll
        for (int mt = 0; mt < 2; ++mt) {
#pragma unroll
            for (int i = 0; i < 8; ++i) {
                const int c0 = nc0 + 8 * i + 2 * ft;
                const int rlo = m0 + 16 * mt + fg;
                float2 bc = *reinterpret_cast<const float2*>(&bc2s[c0]);
                unsigned lo = bf16x2_of(gelu_fast(acc[mt][i][0] + bc.x),
                                        gelu_fast(acc[mt][i][1] + bc.y));
                unsigned hi = bf16x2_of(gelu_fast(acc[mt][i][2] + bc.x),
                                        gelu_fast(acc[mt][i][3] + bc.y));
                *reinterpret_cast<unsigned*>(&T2b[rlo * STR1 + c0]) = lo;
                *reinterpret_cast<unsigned*>(&T2b[(rlo + 8) * STR1 + c0]) = hi;
            }
        }
        __syncthreads();

        // ---- stage 3: [q*T2 | T2] @ Ws1^T ----
#pragma unroll
        for (int mt = 0; mt < 2; ++mt)
#pragma unroll
            for (int i = 0; i < 8; ++i)
#pragma unroll
                for (int k = 0; k < 4; ++k) acc[mt][i][k] = 0.f;

#pragma unroll
        for (int p = 0; p < 2; ++p) {
#pragma unroll
            for (int s = 0; s < 8; ++s) {
                const unsigned kb = 32 * s;
                unsigned A[2][4];
                ldsm_x4(A[0][0], A[0][1], A[0][2], A[0][3], a2_base0 + kb);
                ldsm_x4(A[1][0], A[1][1], A[1][2], A[1][3], a2_base1 + kb);
                if (p == 0) {
                    unsigned q0 = qb[node * 64 + 8 * s + ft];
                    unsigned q1 = qb[node * 64 + 8 * s + ft + 4];
#pragma unroll
                    for (int mt = 0; mt < 2; ++mt) {
                        A[mt][0] = mul_bf16x2(A[mt][0], q0);
                        A[mt][1] = mul_bf16x2(A[mt][1], q0);
                        A[mt][2] = mul_bf16x2(A[mt][2], q1);
                        A[mt][3] = mul_bf16x2(A[mt][3], q1);
                    }
                }
                const unsigned pk = p * 256 + kb;   // +128 bf16 = 256 B for p=1
#pragma unroll
                for (int ii = 0; ii < 4; ++ii) {
                    unsigned r0, r1, r2, r3;
                    ldsm_x4(r0, r1, r2, r3, b3_base[ii] + pk);
                    mma16816(acc[0][2 * ii],     A[0], r0, r1);
                    mma16816(acc[1][2 * ii],     A[1], r0, r1);
                    mma16816(acc[0][2 * ii + 1], A[0], r2, r3);
                    mma16816(acc[1][2 * ii + 1], A[1], r2, r3);
                }
            }
        }

        // ---- epilogue ----
        float rs0[2] = {0.f, 0.f};
        float rs1[2] = {0.f, 0.f};
#pragma unroll
        for (int mt = 0; mt < 2; ++mt) {
#pragma unroll
            for (int i = 0; i < 8; ++i) {
                const int c0 = nc0 + 8 * i + 2 * ft;
                float2 b1 = *reinterpret_cast<const float2*>(&bs1s[c0]);
                float2 w2 = *reinterpret_cast<const float2*>(&Ws2s[c0]);
                rs0[mt] += gelu_fast(acc[mt][i][0] + b1.x) * w2.x
                         + gelu_fast(acc[mt][i][1] + b1.y) * w2.y;
                rs1[mt] += gelu_fast(acc[mt][i][2] + b1.x) * w2.x
                         + gelu_fast(acc[mt][i][3] + b1.y) * w2.y;
            }
        }
#pragma unroll
        for (int off = 1; off <= 2; off <<= 1) {
#pragma unroll
            for (int mt = 0; mt < 2; ++mt) {
                rs0[mt] += __shfl_xor_sync(0xffffffffu, rs0[mt], off);
                rs1[mt] += __shfl_xor_sync(0xffffffffu, rs1[mt], off);
            }
        }
        if (ft == 0) {
#pragma unroll
            for (int mt = 0; mt < 2; ++mt) {
                part[(m0 + 16 * mt + fg) * 2 + wn]     = rs0[mt];
                part[(m0 + 16 * mt + 8 + fg) * 2 + wn] = rs1[mt];
            }
        }
        __syncthreads();

        if (tid < 128) {
            const int r = tid;
            const int l = r >> 6, c = r & 63;
            const float* cfr = &cf_s[r * 10];
            float bias = 20.0f * cfr[0] + 4.0f * cfr[4] + 1.5f * cfr[5]
                       + 1.5f * cfr[1] - 1.5f * cfr[2] + 1.2f * cfr[6]
                       + 2.5f * cfr[7] + 1.6f * cfr[8] + 1.2f * cfr[9];
            float logit = part[2 * r] + part[2 * r + 1] + bs2v + bias;
            float amv = am_s[r];
            bool valid = (amv > 0.f) || (c == 0 && misc[l] > 0.5f);
            out[(size_t)(n0 + l) * 64 + c] = valid ? logit : NEGV;
        }
    }
}

// =========================================================================
extern "C" void kernel_launch(void* const* d_in, const int* in_sizes, int n_in,
                              void* d_out, int out_size) {
    const float* x    = (const float*)d_in[0];
    const float* cf   = (const float*)d_in[1];
    const int*   adj  = (const int*)  d_in[2];
    const float* am   = (const float*)d_in[3];
    const float* W1   = (const float*)d_in[4];
    const float* a1s  = (const float*)d_in[5];
    const float* a1d  = (const float*)d_in[6];
    const float* W2   = (const float*)d_in[7];
    const float* a2s  = (const float*)d_in[8];
    const float* a2d  = (const float*)d_in[9];
    const float* lnw  = (const float*)d_in[10];
    const float* lnb  = (const float*)d_in[11];
    const float* Wc1  = (const float*)d_in[12];
    const float* bc1  = (const float*)d_in[13];
    const float* Wc2  = (const float*)d_in[14];
    const float* bc2  = (const float*)d_in[15];
    const float* Wq   = (const float*)d_in[16];
    const float* bq   = (const float*)d_in[17];
    const float* Ws1  = (const float*)d_in[18];
    const float* bs1  = (const float*)d_in[19];
    const float* Ws2  = (const float*)d_in[20];
    const float* bs2  = (const float*)d_in[21];
    float* out = (float*)d_out;

    float *s1, *d1, *g1, *s2, *d2, *hn, *pt, *zp;
    unsigned *h1b, *h2b, *qbg;
    cudaGetSymbolAddress((void**)&s1, g_s1);
    cudaGetSymbolAddress((void**)&d1, g_d1);
    cudaGetSymbolAddress((void**)&g1, g_g1);
    cudaGetSymbolAddress((void**)&s2, g_s2);
    cudaGetSymbolAddress((void**)&d2, g_d2);
    cudaGetSymbolAddress((void**)&hn, g_hn);
    cudaGetSymbolAddress((void**)&h1b, g_h1b);
    cudaGetSymbolAddress((void**)&h2b, g_h2b);
    cudaGetSymbolAddress((void**)&qbg, g_qb);
    cudaGetSymbolAddress((void**)&pt, g_part);
    cudaGetSymbolAddress((void**)&zp, g_zp);

    const int smem_k64  = (32 * 64  + WT_STR * 64)  * 4;
    const int smem_k128 = (32 * 128 + WT_STR * 128) * 4;

    cudaFuncSetAttribute(gemm_attn_kernel,
                         cudaFuncAttributeMaxDynamicSharedMemorySize, smem_k128);
    cudaFuncSetAttribute(cand_kernel,
                         cudaFuncAttributeMaxDynamicSharedMemorySize, CAND_SMEM_BYTES);

    dim3 gat_grid(128, GAT_SPLITS);

    // layer 1
    gemm_attn_kernel<<<128, 256, smem_k64>>>(x, 64, W1, a1s, a1d, nullptr,
                                             h1b, s1, d1);
    gat_part_kernel<<<gat_grid, 256>>>(h1b, s1, d1, adj, pt, zp);
    gat_reduce_kernel<<<128, 256>>>(pt, zp, nullptr, nullptr, nullptr, g1, 0);
    // layer 2 + residual + LN
    gemm_attn_kernel<<<128, 256, smem_k128>>>(g1, 128, W2, a2s, a2d, nullptr,
                                              h2b, s2, d2);
    gat_part_kernel<<<gat_grid, 256>>>(h2b, s2, d2, adj, pt, zp);
    gat_reduce_kernel<<<128, 256>>>(pt, zp, g1, lnw, lnb, hn, 1);
    // q projection -> packed bf16 directly
    gemm_attn_kernel<<<128, 256, smem_k128>>>(hn, 128, Wq, nullptr, nullptr, bq,
                                              qbg, nullptr, nullptr);
    // persistent fused candidate head
    cand_kernel<<<148, 256, CAND_SMEM_BYTES>>>(cf, am, Wc1, bc1, Wc2, bc2,
                                               Ws1, bs1, Ws2, bs2, qbg, out);
}